// round 9
// baseline (speedup 1.0000x reference)
#include <cuda_runtime.h>

// ---------------- problem constants ----------------
#define Bn    2
#define Sn    1024
#define Hn    8
#define DIMn  128
#define LCMP  32
#define NCMP  63          // (1024-32)/16+1
#define NSLC  61          // (1024-64)/16+1
#define BQ    64
#define NQB   (Sn / BQ)   // 16
#define WINR  128
#define QSTR  129         // padded row stride (conflict-free scalar LDS)
#define PSTR  133         // logit buffer row stride (>=128, odd vs 32 banks)
#define NEG_INF (-1e30f)

#define SCALE_MUL 0.08838834764831845f   // 1/sqrt(128): slc & window
#define SQRT_D    11.313708498984761f    // sqrt(128): cmp branch (reference divides by scale)

// scratch for compressed K/V: [b][h][n][d]
__device__ float g_cmpK[Bn * Hn * NCMP * DIMn];
__device__ float g_cmpV[Bn * Hn * NCMP * DIMn];

// ---------------- kernel A: compressed K/V ----------------
__global__ void __launch_bounds__(256) cmp_kv_kernel(
    const float* __restrict__ k, const float* __restrict__ v,
    const float* __restrict__ wck, const float* __restrict__ bck,
    const float* __restrict__ wcv, const float* __restrict__ bcv)
{
    __shared__ float swk[LCMP], swv[LCMP], sb[2];
    int tid = threadIdx.x;
    if (tid < LCMP) { swk[tid] = wck[tid]; swv[tid] = wcv[tid]; }
    if (tid == 0)   { sb[0] = bck[0]; sb[1] = bcv[0]; }
    __syncthreads();

    int idx = blockIdx.x * 256 + tid;
    if (idx >= Bn * Hn * NCMP * DIMn) return;
    int d  = idx & (DIMn - 1);
    int n  = (idx >> 7) % NCMP;
    int bh = idx / (NCMP * DIMn);
    int h  = bh & (Hn - 1);
    int b  = bh >> 3;

    const float* kb = k + ((size_t)(b * Sn + n * 16) * Hn + h) * DIMn + d;
    const float* vb = v + ((size_t)(b * Sn + n * 16) * Hn + h) * DIMn + d;
    float ak = 0.f, av = 0.f;
#pragma unroll
    for (int l = 0; l < LCMP; ++l) {
        ak += kb[(size_t)l * Hn * DIMn] * swk[l];
        av += vb[(size_t)l * Hn * DIMn] * swv[l];
    }
    g_cmpK[idx] = ak + sb[0];
    g_cmpV[idx] = av + sb[1];
}

// ---------------- helpers for the fused kernel ----------------

// QK core: s[4][4] = Qs(64x128) * Ks(64x128)^T register tile (no scale/mask)
__device__ __forceinline__ void qk_core(const float* __restrict__ Qs,
                                        const float* __restrict__ Ks,
                                        float s[4][4], int rho, int gg)
{
#pragma unroll
    for (int i = 0; i < 4; ++i)
#pragma unroll
        for (int j = 0; j < 4; ++j) s[i][j] = 0.f;

    const float* qp = Qs + rho * QSTR;
    const float* kp = Ks + gg  * QSTR;
#pragma unroll 4
    for (int kd = 0; kd < DIMn; ++kd) {
        float a0 = qp[kd];
        float a1 = qp[16 * QSTR + kd];
        float a2 = qp[32 * QSTR + kd];
        float a3 = qp[48 * QSTR + kd];
        float b0 = kp[kd];
        float b1 = kp[16 * QSTR + kd];
        float b2 = kp[32 * QSTR + kd];
        float b3 = kp[48 * QSTR + kd];
        s[0][0] += a0 * b0; s[0][1] += a0 * b1; s[0][2] += a0 * b2; s[0][3] += a0 * b3;
        s[1][0] += a1 * b0; s[1][1] += a1 * b1; s[1][2] += a1 * b2; s[1][3] += a1 * b3;
        s[2][0] += a2 * b0; s[2][1] += a2 * b1; s[2][2] += a2 * b2; s[2][3] += a2 * b3;
        s[3][0] += a3 * b0; s[3][1] += a3 * b1; s[3][2] += a3 * b2; s[3][3] += a3 * b3;
    }
}

// QK GEMM -> Pb.  MODE 0 = cmp (mask c>=NCMP), 1 = slc (no mask)
template <int MODE>
__device__ __forceinline__ void gemm_qk(const float* __restrict__ Qs,
                                        const float* __restrict__ Ks,
                                        float* __restrict__ Pb,
                                        int rho, int gg, int cb, float scl)
{
    float s[4][4];
    qk_core(Qs, Ks, s, rho, gg);
#pragma unroll
    for (int i = 0; i < 4; ++i) {
        int r = rho + 16 * i;
#pragma unroll
        for (int j = 0; j < 4; ++j) {
            int c = gg + 16 * j;
            float val = s[i][j] * scl;
            if (MODE == 0) {
                if (c >= NCMP) val = NEG_INF;
            }
            Pb[r * PSTR + cb + c] = val;
        }
    }
}

// PV GEMM: acc[4][8] += P(64 x 64-tile) * Vs(64x128)
__device__ __forceinline__ void gemm_pv(const float* __restrict__ Pb,
                                        const float* __restrict__ Vs,
                                        float acc[4][8], int rho, int gg, int cb)
{
    const float* pp = Pb + rho * PSTR + cb;
#pragma unroll 2
    for (int cl = 0; cl < 64; ++cl) {
        float p0 = pp[cl];
        float p1 = pp[16 * PSTR + cl];
        float p2 = pp[32 * PSTR + cl];
        float p3 = pp[48 * PSTR + cl];
        const float* vr = Vs + cl * QSTR + gg;
#pragma unroll
        for (int j = 0; j < 8; ++j) {
            float vv = vr[16 * j];
            acc[0][j] += p0 * vv;
            acc[1][j] += p1 * vv;
            acc[2][j] += p2 * vv;
            acc[3][j] += p3 * vv;
        }
    }
}

// two-pass row softmax over Pb[:, 0:NK]; leaves exp() in Pb, 1/rowsum in rinv
__device__ __forceinline__ void softmax_rows(float* __restrict__ Pb,
                                             float* __restrict__ rmax,
                                             float* __restrict__ rinv,
                                             float* __restrict__ red,
                                             int NK, int tid)
{
    int r = tid & 63, part = tid >> 6;
    float m = NEG_INF;
    for (int c = part; c < NK; c += 4) m = fmaxf(m, Pb[r * PSTR + c]);
    red[part * 64 + r] = m;
    __syncthreads();
    if (tid < 64)
        rmax[tid] = fmaxf(fmaxf(red[tid], red[64 + tid]),
                          fmaxf(red[128 + tid], red[192 + tid]));
    __syncthreads();
    float mr = rmax[r];
    float sum = 0.f;
    for (int c = part; c < NK; c += 4) {
        float e = __expf(Pb[r * PSTR + c] - mr);
        Pb[r * PSTR + c] = e;
        sum += e;
    }
    red[part * 64 + r] = sum;
    __syncthreads();
    if (tid < 64)
        rinv[tid] = 1.0f / (red[tid] + red[64 + tid] + red[128 + tid] + red[192 + tid]);
    __syncthreads();
}

// P[r][c] *= gate[r][gi] / rowsum[r]
__device__ __forceinline__ void scale_rows(float* __restrict__ Pb,
                                           const float* __restrict__ rinv,
                                           const float* __restrict__ gts,
                                           int gi, int NK, int tid)
{
    int r = tid & 63, part = tid >> 6;
    float f = gts[r * 3 + gi] * rinv[r];
    for (int c = part; c < NK; c += 4) Pb[r * PSTR + c] *= f;
    __syncthreads();
}

// load a 64x128 tile from q/k/v-layout global memory into padded smem, zero-fill invalid
__device__ __forceinline__ void load_tile_kv(float* __restrict__ dst,
                                             const float* __restrict__ src,
                                             int b, int h, int s_base, int tid, bool check)
{
    for (int idx = tid; idx < 64 * 32; idx += 256) {
        int t = idx >> 5, d4 = idx & 31;
        int srow = s_base + t;
        float4 val = make_float4(0.f, 0.f, 0.f, 0.f);
        if (!check || ((unsigned)srow < (unsigned)Sn))
            val = ((const float4*)(src + ((size_t)(b * Sn + srow) * Hn + h) * DIMn))[d4];
        float* ds = &dst[t * QSTR + (d4 << 2)];
        ds[0] = val.x; ds[1] = val.y; ds[2] = val.z; ds[3] = val.w;
    }
}

// load compressed K/V tile (63 rows), zero row 63
__device__ __forceinline__ void load_tile_cmp(float* __restrict__ dst,
                                              const float* __restrict__ src,
                                              int bh, int tid)
{
    for (int idx = tid; idx < 64 * 32; idx += 256) {
        int t = idx >> 5, d4 = idx & 31;
        float4 val = make_float4(0.f, 0.f, 0.f, 0.f);
        if (t < NCMP)
            val = ((const float4*)(src + ((size_t)bh * NCMP + t) * DIMn))[d4];
        float* ds = &dst[t * QSTR + (d4 << 2)];
        ds[0] = val.x; ds[1] = val.y; ds[2] = val.z; ds[3] = val.w;
    }
}

// ---------------- fused main kernel ----------------
__global__ void __launch_bounds__(256, 2) nsa_main(
    const float* __restrict__ q, const float* __restrict__ k, const float* __restrict__ v,
    const float* __restrict__ wgate, const float* __restrict__ bgate,
    float* __restrict__ out)
{
    extern __shared__ float sm[];
    float* Qs   = sm;                    // 64*129
    float* KV   = Qs  + 64 * QSTR;       // 64*129 (shared K/V tile)
    float* Pb   = KV  + 64 * QSTR;       // 64*133
    float* rinv = Pb  + 64 * PSTR;       // 64
    float* rmax = rinv + 64;             // 64
    float* red  = rmax + 64;             // 256
    float* gts  = red  + 256;            // 192
    float* Cs   = gts  + 192;            // 64
    float* Gb   = Cs   + 64;             // 64
    float* wgs  = Gb   + 64;             // 384
    int*   topi = (int*)(wgs + 384);     // 2

    const int tid = threadIdx.x;
    const int bhq = blockIdx.x;
    const int qb  = bhq & (NQB - 1);
    const int bh  = bhq >> 4;
    const int h   = bh & (Hn - 1);
    const int b   = bh >> 3;
    const int q0  = qb * BQ;
    const int rho = tid >> 4;   // 0..15 row group
    const int gg  = tid & 15;   // 0..15 col group

    // ---- load Q tile + gate weights ----
    {
        const float4* q4 = (const float4*)(q + ((size_t)(b * Sn + q0) * Hn + h) * DIMn);
        for (int idx = tid; idx < 64 * 32; idx += 256) {
            int t = idx >> 5, d4 = idx & 31;
            float4 val = q4[(size_t)t * (Hn * DIMn / 4) + d4];
            float* ds = &Qs[t * QSTR + (d4 << 2)];
            ds[0] = val.x; ds[1] = val.y; ds[2] = val.z; ds[3] = val.w;
        }
        for (int i = tid; i < 3 * DIMn; i += 256) wgs[i] = wgate[i];
    }
    __syncthreads();

    // ---- gates: sigmoid(q . w_gate[c] + b_gate[c]) ----
    if (tid < 192) {
        int r = tid / 3, c = tid - 3 * r;
        float a = bgate[c];
        const float* qr = &Qs[r * QSTR];
        const float* wr = &wgs[c * DIMn];
#pragma unroll 8
        for (int d = 0; d < DIMn; ++d) a += qr[d] * wr[d];
        gts[r * 3 + c] = 1.0f / (1.0f + __expf(-a));
    }
    __syncthreads();

    float acc[4][8];
#pragma unroll
    for (int i = 0; i < 4; ++i)
#pragma unroll
        for (int j = 0; j < 8; ++j) acc[i][j] = 0.f;

    // ================= WINDOW branch (flash-style online softmax) =================
    {
        const int wbase = q0 - WINR;
        float m_[4], l_[4];
#pragma unroll
        for (int i = 0; i < 4; ++i) { m_[i] = NEG_INF; l_[i] = 0.f; }

#pragma unroll 1
        for (int kt = 0; kt < 5; ++kt) {
            load_tile_kv(KV, k, b, h, wbase + kt * 64, tid, true);
            __syncthreads();

            float s[4][4];
            qk_core(Qs, KV, s, rho, gg);

            // scale + band/range mask
#pragma unroll
            for (int i = 0; i < 4; ++i) {
                int r = rho + 16 * i;
#pragma unroll
                for (int j = 0; j < 4; ++j) {
                    int cgl = kt * 64 + gg + 16 * j;
                    int key = wbase + cgl;
                    bool ok = (key >= 0) && (key < Sn) && (cgl >= r) && (cgl <= r + 2 * WINR);
                    s[i][j] = ok ? s[i][j] * SCALE_MUL : NEG_INF;
                }
            }

            // online softmax update; stats replicated over the 16-lane column group
#pragma unroll
            for (int i = 0; i < 4; ++i) {
                float tm = fmaxf(fmaxf(s[i][0], s[i][1]), fmaxf(s[i][2], s[i][3]));
                tm = fmaxf(tm, __shfl_xor_sync(0xffffffffu, tm, 1));
                tm = fmaxf(tm, __shfl_xor_sync(0xffffffffu, tm, 2));
                tm = fmaxf(tm, __shfl_xor_sync(0xffffffffu, tm, 4));
                tm = fmaxf(tm, __shfl_xor_sync(0xffffffffu, tm, 8));
                float nm = fmaxf(m_[i], tm);
                float sc = __expf(m_[i] - nm);   // ==1 when both -inf (acc is 0 there)
                m_[i] = nm;
                float rs = 0.f;
#pragma unroll
                for (int j = 0; j < 4; ++j) {
                    float e = (s[i][j] > -1e29f) ? __expf(s[i][j] - nm) : 0.f;
                    s[i][j] = e;
                    rs += e;
                }
                rs += __shfl_xor_sync(0xffffffffu, rs, 1);
                rs += __shfl_xor_sync(0xffffffffu, rs, 2);
                rs += __shfl_xor_sync(0xffffffffu, rs, 4);
                rs += __shfl_xor_sync(0xffffffffu, rs, 8);
                l_[i] = l_[i] * sc + rs;
#pragma unroll
                for (int j = 0; j < 8; ++j) acc[i][j] *= sc;
                int r = rho + 16 * i;
#pragma unroll
                for (int j = 0; j < 4; ++j) Pb[r * PSTR + gg + 16 * j] = s[i][j];
            }
            __syncthreads();  // Pb written, K reads done

            load_tile_kv(KV, v, b, h, wbase + kt * 64, tid, true);
            __syncthreads();
            gemm_pv(Pb, KV, acc, rho, gg, 0);
            __syncthreads();
        }
        // finalize window: acc *= gate2 / rowsum
#pragma unroll
        for (int i = 0; i < 4; ++i) {
            int r = rho + 16 * i;
            float f = gts[r * 3 + 2] / l_[i];
#pragma unroll
            for (int j = 0; j < 8; ++j) acc[i][j] *= f;
        }
    }

    // ================= CMP branch =================
    load_tile_cmp(KV, g_cmpK, bh, tid);
    __syncthreads();
    gemm_qk<0>(Qs, KV, Pb, rho, gg, 0, SQRT_D);
    __syncthreads();
    softmax_rows(Pb, rmax, rinv, red, 64, tid);

    // column sums of normalized P_cmp
    if (tid < NCMP) {
        float s = 0.f;
#pragma unroll 4
        for (int r = 0; r < 64; ++r) s += Pb[r * PSTR + tid] * rinv[r];
        Cs[tid] = s;
    }
    __syncthreads();
    // slc-map convolution: weights 1,2,2,2,1 at i = 4j, 4j-1, 4j-2, 4j-3, 4j-4
    if (tid < NSLC) {
        int j4 = 4 * tid;
        float g = 0.f;
        if (j4 < NCMP)                       g += Cs[j4];
        if (j4 - 1 >= 0 && j4 - 1 < NCMP)    g += 2.f * Cs[j4 - 1];
        if (j4 - 2 >= 0 && j4 - 2 < NCMP)    g += 2.f * Cs[j4 - 2];
        if (j4 - 3 >= 0 && j4 - 3 < NCMP)    g += 2.f * Cs[j4 - 3];
        if (j4 - 4 >= 0 && j4 - 4 < NCMP)    g += Cs[j4 - 4];
        Gb[tid] = g;
    }
    __syncthreads();
    // deterministic top-2 (jax tie rule: lower index first)
    if (tid == 0) {
        int i0 = 0; float v0 = Gb[0];
        for (int j = 1; j < NSLC; ++j) if (Gb[j] > v0) { v0 = Gb[j]; i0 = j; }
        int i1 = 0; float v1 = NEG_INF;
        for (int j = 0; j < NSLC; ++j) if (j != i0 && Gb[j] > v1) { v1 = Gb[j]; i1 = j; }
        topi[0] = i0; topi[1] = i1;
    }
    scale_rows(Pb, rinv, gts, 0, 64, tid);   // fold in gate0 (ends with sync -> topi visible)
    load_tile_cmp(KV, g_cmpV, bh, tid);
    __syncthreads();
    gemm_pv(Pb, KV, acc, rho, gg, 0);
    __syncthreads();

    // ================= SLC branch =================
    {
        int j0 = topi[0], j1 = topi[1];
        load_tile_kv(KV, k, b, h, j0 * 16, tid, false);
        __syncthreads();
        gemm_qk<1>(Qs, KV, Pb, rho, gg, 0, SCALE_MUL);
        __syncthreads();
        load_tile_kv(KV, k, b, h, j1 * 16, tid, false);
        __syncthreads();
        gemm_qk<1>(Qs, KV, Pb, rho, gg, 64, SCALE_MUL);
        __syncthreads();

        softmax_rows(Pb, rmax, rinv, red, 128, tid);
        scale_rows(Pb, rinv, gts, 1, 128, tid);

        load_tile_kv(KV, v, b, h, j0 * 16, tid, false);
        __syncthreads();
        gemm_pv(Pb, KV, acc, rho, gg, 0);
        __syncthreads();
        load_tile_kv(KV, v, b, h, j1 * 16, tid, false);
        __syncthreads();
        gemm_pv(Pb, KV, acc, rho, gg, 64);
    }

    // ---- write output ----
#pragma unroll
    for (int i = 0; i < 4; ++i) {
        int r = rho + 16 * i;
        float* op = out + ((size_t)(b * Sn + q0 + r) * Hn + h) * DIMn + gg;
#pragma unroll
        for (int j = 0; j < 8; ++j) op[16 * j] = acc[i][j];
    }
}

// ---------------- launch ----------------
extern "C" void kernel_launch(void* const* d_in, const int* in_sizes, int n_in,
                              void* d_out, int out_size)
{
    (void)in_sizes; (void)n_in; (void)out_size;
    const float* q   = (const float*)d_in[0];
    const float* k   = (const float*)d_in[1];
    const float* v   = (const float*)d_in[2];
    const float* wck = (const float*)d_in[3];
    const float* bck = (const float*)d_in[4];
    const float* wcv = (const float*)d_in[5];
    const float* bcv = (const float*)d_in[6];
    const float* wg  = (const float*)d_in[7];
    const float* bg  = (const float*)d_in[8];
    float* out = (float*)d_out;

    // kernel A: compressed K/V
    int totalA = Bn * Hn * NCMP * DIMn;
    cmp_kv_kernel<<<(totalA + 255) / 256, 256>>>(k, v, wck, bck, wcv, bcv);

    // fused NSA kernel
    size_t smem_floats = (size_t)2 * 64 * QSTR + (size_t)64 * PSTR
                       + 64 + 64 + 256 + 192 + 64 + 64 + 384 + 4;
    size_t smem_bytes = smem_floats * sizeof(float);
    cudaFuncSetAttribute(nsa_main, cudaFuncAttributeMaxDynamicSharedMemorySize,
                         (int)smem_bytes);
    nsa_main<<<Bn * Hn * NQB, 256, smem_bytes>>>(q, k, v, wg, bg, out);
}

// round 10
// speedup vs baseline: 1.2289x; 1.2289x over previous
#include <cuda_runtime.h>

// ---------------- problem constants ----------------
#define Bn    2
#define Sn    1024
#define Hn    8
#define DIMn  128
#define LCMP  32
#define NCMP  63          // (1024-32)/16+1
#define NSLC  61          // (1024-64)/16+1
#define BQ    64
#define NQB   (Sn / BQ)   // 16
#define WINR  128
#define QSTR  130         // even (8B-aligned rows), ==2 mod 4 (conflict-free LDS.64)
#define PSTR  130
#define NEG_INF (-1e30f)

#define SCALE_MUL 0.08838834764831845f   // 1/sqrt(128): slc & window
#define SQRT_D    11.313708498984761f    // sqrt(128): cmp branch (reference divides by scale)

typedef unsigned long long u64;

// ---------------- f32x2 packed helpers ----------------
__device__ __forceinline__ u64 FMA2(u64 a, u64 b, u64 c) {
    u64 d;
    asm("fma.rn.f32x2 %0, %1, %2, %3;" : "=l"(d) : "l"(a), "l"(b), "l"(c));
    return d;
}
__device__ __forceinline__ u64 MUL2(u64 a, u64 b) {
    u64 d;
    asm("mul.rn.f32x2 %0, %1, %2;" : "=l"(d) : "l"(a), "l"(b));
    return d;
}
__device__ __forceinline__ u64 DUP2(float p) {
    u64 d;
    asm("mov.b64 %0, {%1, %1};" : "=l"(d) : "f"(p));
    return d;
}
__device__ __forceinline__ void UNPK(u64 a, float& x, float& y) {
    asm("mov.b64 {%0, %1}, %2;" : "=f"(x), "=f"(y) : "l"(a));
}
__device__ __forceinline__ u64 PK2(float x, float y) {
    u64 d;
    asm("mov.b64 %0, {%1, %2};" : "=l"(d) : "f"(x), "f"(y));
    return d;
}

// scratch for compressed K/V: [b][h][n][d]
__device__ float g_cmpK[Bn * Hn * NCMP * DIMn];
__device__ float g_cmpV[Bn * Hn * NCMP * DIMn];

// ---------------- kernel A: compressed K/V ----------------
__global__ void __launch_bounds__(256) cmp_kv_kernel(
    const float* __restrict__ k, const float* __restrict__ v,
    const float* __restrict__ wck, const float* __restrict__ bck,
    const float* __restrict__ wcv, const float* __restrict__ bcv)
{
    __shared__ float swk[LCMP], swv[LCMP], sb[2];
    int tid = threadIdx.x;
    if (tid < LCMP) { swk[tid] = wck[tid]; swv[tid] = wcv[tid]; }
    if (tid == 0)   { sb[0] = bck[0]; sb[1] = bcv[0]; }
    __syncthreads();

    int idx = blockIdx.x * 256 + tid;
    if (idx >= Bn * Hn * NCMP * DIMn) return;
    int d  = idx & (DIMn - 1);
    int n  = (idx >> 7) % NCMP;
    int bh = idx / (NCMP * DIMn);
    int h  = bh & (Hn - 1);
    int b  = bh >> 3;

    const float* kb = k + ((size_t)(b * Sn + n * 16) * Hn + h) * DIMn + d;
    const float* vb = v + ((size_t)(b * Sn + n * 16) * Hn + h) * DIMn + d;
    float ak = 0.f, av = 0.f;
#pragma unroll
    for (int l = 0; l < LCMP; ++l) {
        ak += kb[(size_t)l * Hn * DIMn] * swk[l];
        av += vb[(size_t)l * Hn * DIMn] * swv[l];
    }
    g_cmpK[idx] = ak + sb[0];
    g_cmpV[idx] = av + sb[1];
}

// ---------------- helpers for the fused kernel ----------------

// QK core (f32x2 along kd): s[4][4] = Qs(64x128) * Ks(64x128)^T
__device__ __forceinline__ void qk_core(const float* __restrict__ Qs,
                                        const float* __restrict__ Ks,
                                        float s[4][4], int rho, int gg)
{
    u64 s2[4][4];
#pragma unroll
    for (int i = 0; i < 4; ++i)
#pragma unroll
        for (int j = 0; j < 4; ++j) s2[i][j] = 0ULL;

    const u64* qp = (const u64*)(Qs + rho * QSTR);
    const u64* kp = (const u64*)(Ks + gg  * QSTR);
    const int RS = 8 * QSTR;   // 16 rows in u64 units
#pragma unroll 4
    for (int kd = 0; kd < DIMn / 2; ++kd) {
        u64 a0 = qp[kd];
        u64 a1 = qp[RS + kd];
        u64 a2 = qp[2 * RS + kd];
        u64 a3 = qp[3 * RS + kd];
        u64 b0 = kp[kd];
        u64 b1 = kp[RS + kd];
        u64 b2 = kp[2 * RS + kd];
        u64 b3 = kp[3 * RS + kd];
        s2[0][0] = FMA2(a0, b0, s2[0][0]); s2[0][1] = FMA2(a0, b1, s2[0][1]);
        s2[0][2] = FMA2(a0, b2, s2[0][2]); s2[0][3] = FMA2(a0, b3, s2[0][3]);
        s2[1][0] = FMA2(a1, b0, s2[1][0]); s2[1][1] = FMA2(a1, b1, s2[1][1]);
        s2[1][2] = FMA2(a1, b2, s2[1][2]); s2[1][3] = FMA2(a1, b3, s2[1][3]);
        s2[2][0] = FMA2(a2, b0, s2[2][0]); s2[2][1] = FMA2(a2, b1, s2[2][1]);
        s2[2][2] = FMA2(a2, b2, s2[2][2]); s2[2][3] = FMA2(a2, b3, s2[2][3]);
        s2[3][0] = FMA2(a3, b0, s2[3][0]); s2[3][1] = FMA2(a3, b1, s2[3][1]);
        s2[3][2] = FMA2(a3, b2, s2[3][2]); s2[3][3] = FMA2(a3, b3, s2[3][3]);
    }
#pragma unroll
    for (int i = 0; i < 4; ++i)
#pragma unroll
        for (int j = 0; j < 4; ++j) {
            float x, y; UNPK(s2[i][j], x, y);
            s[i][j] = x + y;
        }
}

// QK GEMM -> Pb.  MODE 0 = cmp (mask c>=NCMP), 1 = slc (no mask)
template <int MODE>
__device__ __forceinline__ void gemm_qk(const float* __restrict__ Qs,
                                        const float* __restrict__ Ks,
                                        float* __restrict__ Pb,
                                        int rho, int gg, int cb, float scl)
{
    float s[4][4];
    qk_core(Qs, Ks, s, rho, gg);
#pragma unroll
    for (int i = 0; i < 4; ++i) {
        int r = rho + 16 * i;
#pragma unroll
        for (int j = 0; j < 4; ++j) {
            int c = gg + 16 * j;
            float val = s[i][j] * scl;
            if (MODE == 0) {
                if (c >= NCMP) val = NEG_INF;
            }
            Pb[r * PSTR + cb + c] = val;
        }
    }
}

// PV GEMM (f32x2 along output cols): acc2[4][4] += P(64 x 64-tile) * Vs(64x128)
// thread owns column pairs {2gg+32m, 2gg+32m+1}, m=0..3
__device__ __forceinline__ void gemm_pv(const float* __restrict__ Pb,
                                        const float* __restrict__ Vs,
                                        u64 acc2[4][4], int rho, int gg, int cb)
{
    const float* pp = Pb + rho * PSTR + cb;
    const float* vb = Vs + 2 * gg;
#pragma unroll 2
    for (int cl = 0; cl < 64; cl += 2) {
        const u64* vr0 = (const u64*)(vb + cl * QSTR);
        const u64* vr1 = (const u64*)(vb + (cl + 1) * QSTR);
        u64 v0[4], v1[4];
#pragma unroll
        for (int m = 0; m < 4; ++m) { v0[m] = vr0[16 * m]; v1[m] = vr1[16 * m]; }
#pragma unroll
        for (int i = 0; i < 4; ++i) {
            u64 p2 = *(const u64*)(pp + 16 * i * PSTR + cl);
            float pa, pbv; UNPK(p2, pa, pbv);
            u64 da = DUP2(pa), db = DUP2(pbv);
#pragma unroll
            for (int m = 0; m < 4; ++m) {
                acc2[i][m] = FMA2(da, v0[m], acc2[i][m]);
                acc2[i][m] = FMA2(db, v1[m], acc2[i][m]);
            }
        }
    }
}

// two-pass row softmax over Pb[:, 0:NK]; leaves exp() in Pb, 1/rowsum in rinv
__device__ __forceinline__ void softmax_rows(float* __restrict__ Pb,
                                             float* __restrict__ rmax,
                                             float* __restrict__ rinv,
                                             float* __restrict__ red,
                                             int NK, int tid)
{
    int r = tid & 63, part = tid >> 6;
    float m = NEG_INF;
    for (int c = part; c < NK; c += 4) m = fmaxf(m, Pb[r * PSTR + c]);
    red[part * 64 + r] = m;
    __syncthreads();
    if (tid < 64)
        rmax[tid] = fmaxf(fmaxf(red[tid], red[64 + tid]),
                          fmaxf(red[128 + tid], red[192 + tid]));
    __syncthreads();
    float mr = rmax[r];
    float sum = 0.f;
    for (int c = part; c < NK; c += 4) {
        float e = __expf(Pb[r * PSTR + c] - mr);
        Pb[r * PSTR + c] = e;
        sum += e;
    }
    red[part * 64 + r] = sum;
    __syncthreads();
    if (tid < 64)
        rinv[tid] = 1.0f / (red[tid] + red[64 + tid] + red[128 + tid] + red[192 + tid]);
    __syncthreads();
}

// P[r][c] *= gate[r][gi] / rowsum[r]
__device__ __forceinline__ void scale_rows(float* __restrict__ Pb,
                                           const float* __restrict__ rinv,
                                           const float* __restrict__ gts,
                                           int gi, int NK, int tid)
{
    int r = tid & 63, part = tid >> 6;
    float f = gts[r * 3 + gi] * rinv[r];
    for (int c = part; c < NK; c += 4) Pb[r * PSTR + c] *= f;
    __syncthreads();
}

// load a 64x128 tile from q/k/v-layout global memory into padded smem, zero-fill invalid
__device__ __forceinline__ void load_tile_kv(float* __restrict__ dst,
                                             const float* __restrict__ src,
                                             int b, int h, int s_base, int tid, bool check)
{
    for (int idx = tid; idx < 64 * 32; idx += 256) {
        int t = idx >> 5, d4 = idx & 31;
        int srow = s_base + t;
        float4 val = make_float4(0.f, 0.f, 0.f, 0.f);
        if (!check || ((unsigned)srow < (unsigned)Sn))
            val = ((const float4*)(src + ((size_t)(b * Sn + srow) * Hn + h) * DIMn))[d4];
        float* ds = &dst[t * QSTR + (d4 << 2)];
        ds[0] = val.x; ds[1] = val.y; ds[2] = val.z; ds[3] = val.w;
    }
}

// load compressed K/V tile (63 rows), zero row 63
__device__ __forceinline__ void load_tile_cmp(float* __restrict__ dst,
                                              const float* __restrict__ src,
                                              int bh, int tid)
{
    for (int idx = tid; idx < 64 * 32; idx += 256) {
        int t = idx >> 5, d4 = idx & 31;
        float4 val = make_float4(0.f, 0.f, 0.f, 0.f);
        if (t < NCMP)
            val = ((const float4*)(src + ((size_t)bh * NCMP + t) * DIMn))[d4];
        float* ds = &dst[t * QSTR + (d4 << 2)];
        ds[0] = val.x; ds[1] = val.y; ds[2] = val.z; ds[3] = val.w;
    }
}

// ---------------- fused main kernel ----------------
__global__ void __launch_bounds__(256, 2) nsa_main(
    const float* __restrict__ q, const float* __restrict__ k, const float* __restrict__ v,
    const float* __restrict__ wgate, const float* __restrict__ bgate,
    float* __restrict__ out)
{
    extern __shared__ float sm[];
    float* Qs   = sm;                    // 64*130
    float* KV   = Qs  + 64 * QSTR;       // 64*130 (shared K/V tile)
    float* Pb   = KV  + 64 * QSTR;       // 64*130
    float* rinv = Pb  + 64 * PSTR;       // 64
    float* rmax = rinv + 64;             // 64
    float* red  = rmax + 64;             // 256
    float* gts  = red  + 256;            // 192
    float* Cs   = gts  + 192;            // 64
    float* Gb   = Cs   + 64;             // 64
    float* wgs  = Gb   + 64;             // 384
    int*   topi = (int*)(wgs + 384);     // 2

    const int tid = threadIdx.x;
    const int bhq = blockIdx.x;
    const int qb  = bhq & (NQB - 1);
    const int bh  = bhq >> 4;
    const int h   = bh & (Hn - 1);
    const int b   = bh >> 3;
    const int q0  = qb * BQ;
    const int rho = tid >> 4;   // 0..15 row group
    const int gg  = tid & 15;   // 0..15 col group

    // ---- load Q tile + gate weights ----
    {
        const float4* q4 = (const float4*)(q + ((size_t)(b * Sn + q0) * Hn + h) * DIMn);
        for (int idx = tid; idx < 64 * 32; idx += 256) {
            int t = idx >> 5, d4 = idx & 31;
            float4 val = q4[(size_t)t * (Hn * DIMn / 4) + d4];
            float* ds = &Qs[t * QSTR + (d4 << 2)];
            ds[0] = val.x; ds[1] = val.y; ds[2] = val.z; ds[3] = val.w;
        }
        for (int i = tid; i < 3 * DIMn; i += 256) wgs[i] = wgate[i];
    }
    __syncthreads();

    // ---- gates: sigmoid(q . w_gate[c] + b_gate[c]) ----
    if (tid < 192) {
        int r = tid / 3, c = tid - 3 * r;
        float a = bgate[c];
        const float* qr = &Qs[r * QSTR];
        const float* wr = &wgs[c * DIMn];
#pragma unroll 8
        for (int d = 0; d < DIMn; ++d) a += qr[d] * wr[d];
        gts[r * 3 + c] = 1.0f / (1.0f + __expf(-a));
    }
    __syncthreads();

    u64 acc2[4][4];
#pragma unroll
    for (int i = 0; i < 4; ++i)
#pragma unroll
        for (int m = 0; m < 4; ++m) acc2[i][m] = 0ULL;

    // ================= WINDOW branch (flash-style online softmax) =================
    {
        const int wbase = q0 - WINR;
        float m_[4], l_[4];
#pragma unroll
        for (int i = 0; i < 4; ++i) { m_[i] = NEG_INF; l_[i] = 0.f; }

#pragma unroll 1
        for (int kt = 0; kt < 5; ++kt) {
            load_tile_kv(KV, k, b, h, wbase + kt * 64, tid, true);
            __syncthreads();

            float s[4][4];
            qk_core(Qs, KV, s, rho, gg);

            // scale + band/range mask
#pragma unroll
            for (int i = 0; i < 4; ++i) {
                int r = rho + 16 * i;
#pragma unroll
                for (int j = 0; j < 4; ++j) {
                    int cgl = kt * 64 + gg + 16 * j;
                    int key = wbase + cgl;
                    bool ok = (key >= 0) && (key < Sn) && (cgl >= r) && (cgl <= r + 2 * WINR);
                    s[i][j] = ok ? s[i][j] * SCALE_MUL : NEG_INF;
                }
            }

            // online softmax update; stats replicated over the 16-lane column group
#pragma unroll
            for (int i = 0; i < 4; ++i) {
                float tm = fmaxf(fmaxf(s[i][0], s[i][1]), fmaxf(s[i][2], s[i][3]));
                tm = fmaxf(tm, __shfl_xor_sync(0xffffffffu, tm, 1));
                tm = fmaxf(tm, __shfl_xor_sync(0xffffffffu, tm, 2));
                tm = fmaxf(tm, __shfl_xor_sync(0xffffffffu, tm, 4));
                tm = fmaxf(tm, __shfl_xor_sync(0xffffffffu, tm, 8));
                float nm = fmaxf(m_[i], tm);
                float sc = __expf(m_[i] - nm);   // ==1 when both -inf (acc is 0 there)
                m_[i] = nm;
                float rs = 0.f;
#pragma unroll
                for (int j = 0; j < 4; ++j) {
                    float e = (s[i][j] > -1e29f) ? __expf(s[i][j] - nm) : 0.f;
                    s[i][j] = e;
                    rs += e;
                }
                rs += __shfl_xor_sync(0xffffffffu, rs, 1);
                rs += __shfl_xor_sync(0xffffffffu, rs, 2);
                rs += __shfl_xor_sync(0xffffffffu, rs, 4);
                rs += __shfl_xor_sync(0xffffffffu, rs, 8);
                l_[i] = l_[i] * sc + rs;
                u64 sc2 = DUP2(sc);
#pragma unroll
                for (int m = 0; m < 4; ++m) acc2[i][m] = MUL2(acc2[i][m], sc2);
                int r = rho + 16 * i;
#pragma unroll
                for (int j = 0; j < 4; ++j) Pb[r * PSTR + gg + 16 * j] = s[i][j];
            }
            __syncthreads();  // Pb written, K reads done

            load_tile_kv(KV, v, b, h, wbase + kt * 64, tid, true);
            __syncthreads();
            gemm_pv(Pb, KV, acc2, rho, gg, 0);
            __syncthreads();
        }
        // finalize window: acc *= gate2 / rowsum
#pragma unroll
        for (int i = 0; i < 4; ++i) {
            int r = rho + 16 * i;
            u64 f2 = DUP2(gts[r * 3 + 2] / l_[i]);
#pragma unroll
            for (int m = 0; m < 4; ++m) acc2[i][m] = MUL2(acc2[i][m], f2);
        }
    }

    // ================= CMP branch =================
    load_tile_cmp(KV, g_cmpK, bh, tid);
    __syncthreads();
    gemm_qk<0>(Qs, KV, Pb, rho, gg, 0, SQRT_D);
    __syncthreads();
    softmax_rows(Pb, rmax, rinv, red, 64, tid);

    // column sums of normalized P_cmp
    if (tid < NCMP) {
        float s = 0.f;
#pragma unroll 4
        for (int r = 0; r < 64; ++r) s += Pb[r * PSTR + tid] * rinv[r];
        Cs[tid] = s;
    }
    __syncthreads();
    // slc-map convolution: weights 1,2,2,2,1 at i = 4j, 4j-1, 4j-2, 4j-3, 4j-4
    if (tid < NSLC) {
        int j4 = 4 * tid;
        float g = 0.f;
        if (j4 < NCMP)                       g += Cs[j4];
        if (j4 - 1 >= 0 && j4 - 1 < NCMP)    g += 2.f * Cs[j4 - 1];
        if (j4 - 2 >= 0 && j4 - 2 < NCMP)    g += 2.f * Cs[j4 - 2];
        if (j4 - 3 >= 0 && j4 - 3 < NCMP)    g += 2.f * Cs[j4 - 3];
        if (j4 - 4 >= 0 && j4 - 4 < NCMP)    g += Cs[j4 - 4];
        Gb[tid] = g;
    }
    __syncthreads();
    // deterministic top-2 (jax tie rule: lower index first)
    if (tid == 0) {
        int i0 = 0; float v0 = Gb[0];
        for (int j = 1; j < NSLC; ++j) if (Gb[j] > v0) { v0 = Gb[j]; i0 = j; }
        int i1 = 0; float v1 = NEG_INF;
        for (int j = 0; j < NSLC; ++j) if (j != i0 && Gb[j] > v1) { v1 = Gb[j]; i1 = j; }
        topi[0] = i0; topi[1] = i1;
    }
    scale_rows(Pb, rinv, gts, 0, 64, tid);   // fold in gate0 (ends with sync -> topi visible)
    load_tile_cmp(KV, g_cmpV, bh, tid);
    __syncthreads();
    gemm_pv(Pb, KV, acc2, rho, gg, 0);
    __syncthreads();

    // ================= SLC branch =================
    {
        int j0 = topi[0], j1 = topi[1];
        load_tile_kv(KV, k, b, h, j0 * 16, tid, false);
        __syncthreads();
        gemm_qk<1>(Qs, KV, Pb, rho, gg, 0, SCALE_MUL);
        __syncthreads();
        load_tile_kv(KV, k, b, h, j1 * 16, tid, false);
        __syncthreads();
        gemm_qk<1>(Qs, KV, Pb, rho, gg, 64, SCALE_MUL);
        __syncthreads();

        softmax_rows(Pb, rmax, rinv, red, 128, tid);
        scale_rows(Pb, rinv, gts, 1, 128, tid);

        load_tile_kv(KV, v, b, h, j0 * 16, tid, false);
        __syncthreads();
        gemm_pv(Pb, KV, acc2, rho, gg, 0);
        __syncthreads();
        load_tile_kv(KV, v, b, h, j1 * 16, tid, false);
        __syncthreads();
        gemm_pv(Pb, KV, acc2, rho, gg, 64);
    }

    // ---- write output (column pairs 2gg+32m) ----
#pragma unroll
    for (int i = 0; i < 4; ++i) {
        int r = rho + 16 * i;
        float* op = out + ((size_t)(b * Sn + q0 + r) * Hn + h) * DIMn + 2 * gg;
#pragma unroll
        for (int m = 0; m < 4; ++m) {
            float x, y; UNPK(acc2[i][m], x, y);
            *(float2*)(op + 32 * m) = make_float2(x, y);
        }
    }
}

// ---------------- launch ----------------
extern "C" void kernel_launch(void* const* d_in, const int* in_sizes, int n_in,
                              void* d_out, int out_size)
{
    (void)in_sizes; (void)n_in; (void)out_size;
    const float* q   = (const float*)d_in[0];
    const float* k   = (const float*)d_in[1];
    const float* v   = (const float*)d_in[2];
    const float* wck = (const float*)d_in[3];
    const float* bck = (const float*)d_in[4];
    const float* wcv = (const float*)d_in[5];
    const float* bcv = (const float*)d_in[6];
    const float* wg  = (const float*)d_in[7];
    const float* bg  = (const float*)d_in[8];
    float* out = (float*)d_out;

    // kernel A: compressed K/V
    int totalA = Bn * Hn * NCMP * DIMn;
    cmp_kv_kernel<<<(totalA + 255) / 256, 256>>>(k, v, wck, bck, wcv, bcv);

    // fused NSA kernel
    size_t smem_floats = (size_t)2 * 64 * QSTR + (size_t)64 * PSTR
                       + 64 + 64 + 256 + 192 + 64 + 64 + 384 + 4;
    size_t smem_bytes = smem_floats * sizeof(float);
    cudaFuncSetAttribute(nsa_main, cudaFuncAttributeMaxDynamicSharedMemorySize,
                         (int)smem_bytes);
    nsa_main<<<Bn * Hn * NQB, 256, smem_bytes>>>(q, k, v, wg, bg, out);
}

// round 11
// speedup vs baseline: 1.2393x; 1.0084x over previous
#include <cuda_runtime.h>

// ---------------- problem constants ----------------
#define Bn    2
#define Sn    1024
#define Hn    8
#define DIMn  128
#define LCMP  32
#define NCMP  63          // (1024-32)/16+1
#define NSLC  61          // (1024-64)/16+1
#define BQ    64
#define NQB   (Sn / BQ)   // 16
#define WINR  128
#define QSTR  130         // even (8B-aligned rows), ==2 mod 4 (conflict-free LDS.64)
#define PSTR  130
#define NEG_INF (-1e30f)

#define SCALE_MUL 0.08838834764831845f   // 1/sqrt(128): slc & window
#define SQRT_D    11.313708498984761f    // sqrt(128): cmp branch (reference divides by scale)

typedef unsigned long long u64;

// ---------------- f32x2 packed helpers ----------------
__device__ __forceinline__ u64 FMA2(u64 a, u64 b, u64 c) {
    u64 d;
    asm("fma.rn.f32x2 %0, %1, %2, %3;" : "=l"(d) : "l"(a), "l"(b), "l"(c));
    return d;
}
__device__ __forceinline__ u64 MUL2(u64 a, u64 b) {
    u64 d;
    asm("mul.rn.f32x2 %0, %1, %2;" : "=l"(d) : "l"(a), "l"(b));
    return d;
}
__device__ __forceinline__ u64 DUP2(float p) {
    u64 d;
    asm("mov.b64 %0, {%1, %1};" : "=l"(d) : "f"(p));
    return d;
}
__device__ __forceinline__ void UNPK(u64 a, float& x, float& y) {
    asm("mov.b64 {%0, %1}, %2;" : "=f"(x), "=f"(y) : "l"(a));
}
__device__ __forceinline__ u64 PK2(float x, float y) {
    u64 d;
    asm("mov.b64 %0, {%1, %2};" : "=l"(d) : "f"(x), "f"(y));
    return d;
}

// scratch for compressed K/V: [b][h][n][d]
__device__ float g_cmpK[Bn * Hn * NCMP * DIMn];
__device__ float g_cmpV[Bn * Hn * NCMP * DIMn];

// ---------------- kernel A: compressed K/V ----------------
__global__ void __launch_bounds__(256) cmp_kv_kernel(
    const float* __restrict__ k, const float* __restrict__ v,
    const float* __restrict__ wck, const float* __restrict__ bck,
    const float* __restrict__ wcv, const float* __restrict__ bcv)
{
    __shared__ float swk[LCMP], swv[LCMP], sb[2];
    int tid = threadIdx.x;
    if (tid < LCMP) { swk[tid] = wck[tid]; swv[tid] = wcv[tid]; }
    if (tid == 0)   { sb[0] = bck[0]; sb[1] = bcv[0]; }
    __syncthreads();

    int idx = blockIdx.x * 256 + tid;
    if (idx >= Bn * Hn * NCMP * DIMn) return;
    int d  = idx & (DIMn - 1);
    int n  = (idx >> 7) % NCMP;
    int bh = idx / (NCMP * DIMn);
    int h  = bh & (Hn - 1);
    int b  = bh >> 3;

    const float* kb = k + ((size_t)(b * Sn + n * 16) * Hn + h) * DIMn + d;
    const float* vb = v + ((size_t)(b * Sn + n * 16) * Hn + h) * DIMn + d;
    float ak = 0.f, av = 0.f;
#pragma unroll
    for (int l = 0; l < LCMP; ++l) {
        ak += kb[(size_t)l * Hn * DIMn] * swk[l];
        av += vb[(size_t)l * Hn * DIMn] * swv[l];
    }
    g_cmpK[idx] = ak + sb[0];
    g_cmpV[idx] = av + sb[1];
}

// ---------------- helpers for the fused kernel ----------------

// QK core (f32x2 along kd): s[4][4] = Qs(64x128) * Ks(64x128)^T
__device__ __forceinline__ void qk_core(const float* __restrict__ Qs,
                                        const float* __restrict__ Ks,
                                        float s[4][4], int rho, int gg)
{
    u64 s2[4][4];
#pragma unroll
    for (int i = 0; i < 4; ++i)
#pragma unroll
        for (int j = 0; j < 4; ++j) s2[i][j] = 0ULL;

    const u64* qp = (const u64*)(Qs + rho * QSTR);
    const u64* kp = (const u64*)(Ks + gg  * QSTR);
    const int RS = 8 * QSTR;   // 16 rows in u64 units
#pragma unroll 4
    for (int kd = 0; kd < DIMn / 2; ++kd) {
        u64 a0 = qp[kd];
        u64 a1 = qp[RS + kd];
        u64 a2 = qp[2 * RS + kd];
        u64 a3 = qp[3 * RS + kd];
        u64 b0 = kp[kd];
        u64 b1 = kp[RS + kd];
        u64 b2 = kp[2 * RS + kd];
        u64 b3 = kp[3 * RS + kd];
        s2[0][0] = FMA2(a0, b0, s2[0][0]); s2[0][1] = FMA2(a0, b1, s2[0][1]);
        s2[0][2] = FMA2(a0, b2, s2[0][2]); s2[0][3] = FMA2(a0, b3, s2[0][3]);
        s2[1][0] = FMA2(a1, b0, s2[1][0]); s2[1][1] = FMA2(a1, b1, s2[1][1]);
        s2[1][2] = FMA2(a1, b2, s2[1][2]); s2[1][3] = FMA2(a1, b3, s2[1][3]);
        s2[2][0] = FMA2(a2, b0, s2[2][0]); s2[2][1] = FMA2(a2, b1, s2[2][1]);
        s2[2][2] = FMA2(a2, b2, s2[2][2]); s2[2][3] = FMA2(a2, b3, s2[2][3]);
        s2[3][0] = FMA2(a3, b0, s2[3][0]); s2[3][1] = FMA2(a3, b1, s2[3][1]);
        s2[3][2] = FMA2(a3, b2, s2[3][2]); s2[3][3] = FMA2(a3, b3, s2[3][3]);
    }
#pragma unroll
    for (int i = 0; i < 4; ++i)
#pragma unroll
        for (int j = 0; j < 4; ++j) {
            float x, y; UNPK(s2[i][j], x, y);
            s[i][j] = x + y;
        }
}

// QK GEMM -> Pb.  MODE 0 = cmp (mask c>=NCMP), 1 = slc (no mask)
template <int MODE>
__device__ __forceinline__ void gemm_qk(const float* __restrict__ Qs,
                                        const float* __restrict__ Ks,
                                        float* __restrict__ Pb,
                                        int rho, int gg, int cb, float scl)
{
    float s[4][4];
    qk_core(Qs, Ks, s, rho, gg);
#pragma unroll
    for (int i = 0; i < 4; ++i) {
        int r = rho + 16 * i;
#pragma unroll
        for (int j = 0; j < 4; ++j) {
            int c = gg + 16 * j;
            float val = s[i][j] * scl;
            if (MODE == 0) {
                if (c >= NCMP) val = NEG_INF;
            }
            Pb[r * PSTR + cb + c] = val;
        }
    }
}

// PV GEMM (f32x2 along output cols): acc2[4][4] += P(64 x 64-tile) * Vs(64x128)
// thread owns column pairs {2gg+32m, 2gg+32m+1}, m=0..3
__device__ __forceinline__ void gemm_pv(const float* __restrict__ Pb,
                                        const float* __restrict__ Vs,
                                        u64 acc2[4][4], int rho, int gg, int cb)
{
    const float* pp = Pb + rho * PSTR + cb;
    const float* vb = Vs + 2 * gg;
#pragma unroll 2
    for (int cl = 0; cl < 64; cl += 2) {
        const u64* vr0 = (const u64*)(vb + cl * QSTR);
        const u64* vr1 = (const u64*)(vb + (cl + 1) * QSTR);
        u64 v0[4], v1[4];
#pragma unroll
        for (int m = 0; m < 4; ++m) { v0[m] = vr0[16 * m]; v1[m] = vr1[16 * m]; }
#pragma unroll
        for (int i = 0; i < 4; ++i) {
            u64 p2 = *(const u64*)(pp + 16 * i * PSTR + cl);
            float pa, pbv; UNPK(p2, pa, pbv);
            u64 da = DUP2(pa), db = DUP2(pbv);
#pragma unroll
            for (int m = 0; m < 4; ++m) {
                acc2[i][m] = FMA2(da, v0[m], acc2[i][m]);
                acc2[i][m] = FMA2(db, v1[m], acc2[i][m]);
            }
        }
    }
}

// two-pass row softmax over Pb[:, 0:NK]; leaves exp() in Pb, 1/rowsum in rinv
__device__ __forceinline__ void softmax_rows(float* __restrict__ Pb,
                                             float* __restrict__ rmax,
                                             float* __restrict__ rinv,
                                             float* __restrict__ red,
                                             int NK, int tid)
{
    int r = tid & 63, part = tid >> 6;
    float m = NEG_INF;
    for (int c = part; c < NK; c += 4) m = fmaxf(m, Pb[r * PSTR + c]);
    red[part * 64 + r] = m;
    __syncthreads();
    if (tid < 64)
        rmax[tid] = fmaxf(fmaxf(red[tid], red[64 + tid]),
                          fmaxf(red[128 + tid], red[192 + tid]));
    __syncthreads();
    float mr = rmax[r];
    float sum = 0.f;
    for (int c = part; c < NK; c += 4) {
        float e = __expf(Pb[r * PSTR + c] - mr);
        Pb[r * PSTR + c] = e;
        sum += e;
    }
    red[part * 64 + r] = sum;
    __syncthreads();
    if (tid < 64)
        rinv[tid] = 1.0f / (red[tid] + red[64 + tid] + red[128 + tid] + red[192 + tid]);
    __syncthreads();
}

// P[r][c] *= gate[r][gi] / rowsum[r]
__device__ __forceinline__ void scale_rows(float* __restrict__ Pb,
                                           const float* __restrict__ rinv,
                                           const float* __restrict__ gts,
                                           int gi, int NK, int tid)
{
    int r = tid & 63, part = tid >> 6;
    float f = gts[r * 3 + gi] * rinv[r];
    for (int c = part; c < NK; c += 4) Pb[r * PSTR + c] *= f;
    __syncthreads();
}

// load a 64x128 tile from q/k/v-layout global memory into padded smem, zero-fill invalid
__device__ __forceinline__ void load_tile_kv(float* __restrict__ dst,
                                             const float* __restrict__ src,
                                             int b, int h, int s_base, int tid, bool check)
{
    for (int idx = tid; idx < 64 * 32; idx += 256) {
        int t = idx >> 5, d4 = idx & 31;
        int srow = s_base + t;
        float4 val = make_float4(0.f, 0.f, 0.f, 0.f);
        if (!check || ((unsigned)srow < (unsigned)Sn))
            val = ((const float4*)(src + ((size_t)(b * Sn + srow) * Hn + h) * DIMn))[d4];
        float* ds = &dst[t * QSTR + (d4 << 2)];
        ds[0] = val.x; ds[1] = val.y; ds[2] = val.z; ds[3] = val.w;
    }
}

// load compressed K/V tile (63 rows), zero row 63
__device__ __forceinline__ void load_tile_cmp(float* __restrict__ dst,
                                              const float* __restrict__ src,
                                              int bh, int tid)
{
    for (int idx = tid; idx < 64 * 32; idx += 256) {
        int t = idx >> 5, d4 = idx & 31;
        float4 val = make_float4(0.f, 0.f, 0.f, 0.f);
        if (t < NCMP)
            val = ((const float4*)(src + ((size_t)bh * NCMP + t) * DIMn))[d4];
        float* ds = &dst[t * QSTR + (d4 << 2)];
        ds[0] = val.x; ds[1] = val.y; ds[2] = val.z; ds[3] = val.w;
    }
}

// ---------------- fused main kernel ----------------
__global__ void __launch_bounds__(256, 2) nsa_main(
    const float* __restrict__ q, const float* __restrict__ k, const float* __restrict__ v,
    const float* __restrict__ wgate, const float* __restrict__ bgate,
    float* __restrict__ out)
{
    extern __shared__ float sm[];
    float* Qs   = sm;                    // 64*130
    float* KV   = Qs  + 64 * QSTR;       // 64*130 (shared K/V tile)
    float* Pb   = KV  + 64 * QSTR;       // 64*130
    float* rinv = Pb  + 64 * PSTR;       // 64
    float* rmax = rinv + 64;             // 64
    float* red  = rmax + 64;             // 256
    float* gts  = red  + 256;            // 192
    float* Cs   = gts  + 192;            // 64
    float* Gb   = Cs   + 64;             // 64
    float* wgs  = Gb   + 64;             // 384
    int*   topi = (int*)(wgs + 384);     // 2

    const int tid = threadIdx.x;
    const int bhq = blockIdx.x;
    const int qb  = bhq & (NQB - 1);
    const int bh  = bhq >> 4;
    const int h   = bh & (Hn - 1);
    const int b   = bh >> 3;
    const int q0  = qb * BQ;
    const int rho = tid >> 4;   // 0..15 row group
    const int gg  = tid & 15;   // 0..15 col group

    // ---- load Q tile + gate weights ----
    {
        const float4* q4 = (const float4*)(q + ((size_t)(b * Sn + q0) * Hn + h) * DIMn);
        for (int idx = tid; idx < 64 * 32; idx += 256) {
            int t = idx >> 5, d4 = idx & 31;
            float4 val = q4[(size_t)t * (Hn * DIMn / 4) + d4];
            float* ds = &Qs[t * QSTR + (d4 << 2)];
            ds[0] = val.x; ds[1] = val.y; ds[2] = val.z; ds[3] = val.w;
        }
        for (int i = tid; i < 3 * DIMn; i += 256) wgs[i] = wgate[i];
    }
    __syncthreads();

    // ---- gates: sigmoid(q . w_gate[c] + b_gate[c]) ----
    if (tid < 192) {
        int r = tid / 3, c = tid - 3 * r;
        float a = bgate[c];
        const float* qr = &Qs[r * QSTR];
        const float* wr = &wgs[c * DIMn];
#pragma unroll 8
        for (int d = 0; d < DIMn; ++d) a += qr[d] * wr[d];
        gts[r * 3 + c] = 1.0f / (1.0f + __expf(-a));
    }
    __syncthreads();

    u64 acc2[4][4];
#pragma unroll
    for (int i = 0; i < 4; ++i)
#pragma unroll
        for (int m = 0; m < 4; ++m) acc2[i][m] = 0ULL;

    // ================= WINDOW branch (flash-style online softmax) =================
    {
        const int wbase = q0 - WINR;
        float m_[4], l_[4];
#pragma unroll
        for (int i = 0; i < 4; ++i) { m_[i] = NEG_INF; l_[i] = 0.f; }

#pragma unroll 1
        for (int kt = 0; kt < 5; ++kt) {
            load_tile_kv(KV, k, b, h, wbase + kt * 64, tid, true);
            __syncthreads();

            float s[4][4];
            qk_core(Qs, KV, s, rho, gg);

            // scale + band/range mask
#pragma unroll
            for (int i = 0; i < 4; ++i) {
                int r = rho + 16 * i;
#pragma unroll
                for (int j = 0; j < 4; ++j) {
                    int cgl = kt * 64 + gg + 16 * j;
                    int key = wbase + cgl;
                    bool ok = (key >= 0) && (key < Sn) && (cgl >= r) && (cgl <= r + 2 * WINR);
                    s[i][j] = ok ? s[i][j] * SCALE_MUL : NEG_INF;
                }
            }

            // online softmax update; stats replicated over the 16-lane column group
#pragma unroll
            for (int i = 0; i < 4; ++i) {
                float tm = fmaxf(fmaxf(s[i][0], s[i][1]), fmaxf(s[i][2], s[i][3]));
                tm = fmaxf(tm, __shfl_xor_sync(0xffffffffu, tm, 1));
                tm = fmaxf(tm, __shfl_xor_sync(0xffffffffu, tm, 2));
                tm = fmaxf(tm, __shfl_xor_sync(0xffffffffu, tm, 4));
                tm = fmaxf(tm, __shfl_xor_sync(0xffffffffu, tm, 8));
                float nm = fmaxf(m_[i], tm);
                float sc = __expf(m_[i] - nm);   // ==1 when both -inf (acc is 0 there)
                m_[i] = nm;
                float rs = 0.f;
#pragma unroll
                for (int j = 0; j < 4; ++j) {
                    float e = (s[i][j] > -1e29f) ? __expf(s[i][j] - nm) : 0.f;
                    s[i][j] = e;
                    rs += e;
                }
                rs += __shfl_xor_sync(0xffffffffu, rs, 1);
                rs += __shfl_xor_sync(0xffffffffu, rs, 2);
                rs += __shfl_xor_sync(0xffffffffu, rs, 4);
                rs += __shfl_xor_sync(0xffffffffu, rs, 8);
                l_[i] = l_[i] * sc + rs;
                u64 sc2 = DUP2(sc);
#pragma unroll
                for (int m = 0; m < 4; ++m) acc2[i][m] = MUL2(acc2[i][m], sc2);
                int r = rho + 16 * i;
#pragma unroll
                for (int j = 0; j < 4; ++j) Pb[r * PSTR + gg + 16 * j] = s[i][j];
            }
            __syncthreads();  // Pb written, K reads done

            load_tile_kv(KV, v, b, h, wbase + kt * 64, tid, true);
            __syncthreads();
            gemm_pv(Pb, KV, acc2, rho, gg, 0);
            __syncthreads();
        }
        // finalize window: acc *= gate2 / rowsum
#pragma unroll
        for (int i = 0; i < 4; ++i) {
            int r = rho + 16 * i;
            u64 f2 = DUP2(gts[r * 3 + 2] / l_[i]);
#pragma unroll
            for (int m = 0; m < 4; ++m) acc2[i][m] = MUL2(acc2[i][m], f2);
        }
    }

    // ================= CMP branch =================
    load_tile_cmp(KV, g_cmpK, bh, tid);
    __syncthreads();
    gemm_qk<0>(Qs, KV, Pb, rho, gg, 0, SQRT_D);
    __syncthreads();
    softmax_rows(Pb, rmax, rinv, red, 64, tid);

    // column sums of normalized P_cmp
    if (tid < NCMP) {
        float s = 0.f;
#pragma unroll 4
        for (int r = 0; r < 64; ++r) s += Pb[r * PSTR + tid] * rinv[r];
        Cs[tid] = s;
    }
    __syncthreads();
    // slc-map convolution: weights 1,2,2,2,1 at i = 4j, 4j-1, 4j-2, 4j-3, 4j-4
    if (tid < NSLC) {
        int j4 = 4 * tid;
        float g = 0.f;
        if (j4 < NCMP)                       g += Cs[j4];
        if (j4 - 1 >= 0 && j4 - 1 < NCMP)    g += 2.f * Cs[j4 - 1];
        if (j4 - 2 >= 0 && j4 - 2 < NCMP)    g += 2.f * Cs[j4 - 2];
        if (j4 - 3 >= 0 && j4 - 3 < NCMP)    g += 2.f * Cs[j4 - 3];
        if (j4 - 4 >= 0 && j4 - 4 < NCMP)    g += Cs[j4 - 4];
        Gb[tid] = g;
    }
    __syncthreads();
    // deterministic top-2 (jax tie rule: lower index first)
    if (tid == 0) {
        int i0 = 0; float v0 = Gb[0];
        for (int j = 1; j < NSLC; ++j) if (Gb[j] > v0) { v0 = Gb[j]; i0 = j; }
        int i1 = 0; float v1 = NEG_INF;
        for (int j = 0; j < NSLC; ++j) if (j != i0 && Gb[j] > v1) { v1 = Gb[j]; i1 = j; }
        topi[0] = i0; topi[1] = i1;
    }
    scale_rows(Pb, rinv, gts, 0, 64, tid);   // fold in gate0 (ends with sync -> topi visible)
    load_tile_cmp(KV, g_cmpV, bh, tid);
    __syncthreads();
    gemm_pv(Pb, KV, acc2, rho, gg, 0);
    __syncthreads();

    // ================= SLC branch =================
    {
        int j0 = topi[0], j1 = topi[1];
        load_tile_kv(KV, k, b, h, j0 * 16, tid, false);
        __syncthreads();
        gemm_qk<1>(Qs, KV, Pb, rho, gg, 0, SCALE_MUL);
        __syncthreads();
        load_tile_kv(KV, k, b, h, j1 * 16, tid, false);
        __syncthreads();
        gemm_qk<1>(Qs, KV, Pb, rho, gg, 64, SCALE_MUL);
        __syncthreads();

        softmax_rows(Pb, rmax, rinv, red, 128, tid);
        scale_rows(Pb, rinv, gts, 1, 128, tid);

        load_tile_kv(KV, v, b, h, j0 * 16, tid, false);
        __syncthreads();
        gemm_pv(Pb, KV, acc2, rho, gg, 0);
        __syncthreads();
        load_tile_kv(KV, v, b, h, j1 * 16, tid, false);
        __syncthreads();
        gemm_pv(Pb, KV, acc2, rho, gg, 64);
    }

    // ---- write output (column pairs 2gg+32m) ----
#pragma unroll
    for (int i = 0; i < 4; ++i) {
        int r = rho + 16 * i;
        float* op = out + ((size_t)(b * Sn + q0 + r) * Hn + h) * DIMn + 2 * gg;
#pragma unroll
        for (int m = 0; m < 4; ++m) {
            float x, y; UNPK(acc2[i][m], x, y);
            *(float2*)(op + 32 * m) = make_float2(x, y);
        }
    }
}

// ---------------- launch ----------------
extern "C" void kernel_launch(void* const* d_in, const int* in_sizes, int n_in,
                              void* d_out, int out_size)
{
    (void)in_sizes; (void)n_in; (void)out_size;
    const float* q   = (const float*)d_in[0];
    const float* k   = (const float*)d_in[1];
    const float* v   = (const float*)d_in[2];
    const float* wck = (const float*)d_in[3];
    const float* bck = (const float*)d_in[4];
    const float* wcv = (const float*)d_in[5];
    const float* bcv = (const float*)d_in[6];
    const float* wg  = (const float*)d_in[7];
    const float* bg  = (const float*)d_in[8];
    float* out = (float*)d_out;

    // kernel A: compressed K/V
    int totalA = Bn * Hn * NCMP * DIMn;
    cmp_kv_kernel<<<(totalA + 255) / 256, 256>>>(k, v, wck, bck, wcv, bcv);

    // fused NSA kernel
    size_t smem_floats = (size_t)2 * 64 * QSTR + (size_t)64 * PSTR
                       + 64 + 64 + 256 + 192 + 64 + 64 + 384 + 4;
    size_t smem_bytes = smem_floats * sizeof(float);
    cudaFuncSetAttribute(nsa_main, cudaFuncAttributeMaxDynamicSharedMemorySize,
                         (int)smem_bytes);
    nsa_main<<<Bn * Hn * NQB, 256, smem_bytes>>>(q, k, v, wg, bg, out);
}

// round 12
// speedup vs baseline: 1.2398x; 1.0004x over previous
#include <cuda_runtime.h>

// ---------------- problem constants ----------------
#define Bn    2
#define Sn    1024
#define Hn    8
#define DIMn  128
#define LCMP  32
#define NCMP  63          // (1024-32)/16+1
#define NSLC  61          // (1024-64)/16+1
#define BQ    64
#define NQB   (Sn / BQ)   // 16
#define NITEMS (Bn * Hn * NQB)  // 256
#define WINR  128
#define QSTR  130         // even (8B-aligned rows), ==2 mod 4 (conflict-free LDS.64)
#define PSTR  130
#define NEG_INF (-1e30f)

#define SCALE_MUL 0.08838834764831845f   // 1/sqrt(128): slc & window
#define SQRT_D    11.313708498984761f    // sqrt(128): cmp branch (reference divides by scale)

typedef unsigned long long u64;

// ---------------- f32x2 packed helpers ----------------
__device__ __forceinline__ u64 FMA2(u64 a, u64 b, u64 c) {
    u64 d;
    asm("fma.rn.f32x2 %0, %1, %2, %3;" : "=l"(d) : "l"(a), "l"(b), "l"(c));
    return d;
}
__device__ __forceinline__ u64 MUL2(u64 a, u64 b) {
    u64 d;
    asm("mul.rn.f32x2 %0, %1, %2;" : "=l"(d) : "l"(a), "l"(b));
    return d;
}
__device__ __forceinline__ u64 DUP2(float p) {
    u64 d;
    asm("mov.b64 %0, {%1, %1};" : "=l"(d) : "f"(p));
    return d;
}
__device__ __forceinline__ void UNPK(u64 a, float& x, float& y) {
    asm("mov.b64 {%0, %1}, %2;" : "=f"(x), "=f"(y) : "l"(a));
}

// scratch for compressed K/V: [b][h][n][d]
__device__ float g_cmpK[Bn * Hn * NCMP * DIMn];
__device__ float g_cmpV[Bn * Hn * NCMP * DIMn];
__device__ unsigned int g_ticket;

// ---------------- ticket reset (runs each graph replay) ----------------
__global__ void reset_ticket_kernel() { g_ticket = 0u; }

// ---------------- kernel A: compressed K/V ----------------
__global__ void __launch_bounds__(256) cmp_kv_kernel(
    const float* __restrict__ k, const float* __restrict__ v,
    const float* __restrict__ wck, const float* __restrict__ bck,
    const float* __restrict__ wcv, const float* __restrict__ bcv)
{
    __shared__ float swk[LCMP], swv[LCMP], sb[2];
    int tid = threadIdx.x;
    if (tid < LCMP) { swk[tid] = wck[tid]; swv[tid] = wcv[tid]; }
    if (tid == 0)   { sb[0] = bck[0]; sb[1] = bcv[0]; }
    __syncthreads();

    int idx = blockIdx.x * 256 + tid;
    if (idx >= Bn * Hn * NCMP * DIMn) return;
    int d  = idx & (DIMn - 1);
    int n  = (idx >> 7) % NCMP;
    int bh = idx / (NCMP * DIMn);
    int h  = bh & (Hn - 1);
    int b  = bh >> 3;

    const float* kb = k + ((size_t)(b * Sn + n * 16) * Hn + h) * DIMn + d;
    const float* vb = v + ((size_t)(b * Sn + n * 16) * Hn + h) * DIMn + d;
    float ak = 0.f, av = 0.f;
#pragma unroll
    for (int l = 0; l < LCMP; ++l) {
        ak += kb[(size_t)l * Hn * DIMn] * swk[l];
        av += vb[(size_t)l * Hn * DIMn] * swv[l];
    }
    g_cmpK[idx] = ak + sb[0];
    g_cmpV[idx] = av + sb[1];
}

// ---------------- helpers for the fused kernel ----------------

// QK core (f32x2 along kd): s[4][4] = Qs(64x128) * Ks(64x128)^T
__device__ __forceinline__ void qk_core(const float* __restrict__ Qs,
                                        const float* __restrict__ Ks,
                                        float s[4][4], int rho, int gg)
{
    u64 s2[4][4];
#pragma unroll
    for (int i = 0; i < 4; ++i)
#pragma unroll
        for (int j = 0; j < 4; ++j) s2[i][j] = 0ULL;

    const u64* qp = (const u64*)(Qs + rho * QSTR);
    const u64* kp = (const u64*)(Ks + gg  * QSTR);
    const int RS = 8 * QSTR;   // 16 rows in u64 units
#pragma unroll 4
    for (int kd = 0; kd < DIMn / 2; ++kd) {
        u64 a0 = qp[kd];
        u64 a1 = qp[RS + kd];
        u64 a2 = qp[2 * RS + kd];
        u64 a3 = qp[3 * RS + kd];
        u64 b0 = kp[kd];
        u64 b1 = kp[RS + kd];
        u64 b2 = kp[2 * RS + kd];
        u64 b3 = kp[3 * RS + kd];
        s2[0][0] = FMA2(a0, b0, s2[0][0]); s2[0][1] = FMA2(a0, b1, s2[0][1]);
        s2[0][2] = FMA2(a0, b2, s2[0][2]); s2[0][3] = FMA2(a0, b3, s2[0][3]);
        s2[1][0] = FMA2(a1, b0, s2[1][0]); s2[1][1] = FMA2(a1, b1, s2[1][1]);
        s2[1][2] = FMA2(a1, b2, s2[1][2]); s2[1][3] = FMA2(a1, b3, s2[1][3]);
        s2[2][0] = FMA2(a2, b0, s2[2][0]); s2[2][1] = FMA2(a2, b1, s2[2][1]);
        s2[2][2] = FMA2(a2, b2, s2[2][2]); s2[2][3] = FMA2(a2, b3, s2[2][3]);
        s2[3][0] = FMA2(a3, b0, s2[3][0]); s2[3][1] = FMA2(a3, b1, s2[3][1]);
        s2[3][2] = FMA2(a3, b2, s2[3][2]); s2[3][3] = FMA2(a3, b3, s2[3][3]);
    }
#pragma unroll
    for (int i = 0; i < 4; ++i)
#pragma unroll
        for (int j = 0; j < 4; ++j) {
            float x, y; UNPK(s2[i][j], x, y);
            s[i][j] = x + y;
        }
}

// QK GEMM -> Pb.  MODE 0 = cmp (mask c>=NCMP), 1 = slc (no mask)
template <int MODE>
__device__ __forceinline__ void gemm_qk(const float* __restrict__ Qs,
                                        const float* __restrict__ Ks,
                                        float* __restrict__ Pb,
                                        int rho, int gg, int cb, float scl)
{
    float s[4][4];
    qk_core(Qs, Ks, s, rho, gg);
#pragma unroll
    for (int i = 0; i < 4; ++i) {
        int r = rho + 16 * i;
#pragma unroll
        for (int j = 0; j < 4; ++j) {
            int c = gg + 16 * j;
            float val = s[i][j] * scl;
            if (MODE == 0) {
                if (c >= NCMP) val = NEG_INF;
            }
            Pb[r * PSTR + cb + c] = val;
        }
    }
}

// PV GEMM (f32x2 along output cols): acc2[4][4] += P(64 x 64-tile) * Vs(64x128)
// thread owns column pairs {2gg+32m, 2gg+32m+1}, m=0..3
__device__ __forceinline__ void gemm_pv(const float* __restrict__ Pb,
                                        const float* __restrict__ Vs,
                                        u64 acc2[4][4], int rho, int gg, int cb)
{
    const float* pp = Pb + rho * PSTR + cb;
    const float* vb = Vs + 2 * gg;
#pragma unroll 2
    for (int cl = 0; cl < 64; cl += 2) {
        const u64* vr0 = (const u64*)(vb + cl * QSTR);
        const u64* vr1 = (const u64*)(vb + (cl + 1) * QSTR);
        u64 v0[4], v1[4];
#pragma unroll
        for (int m = 0; m < 4; ++m) { v0[m] = vr0[16 * m]; v1[m] = vr1[16 * m]; }
#pragma unroll
        for (int i = 0; i < 4; ++i) {
            u64 p2 = *(const u64*)(pp + 16 * i * PSTR + cl);
            float pa, pbv; UNPK(p2, pa, pbv);
            u64 da = DUP2(pa), db = DUP2(pbv);
#pragma unroll
            for (int m = 0; m < 4; ++m) {
                acc2[i][m] = FMA2(da, v0[m], acc2[i][m]);
                acc2[i][m] = FMA2(db, v1[m], acc2[i][m]);
            }
        }
    }
}

// two-pass row softmax over Pb[:, 0:NK]; leaves exp() in Pb, 1/rowsum in rinv
__device__ __forceinline__ void softmax_rows(float* __restrict__ Pb,
                                             float* __restrict__ rmax,
                                             float* __restrict__ rinv,
                                             float* __restrict__ red,
                                             int NK, int tid)
{
    int r = tid & 63, part = tid >> 6;
    float m = NEG_INF;
    for (int c = part; c < NK; c += 4) m = fmaxf(m, Pb[r * PSTR + c]);
    red[part * 64 + r] = m;
    __syncthreads();
    if (tid < 64)
        rmax[tid] = fmaxf(fmaxf(red[tid], red[64 + tid]),
                          fmaxf(red[128 + tid], red[192 + tid]));
    __syncthreads();
    float mr = rmax[r];
    float sum = 0.f;
    for (int c = part; c < NK; c += 4) {
        float e = __expf(Pb[r * PSTR + c] - mr);
        Pb[r * PSTR + c] = e;
        sum += e;
    }
    red[part * 64 + r] = sum;
    __syncthreads();
    if (tid < 64)
        rinv[tid] = 1.0f / (red[tid] + red[64 + tid] + red[128 + tid] + red[192 + tid]);
    __syncthreads();
}

// P[r][c] *= gate[r][gi] / rowsum[r]
__device__ __forceinline__ void scale_rows(float* __restrict__ Pb,
                                           const float* __restrict__ rinv,
                                           const float* __restrict__ gts,
                                           int gi, int NK, int tid)
{
    int r = tid & 63, part = tid >> 6;
    float f = gts[r * 3 + gi] * rinv[r];
    for (int c = part; c < NK; c += 4) Pb[r * PSTR + c] *= f;
    __syncthreads();
}

// load a 64x128 tile from q/k/v-layout global memory into padded smem, zero-fill invalid
__device__ __forceinline__ void load_tile_kv(float* __restrict__ dst,
                                             const float* __restrict__ src,
                                             int b, int h, int s_base, int tid, bool check)
{
    for (int idx = tid; idx < 64 * 32; idx += 256) {
        int t = idx >> 5, d4 = idx & 31;
        int srow = s_base + t;
        float4 val = make_float4(0.f, 0.f, 0.f, 0.f);
        if (!check || ((unsigned)srow < (unsigned)Sn))
            val = ((const float4*)(src + ((size_t)(b * Sn + srow) * Hn + h) * DIMn))[d4];
        float* ds = &dst[t * QSTR + (d4 << 2)];
        ds[0] = val.x; ds[1] = val.y; ds[2] = val.z; ds[3] = val.w;
    }
}

// load compressed K/V tile (63 rows), zero row 63
__device__ __forceinline__ void load_tile_cmp(float* __restrict__ dst,
                                              const float* __restrict__ src,
                                              int bh, int tid)
{
    for (int idx = tid; idx < 64 * 32; idx += 256) {
        int t = idx >> 5, d4 = idx & 31;
        float4 val = make_float4(0.f, 0.f, 0.f, 0.f);
        if (t < NCMP)
            val = ((const float4*)(src + ((size_t)bh * NCMP + t) * DIMn))[d4];
        float* ds = &dst[t * QSTR + (d4 << 2)];
        ds[0] = val.x; ds[1] = val.y; ds[2] = val.z; ds[3] = val.w;
    }
}

// ---------------- fused main kernel (persistent, work-stealing) ----------------
__global__ void __launch_bounds__(256, 2) nsa_main(
    const float* __restrict__ q, const float* __restrict__ k, const float* __restrict__ v,
    const float* __restrict__ wgate, const float* __restrict__ bgate,
    float* __restrict__ out)
{
    extern __shared__ float sm[];
    float* Qs   = sm;                    // 64*130
    float* KV   = Qs  + 64 * QSTR;       // 64*130 (shared K/V tile)
    float* Pb   = KV  + 64 * QSTR;       // 64*130
    float* rinv = Pb  + 64 * PSTR;       // 64
    float* rmax = rinv + 64;             // 64
    float* red  = rmax + 64;             // 256
    float* gts  = red  + 256;            // 192
    float* Cs   = gts  + 192;            // 64
    float* Gb   = Cs   + 64;             // 64
    float* wgs  = Gb   + 64;             // 384
    int*   topi = (int*)(wgs + 384);     // 2
    unsigned int* s_item = (unsigned int*)(topi + 2);

    const int tid = threadIdx.x;
    const int rho = tid >> 4;   // 0..15 row group
    const int gg  = tid & 15;   // 0..15 col group

    // gate weights loaded once per persistent CTA
    for (int i = tid; i < 3 * DIMn; i += 256) wgs[i] = wgate[i];

    for (;;) {
        __syncthreads();   // smem safe to reuse; also orders s_item
        if (tid == 0) *s_item = atomicAdd(&g_ticket, 1u);
        __syncthreads();
        unsigned int bhq = *s_item;
        if (bhq >= NITEMS) break;

        const int qb  = bhq & (NQB - 1);
        const int bh  = bhq >> 4;
        const int h   = bh & (Hn - 1);
        const int b   = bh >> 3;
        const int q0  = qb * BQ;

        // ---- load Q tile ----
        {
            const float4* q4 = (const float4*)(q + ((size_t)(b * Sn + q0) * Hn + h) * DIMn);
            for (int idx = tid; idx < 64 * 32; idx += 256) {
                int t = idx >> 5, d4 = idx & 31;
                float4 val = q4[(size_t)t * (Hn * DIMn / 4) + d4];
                float* ds = &Qs[t * QSTR + (d4 << 2)];
                ds[0] = val.x; ds[1] = val.y; ds[2] = val.z; ds[3] = val.w;
            }
        }
        __syncthreads();

        // ---- gates: sigmoid(q . w_gate[c] + b_gate[c]) ----
        if (tid < 192) {
            int r = tid / 3, c = tid - 3 * r;
            float a = bgate[c];
            const float* qr = &Qs[r * QSTR];
            const float* wr = &wgs[c * DIMn];
#pragma unroll 8
            for (int d = 0; d < DIMn; ++d) a += qr[d] * wr[d];
            gts[r * 3 + c] = 1.0f / (1.0f + __expf(-a));
        }
        __syncthreads();

        u64 acc2[4][4];
#pragma unroll
        for (int i = 0; i < 4; ++i)
#pragma unroll
            for (int m = 0; m < 4; ++m) acc2[i][m] = 0ULL;

        // ================= WINDOW branch (flash-style online softmax) =================
        {
            const int wbase = q0 - WINR;
            // per-thread valid column range, per row group i:
            //   ok(cgl) = cgl >= clo[i] && cgl <= chi[i]
            int clo[4], chi[4];
#pragma unroll
            for (int i = 0; i < 4; ++i) {
                int r = rho + 16 * i;
                int lo = 128 - q0;  if (lo < r) lo = r;
                int hi = 1151 - q0; if (hi > r + 256) hi = r + 256;
                clo[i] = lo; chi[i] = hi;
            }
            const int clo_min = (128 - q0 > 0) ? (128 - q0) : 0;
            const int chi_max = (1151 - q0 < 319) ? (1151 - q0) : 319;

            float m_[4], l_[4];
#pragma unroll
            for (int i = 0; i < 4; ++i) { m_[i] = NEG_INF; l_[i] = 0.f; }

#pragma unroll 1
            for (int kt = 0; kt < 5; ++kt) {
                // uniform skip of fully-masked tiles
                if (64 * kt + 63 < clo_min || 64 * kt > chi_max) continue;

                load_tile_kv(KV, k, b, h, wbase + kt * 64, tid, true);
                __syncthreads();

                float s[4][4];
                qk_core(Qs, KV, s, rho, gg);

                // scale + hoisted range mask
#pragma unroll
                for (int i = 0; i < 4; ++i) {
#pragma unroll
                    for (int j = 0; j < 4; ++j) {
                        int cgl = kt * 64 + gg + 16 * j;
                        bool ok = (cgl >= clo[i]) && (cgl <= chi[i]);
                        s[i][j] = ok ? s[i][j] * SCALE_MUL : NEG_INF;
                    }
                }

                // online softmax update; stats replicated over the 16-lane column group
#pragma unroll
                for (int i = 0; i < 4; ++i) {
                    float tm = fmaxf(fmaxf(s[i][0], s[i][1]), fmaxf(s[i][2], s[i][3]));
                    tm = fmaxf(tm, __shfl_xor_sync(0xffffffffu, tm, 1));
                    tm = fmaxf(tm, __shfl_xor_sync(0xffffffffu, tm, 2));
                    tm = fmaxf(tm, __shfl_xor_sync(0xffffffffu, tm, 4));
                    tm = fmaxf(tm, __shfl_xor_sync(0xffffffffu, tm, 8));
                    float nm = fmaxf(m_[i], tm);
                    float sc = __expf(m_[i] - nm);   // ==1 when both sentinel (acc is 0 there)
                    m_[i] = nm;
                    float rs = 0.f;
#pragma unroll
                    for (int j = 0; j < 4; ++j) {
                        float e = (s[i][j] > -1e29f) ? __expf(s[i][j] - nm) : 0.f;
                        s[i][j] = e;
                        rs += e;
                    }
                    rs += __shfl_xor_sync(0xffffffffu, rs, 1);
                    rs += __shfl_xor_sync(0xffffffffu, rs, 2);
                    rs += __shfl_xor_sync(0xffffffffu, rs, 4);
                    rs += __shfl_xor_sync(0xffffffffu, rs, 8);
                    l_[i] = l_[i] * sc + rs;
                    u64 sc2 = DUP2(sc);
#pragma unroll
                    for (int m = 0; m < 4; ++m) acc2[i][m] = MUL2(acc2[i][m], sc2);
                    int r = rho + 16 * i;
#pragma unroll
                    for (int j = 0; j < 4; ++j) Pb[r * PSTR + gg + 16 * j] = s[i][j];
                }
                __syncthreads();  // Pb written, K reads done

                load_tile_kv(KV, v, b, h, wbase + kt * 64, tid, true);
                __syncthreads();
                gemm_pv(Pb, KV, acc2, rho, gg, 0);
                __syncthreads();
            }
            // finalize window: acc *= gate2 / rowsum
#pragma unroll
            for (int i = 0; i < 4; ++i) {
                int r = rho + 16 * i;
                u64 f2 = DUP2(gts[r * 3 + 2] / l_[i]);
#pragma unroll
                for (int m = 0; m < 4; ++m) acc2[i][m] = MUL2(acc2[i][m], f2);
            }
        }

        // ================= CMP branch =================
        load_tile_cmp(KV, g_cmpK, bh, tid);
        __syncthreads();
        gemm_qk<0>(Qs, KV, Pb, rho, gg, 0, SQRT_D);
        __syncthreads();
        softmax_rows(Pb, rmax, rinv, red, 64, tid);

        // column sums of normalized P_cmp (256 threads: 64 cols x 4 row-parts)
        {
            int col = tid & 63, part = tid >> 6;
            float s = 0.f;
            int r0 = part * 16;
#pragma unroll 4
            for (int r = r0; r < r0 + 16; ++r) s += Pb[r * PSTR + col] * rinv[r];
            red[part * 64 + col] = s;
        }
        __syncthreads();
        if (tid < 64)
            Cs[tid] = red[tid] + red[64 + tid] + red[128 + tid] + red[192 + tid];
        __syncthreads();
        // slc-map convolution: weights 1,2,2,2,1 at i = 4j, 4j-1, 4j-2, 4j-3, 4j-4
        if (tid < NSLC) {
            int j4 = 4 * tid;
            float g = 0.f;
            if (j4 < NCMP)                       g += Cs[j4];
            if (j4 - 1 >= 0 && j4 - 1 < NCMP)    g += 2.f * Cs[j4 - 1];
            if (j4 - 2 >= 0 && j4 - 2 < NCMP)    g += 2.f * Cs[j4 - 2];
            if (j4 - 3 >= 0 && j4 - 3 < NCMP)    g += 2.f * Cs[j4 - 3];
            if (j4 - 4 >= 0 && j4 - 4 < NCMP)    g += Cs[j4 - 4];
            Gb[tid] = g;
        }
        __syncthreads();
        // deterministic top-2 (jax tie rule: lower index first) — warp 0 reduction
        if (tid < 32) {
            float a  = (tid < NSLC)      ? Gb[tid]      : NEG_INF;
            float bb = (tid + 32 < NSLC) ? Gb[tid + 32] : NEG_INF;
            // pass 1: global max (ties -> lower index)
            float m1 = a; int i1 = tid;
            if (bb > m1) { m1 = bb; i1 = tid + 32; }
#pragma unroll
            for (int off = 16; off > 0; off >>= 1) {
                float om = __shfl_down_sync(0xffffffffu, m1, off);
                int   oi = __shfl_down_sync(0xffffffffu, i1, off);
                if (om > m1 || (om == m1 && oi < i1)) { m1 = om; i1 = oi; }
            }
            int i0 = __shfl_sync(0xffffffffu, i1, 0);
            // pass 2: max excluding i0
            float a2  = (tid == i0)      ? NEG_INF : a;
            float b2  = (tid + 32 == i0) ? NEG_INF : bb;
            float m2 = a2; int i2 = tid;
            if (b2 > m2) { m2 = b2; i2 = tid + 32; }
#pragma unroll
            for (int off = 16; off > 0; off >>= 1) {
                float om = __shfl_down_sync(0xffffffffu, m2, off);
                int   oi = __shfl_down_sync(0xffffffffu, i2, off);
                if (om > m2 || (om == m2 && oi < i2)) { m2 = om; i2 = oi; }
            }
            if (tid == 0) { topi[0] = i0; topi[1] = i2; }
        }
        scale_rows(Pb, rinv, gts, 0, 64, tid);   // fold in gate0 (ends with sync -> topi visible)
        load_tile_cmp(KV, g_cmpV, bh, tid);
        __syncthreads();
        gemm_pv(Pb, KV, acc2, rho, gg, 0);
        __syncthreads();

        // ================= SLC branch =================
        {
            int j0 = topi[0], j1 = topi[1];
            load_tile_kv(KV, k, b, h, j0 * 16, tid, false);
            __syncthreads();
            gemm_qk<1>(Qs, KV, Pb, rho, gg, 0, SCALE_MUL);
            __syncthreads();
            load_tile_kv(KV, k, b, h, j1 * 16, tid, false);
            __syncthreads();
            gemm_qk<1>(Qs, KV, Pb, rho, gg, 64, SCALE_MUL);
            __syncthreads();

            softmax_rows(Pb, rmax, rinv, red, 128, tid);
            scale_rows(Pb, rinv, gts, 1, 128, tid);

            load_tile_kv(KV, v, b, h, j0 * 16, tid, false);
            __syncthreads();
            gemm_pv(Pb, KV, acc2, rho, gg, 0);
            __syncthreads();
            load_tile_kv(KV, v, b, h, j1 * 16, tid, false);
            __syncthreads();
            gemm_pv(Pb, KV, acc2, rho, gg, 64);
        }

        // ---- write output (column pairs 2gg+32m) ----
#pragma unroll
        for (int i = 0; i < 4; ++i) {
            int r = rho + 16 * i;
            float* op = out + ((size_t)(b * Sn + q0 + r) * Hn + h) * DIMn + 2 * gg;
#pragma unroll
            for (int m = 0; m < 4; ++m) {
                float x, y; UNPK(acc2[i][m], x, y);
                *(float2*)(op + 32 * m) = make_float2(x, y);
            }
        }
    }
}

// ---------------- launch ----------------
extern "C" void kernel_launch(void* const* d_in, const int* in_sizes, int n_in,
                              void* d_out, int out_size)
{
    (void)in_sizes; (void)n_in; (void)out_size;
    const float* q   = (const float*)d_in[0];
    const float* k   = (const float*)d_in[1];
    const float* v   = (const float*)d_in[2];
    const float* wck = (const float*)d_in[3];
    const float* bck = (const float*)d_in[4];
    const float* wcv = (const float*)d_in[5];
    const float* bcv = (const float*)d_in[6];
    const float* wg  = (const float*)d_in[7];
    const float* bg  = (const float*)d_in[8];
    float* out = (float*)d_out;

    // reset work-stealing ticket (each graph replay)
    reset_ticket_kernel<<<1, 1>>>();

    // kernel A: compressed K/V
    int totalA = Bn * Hn * NCMP * DIMn;
    cmp_kv_kernel<<<(totalA + 255) / 256, 256>>>(k, v, wck, bck, wcv, bcv);

    // fused NSA kernel: persistent grid, 2 CTAs per SM (152 SMs on GB300)
    size_t smem_floats = (size_t)2 * 64 * QSTR + (size_t)64 * PSTR
                       + 64 + 64 + 256 + 192 + 64 + 64 + 384 + 8;
    size_t smem_bytes = smem_floats * sizeof(float);
    cudaFuncSetAttribute(nsa_main, cudaFuncAttributeMaxDynamicSharedMemorySize,
                         (int)smem_bytes);
    nsa_main<<<304, 256, smem_bytes>>>(q, k, v, wg, bg, out);
}

// round 13
// speedup vs baseline: 1.2503x; 1.0085x over previous
#include <cuda_runtime.h>

// ---------------- problem constants ----------------
#define Bn    2
#define Sn    1024
#define Hn    8
#define DIMn  128
#define LCMP  32
#define NCMP  63          // (1024-32)/16+1
#define NSLC  61          // (1024-64)/16+1
#define BQ    64
#define NQB   (Sn / BQ)   // 16
#define NITEMS (Bn * Hn * NQB)  // 256
#define WINR  128
#define QSTR  130         // even (8B-aligned rows), ==2 mod 4 (conflict-free LDS.64)
#define PSTR  130
#define NEG_INF (-1e30f)

#define SCALE_MUL 0.08838834764831845f   // 1/sqrt(128): slc & window
#define SQRT_D    11.313708498984761f    // sqrt(128): cmp branch (reference divides by scale)

typedef unsigned long long u64;

// ---------------- f32x2 packed helpers ----------------
__device__ __forceinline__ u64 FMA2(u64 a, u64 b, u64 c) {
    u64 d;
    asm("fma.rn.f32x2 %0, %1, %2, %3;" : "=l"(d) : "l"(a), "l"(b), "l"(c));
    return d;
}
__device__ __forceinline__ u64 MUL2(u64 a, u64 b) {
    u64 d;
    asm("mul.rn.f32x2 %0, %1, %2;" : "=l"(d) : "l"(a), "l"(b));
    return d;
}
__device__ __forceinline__ u64 DUP2(float p) {
    u64 d;
    asm("mov.b64 %0, {%1, %1};" : "=l"(d) : "f"(p));
    return d;
}
__device__ __forceinline__ void UNPK(u64 a, float& x, float& y) {
    asm("mov.b64 {%0, %1}, %2;" : "=f"(x), "=f"(y) : "l"(a));
}

// scratch for compressed K/V: [b][h][n][d]
__device__ float g_cmpK[Bn * Hn * NCMP * DIMn];
__device__ float g_cmpV[Bn * Hn * NCMP * DIMn];
__device__ unsigned int g_ticket;

// ---------------- kernel A: compressed K/V (+ ticket reset) ----------------
__global__ void __launch_bounds__(256) cmp_kv_kernel(
    const float* __restrict__ k, const float* __restrict__ v,
    const float* __restrict__ wck, const float* __restrict__ bck,
    const float* __restrict__ wcv, const float* __restrict__ bcv)
{
    __shared__ float swk[LCMP], swv[LCMP], sb[2];
    int tid = threadIdx.x;
    if (blockIdx.x == 0 && tid == 0) g_ticket = 0u;   // reset work-stealing ticket
    if (tid < LCMP) { swk[tid] = wck[tid]; swv[tid] = wcv[tid]; }
    if (tid == 0)   { sb[0] = bck[0]; sb[1] = bcv[0]; }
    __syncthreads();

    int idx = blockIdx.x * 256 + tid;
    if (idx >= Bn * Hn * NCMP * DIMn) return;
    int d  = idx & (DIMn - 1);
    int n  = (idx >> 7) % NCMP;
    int bh = idx / (NCMP * DIMn);
    int h  = bh & (Hn - 1);
    int b  = bh >> 3;

    const float* kb = k + ((size_t)(b * Sn + n * 16) * Hn + h) * DIMn + d;
    const float* vb = v + ((size_t)(b * Sn + n * 16) * Hn + h) * DIMn + d;
    float ak = 0.f, av = 0.f;
#pragma unroll
    for (int l = 0; l < LCMP; ++l) {
        ak += kb[(size_t)l * Hn * DIMn] * swk[l];
        av += vb[(size_t)l * Hn * DIMn] * swv[l];
    }
    g_cmpK[idx] = ak + sb[0];
    g_cmpV[idx] = av + sb[1];
}

// ---------------- prefetch helpers (global -> regs -> smem) ----------------
__device__ __forceinline__ void pf_ldg_kv(float4 r[8], const float* __restrict__ src,
                                          int b, int h, int s_base, int tid, bool check)
{
    int t0 = tid >> 5, d4 = tid & 31;
#pragma unroll
    for (int i = 0; i < 8; ++i) {
        int srow = s_base + t0 + 8 * i;
        float4 val = make_float4(0.f, 0.f, 0.f, 0.f);
        if (!check || ((unsigned)srow < (unsigned)Sn))
            val = ((const float4*)(src + ((size_t)(b * Sn + srow) * Hn + h) * DIMn))[d4];
        r[i] = val;
    }
}
__device__ __forceinline__ void pf_ldg_cmp(float4 r[8], const float* __restrict__ src,
                                           int bh, int tid)
{
    int t0 = tid >> 5, d4 = tid & 31;
#pragma unroll
    for (int i = 0; i < 8; ++i) {
        int t = t0 + 8 * i;
        float4 val = make_float4(0.f, 0.f, 0.f, 0.f);
        if (t < NCMP)
            val = ((const float4*)(src + ((size_t)bh * NCMP + t) * DIMn))[d4];
        r[i] = val;
    }
}
__device__ __forceinline__ void pf_sts(const float4 r[8], float* __restrict__ dst, int tid)
{
    int t0 = tid >> 5, d4 = tid & 31;
#pragma unroll
    for (int i = 0; i < 8; ++i) {
        float* ds = &dst[(t0 + 8 * i) * QSTR + (d4 << 2)];
        *(float2*)(ds)     = make_float2(r[i].x, r[i].y);
        *(float2*)(ds + 2) = make_float2(r[i].z, r[i].w);
    }
}

// ---------------- GEMM helpers ----------------

// QK core (f32x2 along kd): s[4][4] = Qs(64x128) * Ks(64x128)^T
__device__ __forceinline__ void qk_core(const float* __restrict__ Qs,
                                        const float* __restrict__ Ks,
                                        float s[4][4], int rho, int gg)
{
    u64 s2[4][4];
#pragma unroll
    for (int i = 0; i < 4; ++i)
#pragma unroll
        for (int j = 0; j < 4; ++j) s2[i][j] = 0ULL;

    const u64* qp = (const u64*)(Qs + rho * QSTR);
    const u64* kp = (const u64*)(Ks + gg  * QSTR);
    const int RS = 8 * QSTR;   // 16 rows in u64 units
#pragma unroll 4
    for (int kd = 0; kd < DIMn / 2; ++kd) {
        u64 a0 = qp[kd];
        u64 a1 = qp[RS + kd];
        u64 a2 = qp[2 * RS + kd];
        u64 a3 = qp[3 * RS + kd];
        u64 b0 = kp[kd];
        u64 b1 = kp[RS + kd];
        u64 b2 = kp[2 * RS + kd];
        u64 b3 = kp[3 * RS + kd];
        s2[0][0] = FMA2(a0, b0, s2[0][0]); s2[0][1] = FMA2(a0, b1, s2[0][1]);
        s2[0][2] = FMA2(a0, b2, s2[0][2]); s2[0][3] = FMA2(a0, b3, s2[0][3]);
        s2[1][0] = FMA2(a1, b0, s2[1][0]); s2[1][1] = FMA2(a1, b1, s2[1][1]);
        s2[1][2] = FMA2(a1, b2, s2[1][2]); s2[1][3] = FMA2(a1, b3, s2[1][3]);
        s2[2][0] = FMA2(a2, b0, s2[2][0]); s2[2][1] = FMA2(a2, b1, s2[2][1]);
        s2[2][2] = FMA2(a2, b2, s2[2][2]); s2[2][3] = FMA2(a2, b3, s2[2][3]);
        s2[3][0] = FMA2(a3, b0, s2[3][0]); s2[3][1] = FMA2(a3, b1, s2[3][1]);
        s2[3][2] = FMA2(a3, b2, s2[3][2]); s2[3][3] = FMA2(a3, b3, s2[3][3]);
    }
#pragma unroll
    for (int i = 0; i < 4; ++i)
#pragma unroll
        for (int j = 0; j < 4; ++j) {
            float x, y; UNPK(s2[i][j], x, y);
            s[i][j] = x + y;
        }
}

// QK GEMM -> Pb.  MODE 0 = cmp (mask c>=NCMP), 1 = slc (no mask)
template <int MODE>
__device__ __forceinline__ void gemm_qk(const float* __restrict__ Qs,
                                        const float* __restrict__ Ks,
                                        float* __restrict__ Pb,
                                        int rho, int gg, int cb, float scl)
{
    float s[4][4];
    qk_core(Qs, Ks, s, rho, gg);
#pragma unroll
    for (int i = 0; i < 4; ++i) {
        int r = rho + 16 * i;
#pragma unroll
        for (int j = 0; j < 4; ++j) {
            int c = gg + 16 * j;
            float val = s[i][j] * scl;
            if (MODE == 0) {
                if (c >= NCMP) val = NEG_INF;
            }
            Pb[r * PSTR + cb + c] = val;
        }
    }
}

// PV GEMM (f32x2 along output cols): acc2[4][4] += P(64 x 64-tile) * Vs(64x128)
__device__ __forceinline__ void gemm_pv(const float* __restrict__ Pb,
                                        const float* __restrict__ Vs,
                                        u64 acc2[4][4], int rho, int gg, int cb)
{
    const float* pp = Pb + rho * PSTR + cb;
    const float* vb = Vs + 2 * gg;
#pragma unroll 2
    for (int cl = 0; cl < 64; cl += 2) {
        const u64* vr0 = (const u64*)(vb + cl * QSTR);
        const u64* vr1 = (const u64*)(vb + (cl + 1) * QSTR);
        u64 v0[4], v1[4];
#pragma unroll
        for (int m = 0; m < 4; ++m) { v0[m] = vr0[16 * m]; v1[m] = vr1[16 * m]; }
#pragma unroll
        for (int i = 0; i < 4; ++i) {
            u64 p2 = *(const u64*)(pp + 16 * i * PSTR + cl);
            float pa, pbv; UNPK(p2, pa, pbv);
            u64 da = DUP2(pa), db = DUP2(pbv);
#pragma unroll
            for (int m = 0; m < 4; ++m) {
                acc2[i][m] = FMA2(da, v0[m], acc2[i][m]);
                acc2[i][m] = FMA2(db, v1[m], acc2[i][m]);
            }
        }
    }
}

// two-pass row softmax over Pb[:, 0:NK]; leaves exp() in Pb, 1/rowsum in rinv
__device__ __forceinline__ void softmax_rows(float* __restrict__ Pb,
                                             float* __restrict__ rmax,
                                             float* __restrict__ rinv,
                                             float* __restrict__ red,
                                             int NK, int tid)
{
    int r = tid & 63, part = tid >> 6;
    float m = NEG_INF;
    for (int c = part; c < NK; c += 4) m = fmaxf(m, Pb[r * PSTR + c]);
    red[part * 64 + r] = m;
    __syncthreads();
    if (tid < 64)
        rmax[tid] = fmaxf(fmaxf(red[tid], red[64 + tid]),
                          fmaxf(red[128 + tid], red[192 + tid]));
    __syncthreads();
    float mr = rmax[r];
    float sum = 0.f;
    for (int c = part; c < NK; c += 4) {
        float e = __expf(Pb[r * PSTR + c] - mr);
        Pb[r * PSTR + c] = e;
        sum += e;
    }
    red[part * 64 + r] = sum;
    __syncthreads();
    if (tid < 64)
        rinv[tid] = 1.0f / (red[tid] + red[64 + tid] + red[128 + tid] + red[192 + tid]);
    __syncthreads();
}

// P[r][c] *= gate[r][gi] / rowsum[r]  (ends with __syncthreads)
__device__ __forceinline__ void scale_rows(float* __restrict__ Pb,
                                           const float* __restrict__ rinv,
                                           const float* __restrict__ gts,
                                           int gi, int NK, int tid)
{
    int r = tid & 63, part = tid >> 6;
    float f = gts[r * 3 + gi] * rinv[r];
    for (int c = part; c < NK; c += 4) Pb[r * PSTR + c] *= f;
    __syncthreads();
}

// ---------------- fused main kernel (persistent, double-buffered) ----------------
__global__ void __launch_bounds__(256, 1) nsa_main(
    const float* __restrict__ q, const float* __restrict__ k, const float* __restrict__ v,
    const float* __restrict__ wgate, const float* __restrict__ bgate,
    float* __restrict__ out)
{
    extern __shared__ float sm[];
    float* Qs   = sm;                    // 64*130
    float* Abuf = Qs   + 64 * QSTR;      // 64*130  KV buffer A
    float* Bbuf = Abuf + 64 * QSTR;      // 64*130  KV buffer B
    float* Pb   = Bbuf + 64 * QSTR;      // 64*130
    float* rinv = Pb  + 64 * PSTR;       // 64
    float* rmax = rinv + 64;             // 64
    float* red  = rmax + 64;             // 256
    float* gts  = red  + 256;            // 192
    float* Cs   = gts  + 192;            // 64
    float* Gb   = Cs   + 64;             // 64
    float* wgs  = Gb   + 64;             // 384
    int*   topi = (int*)(wgs + 384);     // 2
    unsigned int* s_item = (unsigned int*)(topi + 2);

    const int tid = threadIdx.x;
    const int rho = tid >> 4;   // 0..15 row group
    const int gg  = tid & 15;   // 0..15 col group

    // gate weights loaded once per persistent CTA
    for (int i = tid; i < 3 * DIMn; i += 256) wgs[i] = wgate[i];

    float4 pf[8];

    for (;;) {
        __syncthreads();   // smem safe to reuse; also orders s_item
        if (tid == 0) *s_item = atomicAdd(&g_ticket, 1u);
        __syncthreads();
        unsigned int bhq = *s_item;
        if (bhq >= NITEMS) break;

        const int qb  = bhq & (NQB - 1);
        const int bh  = bhq >> 4;
        const int h   = bh & (Hn - 1);
        const int b   = bh >> 3;
        const int q0  = qb * BQ;
        const int wbase = q0 - WINR;

        // window tile range (contiguous)
        const int clo_min = (128 - q0 > 0) ? (128 - q0) : 0;
        const int chi_max = (1151 - q0 < 319) ? (1151 - q0) : 319;
        const int t_lo = clo_min >> 6;
        const int t_hi = chi_max >> 6;

        // ---- load Q tile ----
        {
            const float4* q4 = (const float4*)(q + ((size_t)(b * Sn + q0) * Hn + h) * DIMn);
            for (int idx = tid; idx < 64 * 32; idx += 256) {
                int t = idx >> 5, d4 = idx & 31;
                float4 val = q4[(size_t)t * (Hn * DIMn / 4) + d4];
                float* ds = &Qs[t * QSTR + (d4 << 2)];
                ds[0] = val.x; ds[1] = val.y; ds[2] = val.z; ds[3] = val.w;
            }
        }
        __syncthreads();

        // prefetch first window K tile; hide behind gate compute
        pf_ldg_kv(pf, k, b, h, wbase + t_lo * 64, tid, true);

        // ---- gates: sigmoid(q . w_gate[c] + b_gate[c]) ----
        if (tid < 192) {
            int r = tid / 3, c = tid - 3 * r;
            float a = bgate[c];
            const float* qr = &Qs[r * QSTR];
            const float* wr = &wgs[c * DIMn];
#pragma unroll 8
            for (int d = 0; d < DIMn; ++d) a += qr[d] * wr[d];
            gts[r * 3 + c] = 1.0f / (1.0f + __expf(-a));
        }
        pf_sts(pf, Abuf, tid);
        __syncthreads();   // A = K_{t_lo}, gates ready

        u64 acc2[4][4];
#pragma unroll
        for (int i = 0; i < 4; ++i)
#pragma unroll
            for (int m = 0; m < 4; ++m) acc2[i][m] = 0ULL;

        // ================= WINDOW branch (flash-style, double-buffered) =================
        {
            int clo[4], chi[4];
#pragma unroll
            for (int i = 0; i < 4; ++i) {
                int r = rho + 16 * i;
                int lo = 128 - q0;  if (lo < r) lo = r;
                int hi = 1151 - q0; if (hi > r + 256) hi = r + 256;
                clo[i] = lo; chi[i] = hi;
            }

            float m_[4], l_[4];
#pragma unroll
            for (int i = 0; i < 4; ++i) { m_[i] = NEG_INF; l_[i] = 0.f; }

#pragma unroll 1
            for (int kt = t_lo; kt <= t_hi; ++kt) {
                // prefetch V_kt while computing QK from A
                pf_ldg_kv(pf, v, b, h, wbase + kt * 64, tid, true);

                float s[4][4];
                qk_core(Qs, Abuf, s, rho, gg);

                // scale + hoisted range mask
#pragma unroll
                for (int i = 0; i < 4; ++i) {
#pragma unroll
                    for (int j = 0; j < 4; ++j) {
                        int cgl = kt * 64 + gg + 16 * j;
                        bool ok = (cgl >= clo[i]) && (cgl <= chi[i]);
                        s[i][j] = ok ? s[i][j] * SCALE_MUL : NEG_INF;
                    }
                }

                // online softmax update; stats replicated over the 16-lane column group
#pragma unroll
                for (int i = 0; i < 4; ++i) {
                    float tm = fmaxf(fmaxf(s[i][0], s[i][1]), fmaxf(s[i][2], s[i][3]));
                    tm = fmaxf(tm, __shfl_xor_sync(0xffffffffu, tm, 1));
                    tm = fmaxf(tm, __shfl_xor_sync(0xffffffffu, tm, 2));
                    tm = fmaxf(tm, __shfl_xor_sync(0xffffffffu, tm, 4));
                    tm = fmaxf(tm, __shfl_xor_sync(0xffffffffu, tm, 8));
                    float nm = fmaxf(m_[i], tm);
                    float sc = __expf(m_[i] - nm);   // ==1 when both sentinel (acc is 0 there)
                    m_[i] = nm;
                    float rs = 0.f;
#pragma unroll
                    for (int j = 0; j < 4; ++j) {
                        float e = (s[i][j] > -1e29f) ? __expf(s[i][j] - nm) : 0.f;
                        s[i][j] = e;
                        rs += e;
                    }
                    rs += __shfl_xor_sync(0xffffffffu, rs, 1);
                    rs += __shfl_xor_sync(0xffffffffu, rs, 2);
                    rs += __shfl_xor_sync(0xffffffffu, rs, 4);
                    rs += __shfl_xor_sync(0xffffffffu, rs, 8);
                    l_[i] = l_[i] * sc + rs;
                    u64 sc2 = DUP2(sc);
#pragma unroll
                    for (int m = 0; m < 4; ++m) acc2[i][m] = MUL2(acc2[i][m], sc2);
                    int r = rho + 16 * i;
#pragma unroll
                    for (int j = 0; j < 4; ++j) Pb[r * PSTR + gg + 16 * j] = s[i][j];
                }
                pf_sts(pf, Bbuf, tid);   // B = V_kt
                __syncthreads();         // Pb + B published; A reads done

                // prefetch next K (or cmp K) while PV runs from B
                if (kt < t_hi) pf_ldg_kv(pf, k, b, h, wbase + (kt + 1) * 64, tid, true);
                else           pf_ldg_cmp(pf, g_cmpK, bh, tid);

                gemm_pv(Pb, Bbuf, acc2, rho, gg, 0);
                pf_sts(pf, Abuf, tid);   // A = next K / cmpK
                __syncthreads();
            }
            // finalize window: acc *= gate2 / rowsum
#pragma unroll
            for (int i = 0; i < 4; ++i) {
                int r = rho + 16 * i;
                u64 f2 = DUP2(gts[r * 3 + 2] / l_[i]);
#pragma unroll
                for (int m = 0; m < 4; ++m) acc2[i][m] = MUL2(acc2[i][m], f2);
            }
        }

        // ================= CMP branch (A = cmpK) =================
        gemm_qk<0>(Qs, Abuf, Pb, rho, gg, 0, SQRT_D);
        pf_ldg_cmp(pf, g_cmpV, bh, tid);    // hide cmpV load behind softmax/reductions
        __syncthreads();
        softmax_rows(Pb, rmax, rinv, red, 64, tid);

        // column sums of normalized P_cmp (256 threads: 64 cols x 4 row-parts)
        {
            int col = tid & 63, part = tid >> 6;
            float s = 0.f;
            int r0 = part * 16;
#pragma unroll 4
            for (int r = r0; r < r0 + 16; ++r) s += Pb[r * PSTR + col] * rinv[r];
            red[part * 64 + col] = s;
        }
        __syncthreads();
        if (tid < 64)
            Cs[tid] = red[tid] + red[64 + tid] + red[128 + tid] + red[192 + tid];
        __syncthreads();
        // slc-map convolution: weights 1,2,2,2,1 at i = 4j, 4j-1, 4j-2, 4j-3, 4j-4
        if (tid < NSLC) {
            int j4 = 4 * tid;
            float g = 0.f;
            if (j4 < NCMP)                       g += Cs[j4];
            if (j4 - 1 >= 0 && j4 - 1 < NCMP)    g += 2.f * Cs[j4 - 1];
            if (j4 - 2 >= 0 && j4 - 2 < NCMP)    g += 2.f * Cs[j4 - 2];
            if (j4 - 3 >= 0 && j4 - 3 < NCMP)    g += 2.f * Cs[j4 - 3];
            if (j4 - 4 >= 0 && j4 - 4 < NCMP)    g += Cs[j4 - 4];
            Gb[tid] = g;
        }
        __syncthreads();
        // deterministic top-2 (jax tie rule: lower index first) — warp 0 reduction
        if (tid < 32) {
            float a  = (tid < NSLC)      ? Gb[tid]      : NEG_INF;
            float bb = (tid + 32 < NSLC) ? Gb[tid + 32] : NEG_INF;
            float m1 = a; int i1 = tid;
            if (bb > m1) { m1 = bb; i1 = tid + 32; }
#pragma unroll
            for (int off = 16; off > 0; off >>= 1) {
                float om = __shfl_down_sync(0xffffffffu, m1, off);
                int   oi = __shfl_down_sync(0xffffffffu, i1, off);
                if (om > m1 || (om == m1 && oi < i1)) { m1 = om; i1 = oi; }
            }
            int i0 = __shfl_sync(0xffffffffu, i1, 0);
            float a2  = (tid == i0)      ? NEG_INF : a;
            float b2  = (tid + 32 == i0) ? NEG_INF : bb;
            float m2 = a2; int i2 = tid;
            if (b2 > m2) { m2 = b2; i2 = tid + 32; }
#pragma unroll
            for (int off = 16; off > 0; off >>= 1) {
                float om = __shfl_down_sync(0xffffffffu, m2, off);
                int   oi = __shfl_down_sync(0xffffffffu, i2, off);
                if (om > m2 || (om == m2 && oi < i2)) { m2 = om; i2 = oi; }
            }
            if (tid == 0) { topi[0] = i0; topi[1] = i2; }
        }
        pf_sts(pf, Bbuf, tid);                   // B = cmpV (published by scale_rows' sync)
        scale_rows(Pb, rinv, gts, 0, 64, tid);   // gate0 fold; end sync -> topi + B visible

        int j0 = topi[0], j1 = topi[1];
        pf_ldg_kv(pf, k, b, h, j0 * 16, tid, false);  // K_j0 hides behind cmp PV
        gemm_pv(Pb, Bbuf, acc2, rho, gg, 0);
        __syncthreads();                  // Pb free for slc QK
        pf_sts(pf, Abuf, tid);            // A = K_j0
        __syncthreads();

        // ================= SLC branch =================
        {
            pf_ldg_kv(pf, k, b, h, j1 * 16, tid, false);
            gemm_qk<1>(Qs, Abuf, Pb, rho, gg, 0, SCALE_MUL);
            pf_sts(pf, Bbuf, tid);        // B = K_j1
            __syncthreads();

            pf_ldg_kv(pf, v, b, h, j0 * 16, tid, false);
            gemm_qk<1>(Qs, Bbuf, Pb, rho, gg, 64, SCALE_MUL);
            pf_sts(pf, Abuf, tid);        // A = V_j0
            __syncthreads();              // Pb complete

            pf_ldg_kv(pf, v, b, h, j1 * 16, tid, false);
            softmax_rows(Pb, rmax, rinv, red, 128, tid);
            pf_sts(pf, Bbuf, tid);        // B = V_j1 (published by scale_rows' sync)
            scale_rows(Pb, rinv, gts, 1, 128, tid);

            gemm_pv(Pb, Abuf, acc2, rho, gg, 0);
            gemm_pv(Pb, Bbuf, acc2, rho, gg, 64);
        }

        // ---- write output (column pairs 2gg+32m) ----
#pragma unroll
        for (int i = 0; i < 4; ++i) {
            int r = rho + 16 * i;
            float* op = out + ((size_t)(b * Sn + q0 + r) * Hn + h) * DIMn + 2 * gg;
#pragma unroll
            for (int m = 0; m < 4; ++m) {
                float x, y; UNPK(acc2[i][m], x, y);
                *(float2*)(op + 32 * m) = make_float2(x, y);
            }
        }
    }
}

// ---------------- launch ----------------
extern "C" void kernel_launch(void* const* d_in, const int* in_sizes, int n_in,
                              void* d_out, int out_size)
{
    (void)in_sizes; (void)n_in; (void)out_size;
    const float* q   = (const float*)d_in[0];
    const float* k   = (const float*)d_in[1];
    const float* v   = (const float*)d_in[2];
    const float* wck = (const float*)d_in[3];
    const float* bck = (const float*)d_in[4];
    const float* wcv = (const float*)d_in[5];
    const float* bcv = (const float*)d_in[6];
    const float* wg  = (const float*)d_in[7];
    const float* bg  = (const float*)d_in[8];
    float* out = (float*)d_out;

    // kernel A: compressed K/V (also resets the work-stealing ticket)
    int totalA = Bn * Hn * NCMP * DIMn;
    cmp_kv_kernel<<<(totalA + 255) / 256, 256>>>(k, v, wck, bck, wcv, bcv);

    // fused NSA kernel: persistent, 1 CTA/SM (GB300: 152 SMs), double-buffered
    size_t smem_floats = (size_t)4 * 64 * QSTR
                       + 64 + 64 + 256 + 192 + 64 + 64 + 384 + 8;
    size_t smem_bytes = smem_floats * sizeof(float);
    cudaFuncSetAttribute(nsa_main, cudaFuncAttributeMaxDynamicSharedMemorySize,
                         (int)smem_bytes);
    nsa_main<<<152, 256, smem_bytes>>>(q, k, v, wg, bg, out);
}

// round 14
// speedup vs baseline: 1.5592x; 1.2470x over previous
#include <cuda_runtime.h>

// ---------------- problem constants ----------------
#define Bn    2
#define Sn    1024
#define Hn    8
#define DIMn  128
#define LCMP  32
#define NCMP  63          // (1024-32)/16+1
#define NSLC  61          // (1024-64)/16+1
#define BQ    64
#define NQB   (Sn / BQ)   // 16
#define NITEMS (Bn * Hn * NQB)  // 256
#define WINR  128
#define QSTR  132         // (4g+t)%32 conflict-free for mma fragments; even for LDS.64
#define PSTR  130
#define NEG_INF (-1e30f)

#define SCALE_MUL 0.08838834764831845f   // 1/sqrt(128): slc & window
#define SQRT_D    11.313708498984761f    // sqrt(128): cmp branch (reference divides by scale)

typedef unsigned long long u64;

// ---------------- f32x2 packed helpers ----------------
__device__ __forceinline__ u64 FMA2(u64 a, u64 b, u64 c) {
    u64 d;
    asm("fma.rn.f32x2 %0, %1, %2, %3;" : "=l"(d) : "l"(a), "l"(b), "l"(c));
    return d;
}
__device__ __forceinline__ u64 MUL2(u64 a, u64 b) {
    u64 d;
    asm("mul.rn.f32x2 %0, %1, %2;" : "=l"(d) : "l"(a), "l"(b));
    return d;
}
__device__ __forceinline__ u64 DUP2(float p) {
    u64 d;
    asm("mov.b64 %0, {%1, %1};" : "=l"(d) : "f"(p));
    return d;
}
__device__ __forceinline__ void UNPK(u64 a, float& x, float& y) {
    asm("mov.b64 {%0, %1}, %2;" : "=f"(x), "=f"(y) : "l"(a));
}
__device__ __forceinline__ float toTf32(float x) {
    unsigned u;
    asm("cvt.rna.tf32.f32 %0, %1;" : "=r"(u) : "f"(x));
    return __uint_as_float(u);
}

// scratch for compressed K/V: [b][h][n][d]
__device__ float g_cmpK[Bn * Hn * NCMP * DIMn];
__device__ float g_cmpV[Bn * Hn * NCMP * DIMn];
__device__ unsigned int g_ticket;

// ---------------- kernel A: compressed K/V (+ ticket reset) ----------------
__global__ void __launch_bounds__(256) cmp_kv_kernel(
    const float* __restrict__ k, const float* __restrict__ v,
    const float* __restrict__ wck, const float* __restrict__ bck,
    const float* __restrict__ wcv, const float* __restrict__ bcv)
{
    __shared__ float swk[LCMP], swv[LCMP], sb[2];
    int tid = threadIdx.x;
    if (blockIdx.x == 0 && tid == 0) g_ticket = 0u;   // reset work-stealing ticket
    if (tid < LCMP) { swk[tid] = wck[tid]; swv[tid] = wcv[tid]; }
    if (tid == 0)   { sb[0] = bck[0]; sb[1] = bcv[0]; }
    __syncthreads();

    int idx = blockIdx.x * 256 + tid;
    if (idx >= Bn * Hn * NCMP * DIMn) return;
    int d  = idx & (DIMn - 1);
    int n  = (idx >> 7) % NCMP;
    int bh = idx / (NCMP * DIMn);
    int h  = bh & (Hn - 1);
    int b  = bh >> 3;

    const float* kb = k + ((size_t)(b * Sn + n * 16) * Hn + h) * DIMn + d;
    const float* vb = v + ((size_t)(b * Sn + n * 16) * Hn + h) * DIMn + d;
    float ak = 0.f, av = 0.f;
#pragma unroll
    for (int l = 0; l < LCMP; ++l) {
        ak += kb[(size_t)l * Hn * DIMn] * swk[l];
        av += vb[(size_t)l * Hn * DIMn] * swv[l];
    }
    g_cmpK[idx] = ak + sb[0];
    g_cmpV[idx] = av + sb[1];
}

// ---------------- prefetch helpers (global -> regs -> smem) ----------------
__device__ __forceinline__ void pf_ldg_kv(float4 r[8], const float* __restrict__ src,
                                          int b, int h, int s_base, int tid, bool check)
{
    int t0 = tid >> 5, d4 = tid & 31;
#pragma unroll
    for (int i = 0; i < 8; ++i) {
        int srow = s_base + t0 + 8 * i;
        float4 val = make_float4(0.f, 0.f, 0.f, 0.f);
        if (!check || ((unsigned)srow < (unsigned)Sn))
            val = ((const float4*)(src + ((size_t)(b * Sn + srow) * Hn + h) * DIMn))[d4];
        r[i] = val;
    }
}
__device__ __forceinline__ void pf_ldg_cmp(float4 r[8], const float* __restrict__ src,
                                           int bh, int tid)
{
    int t0 = tid >> 5, d4 = tid & 31;
#pragma unroll
    for (int i = 0; i < 8; ++i) {
        int t = t0 + 8 * i;
        float4 val = make_float4(0.f, 0.f, 0.f, 0.f);
        if (t < NCMP)
            val = ((const float4*)(src + ((size_t)bh * NCMP + t) * DIMn))[d4];
        r[i] = val;
    }
}
__device__ __forceinline__ void pf_sts(const float4 r[8], float* __restrict__ dst, int tid)
{
    int t0 = tid >> 5, d4 = tid & 31;
#pragma unroll
    for (int i = 0; i < 8; ++i) {
        float* ds = &dst[(t0 + 8 * i) * QSTR + (d4 << 2)];
        *(float2*)(ds)     = make_float2(r[i].x, r[i].y);
        *(float2*)(ds + 2) = make_float2(r[i].z, r[i].w);
    }
}
// tf32-rounded store (for K tiles consumed by mma)
__device__ __forceinline__ void pf_sts_tf32(const float4 r[8], float* __restrict__ dst, int tid)
{
    int t0 = tid >> 5, d4 = tid & 31;
#pragma unroll
    for (int i = 0; i < 8; ++i) {
        float* ds = &dst[(t0 + 8 * i) * QSTR + (d4 << 2)];
        *(float2*)(ds)     = make_float2(toTf32(r[i].x), toTf32(r[i].y));
        *(float2*)(ds + 2) = make_float2(toTf32(r[i].z), toTf32(r[i].w));
    }
}

// ---------------- tf32 mma QK: 64x64 tile, 8 warps (4M x 2N), epilogue STS ----------------
// QsT: tf32-rounded Q [64 x 128] (stride QSTR). Ks: tf32-rounded K [64 x 128].
// Writes scl * (Q K^T) to Pbase (stride PSTR, 64 cols starting at Pbase).
__device__ __forceinline__ void mma_qk_sts(const float* __restrict__ QsT,
                                           const float* __restrict__ Ks,
                                           float* __restrict__ Pbase,
                                           int wid, int lane, float scl)
{
    const int g = lane >> 2, t = lane & 3;
    const int mr = 16 * (wid & 3);
    const int nc = 32 * (wid >> 2);

    float c[4][4];
#pragma unroll
    for (int nt = 0; nt < 4; ++nt)
#pragma unroll
        for (int r = 0; r < 4; ++r) c[nt][r] = 0.f;

    const float* a0p = QsT + (mr + g) * QSTR + t;
    const float* a1p = a0p + 8 * QSTR;
    const float* bbp = Ks + (nc + g) * QSTR + t;

#pragma unroll
    for (int ks = 0; ks < 16; ++ks) {
        int kb = 8 * ks;
        unsigned ua0 = __float_as_uint(a0p[kb]);
        unsigned ua1 = __float_as_uint(a1p[kb]);
        unsigned ua2 = __float_as_uint(a0p[kb + 4]);
        unsigned ua3 = __float_as_uint(a1p[kb + 4]);
#pragma unroll
        for (int nt = 0; nt < 4; ++nt) {
            const float* bp = bbp + nt * 8 * QSTR + kb;
            unsigned ub0 = __float_as_uint(bp[0]);
            unsigned ub1 = __float_as_uint(bp[4]);
            asm volatile(
                "mma.sync.aligned.m16n8k8.row.col.f32.tf32.tf32.f32 "
                "{%0,%1,%2,%3}, {%4,%5,%6,%7}, {%8,%9}, {%0,%1,%2,%3};"
                : "+f"(c[nt][0]), "+f"(c[nt][1]), "+f"(c[nt][2]), "+f"(c[nt][3])
                : "r"(ua0), "r"(ua1), "r"(ua2), "r"(ua3), "r"(ub0), "r"(ub1));
        }
    }
    // epilogue: c0:(g,2t) c1:(g,2t+1) c2:(g+8,2t) c3:(g+8,2t+1) within (mr, nc+8nt)
    float* p0 = Pbase + (mr + g) * PSTR + nc + 2 * t;
    float* p1 = p0 + 8 * PSTR;
#pragma unroll
    for (int nt = 0; nt < 4; ++nt) {
        *(float2*)(p0 + 8 * nt) = make_float2(c[nt][0] * scl, c[nt][1] * scl);
        *(float2*)(p1 + 8 * nt) = make_float2(c[nt][2] * scl, c[nt][3] * scl);
    }
}

// ---------------- scalar GEMM helpers (cmp QK + all PV) ----------------

// QK core (f32x2 along kd): s[4][4] = Qs(64x128) * Ks(64x128)^T
__device__ __forceinline__ void qk_core(const float* __restrict__ Qs,
                                        const float* __restrict__ Ks,
                                        float s[4][4], int rho, int gg)
{
    u64 s2[4][4];
#pragma unroll
    for (int i = 0; i < 4; ++i)
#pragma unroll
        for (int j = 0; j < 4; ++j) s2[i][j] = 0ULL;

    const u64* qp = (const u64*)(Qs + rho * QSTR);
    const u64* kp = (const u64*)(Ks + gg  * QSTR);
    const int RS = 8 * QSTR;   // 16 rows in u64 units
#pragma unroll 4
    for (int kd = 0; kd < DIMn / 2; ++kd) {
        u64 a0 = qp[kd];
        u64 a1 = qp[RS + kd];
        u64 a2 = qp[2 * RS + kd];
        u64 a3 = qp[3 * RS + kd];
        u64 b0 = kp[kd];
        u64 b1 = kp[RS + kd];
        u64 b2 = kp[2 * RS + kd];
        u64 b3 = kp[3 * RS + kd];
        s2[0][0] = FMA2(a0, b0, s2[0][0]); s2[0][1] = FMA2(a0, b1, s2[0][1]);
        s2[0][2] = FMA2(a0, b2, s2[0][2]); s2[0][3] = FMA2(a0, b3, s2[0][3]);
        s2[1][0] = FMA2(a1, b0, s2[1][0]); s2[1][1] = FMA2(a1, b1, s2[1][1]);
        s2[1][2] = FMA2(a1, b2, s2[1][2]); s2[1][3] = FMA2(a1, b3, s2[1][3]);
        s2[2][0] = FMA2(a2, b0, s2[2][0]); s2[2][1] = FMA2(a2, b1, s2[2][1]);
        s2[2][2] = FMA2(a2, b2, s2[2][2]); s2[2][3] = FMA2(a2, b3, s2[2][3]);
        s2[3][0] = FMA2(a3, b0, s2[3][0]); s2[3][1] = FMA2(a3, b1, s2[3][1]);
        s2[3][2] = FMA2(a3, b2, s2[3][2]); s2[3][3] = FMA2(a3, b3, s2[3][3]);
    }
#pragma unroll
    for (int i = 0; i < 4; ++i)
#pragma unroll
        for (int j = 0; j < 4; ++j) {
            float x, y; UNPK(s2[i][j], x, y);
            s[i][j] = x + y;
        }
}

// cmp QK GEMM -> Pb (fp32, mask c>=NCMP)
__device__ __forceinline__ void gemm_qk_cmp(const float* __restrict__ Qs,
                                            const float* __restrict__ Ks,
                                            float* __restrict__ Pb,
                                            int rho, int gg)
{
    float s[4][4];
    qk_core(Qs, Ks, s, rho, gg);
#pragma unroll
    for (int i = 0; i < 4; ++i) {
        int r = rho + 16 * i;
#pragma unroll
        for (int j = 0; j < 4; ++j) {
            int c = gg + 16 * j;
            float val = s[i][j] * SQRT_D;
            if (c >= NCMP) val = NEG_INF;
            Pb[r * PSTR + c] = val;
        }
    }
}

// PV GEMM (f32x2 along output cols): acc2[4][4] += P(64 x 64-tile) * Vs(64x128)
__device__ __forceinline__ void gemm_pv(const float* __restrict__ Pb,
                                        const float* __restrict__ Vs,
                                        u64 acc2[4][4], int rho, int gg, int cb)
{
    const float* pp = Pb + rho * PSTR + cb;
    const float* vb = Vs + 2 * gg;
#pragma unroll 2
    for (int cl = 0; cl < 64; cl += 2) {
        const u64* vr0 = (const u64*)(vb + cl * QSTR);
        const u64* vr1 = (const u64*)(vb + (cl + 1) * QSTR);
        u64 v0[4], v1[4];
#pragma unroll
        for (int m = 0; m < 4; ++m) { v0[m] = vr0[16 * m]; v1[m] = vr1[16 * m]; }
#pragma unroll
        for (int i = 0; i < 4; ++i) {
            u64 p2 = *(const u64*)(pp + 16 * i * PSTR + cl);
            float pa, pbv; UNPK(p2, pa, pbv);
            u64 da = DUP2(pa), db = DUP2(pbv);
#pragma unroll
            for (int m = 0; m < 4; ++m) {
                acc2[i][m] = FMA2(da, v0[m], acc2[i][m]);
                acc2[i][m] = FMA2(db, v1[m], acc2[i][m]);
            }
        }
    }
}

// two-pass row softmax over Pb[:, 0:NK]; leaves exp() in Pb, 1/rowsum in rinv
__device__ __forceinline__ void softmax_rows(float* __restrict__ Pb,
                                             float* __restrict__ rmax,
                                             float* __restrict__ rinv,
                                             float* __restrict__ red,
                                             int NK, int tid)
{
    int r = tid & 63, part = tid >> 6;
    float m = NEG_INF;
    for (int c = part; c < NK; c += 4) m = fmaxf(m, Pb[r * PSTR + c]);
    red[part * 64 + r] = m;
    __syncthreads();
    if (tid < 64)
        rmax[tid] = fmaxf(fmaxf(red[tid], red[64 + tid]),
                          fmaxf(red[128 + tid], red[192 + tid]));
    __syncthreads();
    float mr = rmax[r];
    float sum = 0.f;
    for (int c = part; c < NK; c += 4) {
        float e = __expf(Pb[r * PSTR + c] - mr);
        Pb[r * PSTR + c] = e;
        sum += e;
    }
    red[part * 64 + r] = sum;
    __syncthreads();
    if (tid < 64)
        rinv[tid] = 1.0f / (red[tid] + red[64 + tid] + red[128 + tid] + red[192 + tid]);
    __syncthreads();
}

// P[r][c] *= gate[r][gi] / rowsum[r]  (ends with __syncthreads)
__device__ __forceinline__ void scale_rows(float* __restrict__ Pb,
                                           const float* __restrict__ rinv,
                                           const float* __restrict__ gts,
                                           int gi, int NK, int tid)
{
    int r = tid & 63, part = tid >> 6;
    float f = gts[r * 3 + gi] * rinv[r];
    for (int c = part; c < NK; c += 4) Pb[r * PSTR + c] *= f;
    __syncthreads();
}

// ---------------- fused main kernel (persistent, tf32 mma QK) ----------------
__global__ void __launch_bounds__(256, 1) nsa_main(
    const float* __restrict__ q, const float* __restrict__ k, const float* __restrict__ v,
    const float* __restrict__ wgate, const float* __restrict__ bgate,
    float* __restrict__ out)
{
    extern __shared__ float sm[];
    float* Qs   = sm;                    // 64*132 fp32 Q (cmp QK + gates)
    float* QsT  = Qs   + 64 * QSTR;      // 64*132 tf32 Q (mma)
    float* Abuf = QsT  + 64 * QSTR;      // 64*132 KV buffer A
    float* Bbuf = Abuf + 64 * QSTR;      // 64*132 KV buffer B
    float* Pb   = Bbuf + 64 * QSTR;      // 64*130
    float* rinv = Pb  + 64 * PSTR;       // 64
    float* rmax = rinv + 64;             // 64
    float* red  = rmax + 64;             // 256
    float* gts  = red  + 256;            // 192
    float* Cs   = gts  + 192;            // 64
    float* Gb   = Cs   + 64;             // 64
    float* wgs  = Gb   + 64;             // 384
    int*   topi = (int*)(wgs + 384);     // 2
    unsigned int* s_item = (unsigned int*)(topi + 2);

    const int tid  = threadIdx.x;
    const int wid  = tid >> 5;
    const int lane = tid & 31;
    const int rho  = tid >> 4;   // 0..15 row group
    const int gg   = tid & 15;   // 0..15 col group

    // gate weights loaded once per persistent CTA
    for (int i = tid; i < 3 * DIMn; i += 256) wgs[i] = wgate[i];

    float4 pf[8];

    for (;;) {
        __syncthreads();   // smem safe to reuse; also orders s_item
        if (tid == 0) *s_item = atomicAdd(&g_ticket, 1u);
        __syncthreads();
        unsigned int bhq = *s_item;
        if (bhq >= NITEMS) break;

        const int qb  = bhq & (NQB - 1);
        const int bh  = bhq >> 4;
        const int h   = bh & (Hn - 1);
        const int b   = bh >> 3;
        const int q0  = qb * BQ;
        const int wbase = q0 - WINR;

        // window tile range (contiguous)
        const int clo_min = (128 - q0 > 0) ? (128 - q0) : 0;
        const int chi_max = (1151 - q0 < 319) ? (1151 - q0) : 319;
        const int t_lo = clo_min >> 6;
        const int t_hi = chi_max >> 6;

        // ---- load Q tile (fp32 + tf32 copies) ----
        {
            const float4* q4 = (const float4*)(q + ((size_t)(b * Sn + q0) * Hn + h) * DIMn);
            for (int idx = tid; idx < 64 * 32; idx += 256) {
                int t = idx >> 5, d4 = idx & 31;
                float4 val = q4[(size_t)t * (Hn * DIMn / 4) + d4];
                float* ds = &Qs[t * QSTR + (d4 << 2)];
                ds[0] = val.x; ds[1] = val.y; ds[2] = val.z; ds[3] = val.w;
                float* dt = &QsT[t * QSTR + (d4 << 2)];
                dt[0] = toTf32(val.x); dt[1] = toTf32(val.y);
                dt[2] = toTf32(val.z); dt[3] = toTf32(val.w);
            }
        }
        __syncthreads();

        // prefetch first window K tile; hide behind gate compute
        pf_ldg_kv(pf, k, b, h, wbase + t_lo * 64, tid, true);

        // ---- gates: sigmoid(q . w_gate[c] + b_gate[c]) ----
        if (tid < 192) {
            int r = tid / 3, c = tid - 3 * r;
            float a = bgate[c];
            const float* qr = &Qs[r * QSTR];
            const float* wr = &wgs[c * DIMn];
#pragma unroll 8
            for (int d = 0; d < DIMn; ++d) a += qr[d] * wr[d];
            gts[r * 3 + c] = 1.0f / (1.0f + __expf(-a));
        }
        pf_sts_tf32(pf, Abuf, tid);
        __syncthreads();   // A = K_{t_lo} (tf32), gates ready

        u64 acc2[4][4];
#pragma unroll
        for (int i = 0; i < 4; ++i)
#pragma unroll
            for (int m = 0; m < 4; ++m) acc2[i][m] = 0ULL;

        // ================= WINDOW branch (flash-style, mma QK) =================
        {
            int clo[4], chi[4];
#pragma unroll
            for (int i = 0; i < 4; ++i) {
                int r = rho + 16 * i;
                int lo = 128 - q0;  if (lo < r) lo = r;
                int hi = 1151 - q0; if (hi > r + 256) hi = r + 256;
                clo[i] = lo; chi[i] = hi;
            }

            float m_[4], l_[4];
#pragma unroll
            for (int i = 0; i < 4; ++i) { m_[i] = NEG_INF; l_[i] = 0.f; }

#pragma unroll 1
            for (int kt = t_lo; kt <= t_hi; ++kt) {
                // prefetch V_kt while computing QK from A
                pf_ldg_kv(pf, v, b, h, wbase + kt * 64, tid, true);

                // tensor QK: raw scores -> Pb
                mma_qk_sts(QsT, Abuf, Pb, wid, lane, 1.0f);
                __syncthreads();   // Pb scores visible; Abuf reads done

                // online softmax on Pb (old 4x4 layout)
#pragma unroll
                for (int i = 0; i < 4; ++i) {
                    int r = rho + 16 * i;
                    float s[4];
#pragma unroll
                    for (int j = 0; j < 4; ++j) {
                        int cgl = kt * 64 + gg + 16 * j;
                        bool ok = (cgl >= clo[i]) && (cgl <= chi[i]);
                        s[j] = ok ? Pb[r * PSTR + gg + 16 * j] * SCALE_MUL : NEG_INF;
                    }
                    float tm = fmaxf(fmaxf(s[0], s[1]), fmaxf(s[2], s[3]));
                    tm = fmaxf(tm, __shfl_xor_sync(0xffffffffu, tm, 1));
                    tm = fmaxf(tm, __shfl_xor_sync(0xffffffffu, tm, 2));
                    tm = fmaxf(tm, __shfl_xor_sync(0xffffffffu, tm, 4));
                    tm = fmaxf(tm, __shfl_xor_sync(0xffffffffu, tm, 8));
                    float nm = fmaxf(m_[i], tm);
                    float sc = __expf(m_[i] - nm);   // ==1 when both sentinel (acc is 0 there)
                    m_[i] = nm;
                    float rs = 0.f;
#pragma unroll
                    for (int j = 0; j < 4; ++j) {
                        float e = (s[j] > -1e29f) ? __expf(s[j] - nm) : 0.f;
                        s[j] = e;
                        rs += e;
                    }
                    rs += __shfl_xor_sync(0xffffffffu, rs, 1);
                    rs += __shfl_xor_sync(0xffffffffu, rs, 2);
                    rs += __shfl_xor_sync(0xffffffffu, rs, 4);
                    rs += __shfl_xor_sync(0xffffffffu, rs, 8);
                    l_[i] = l_[i] * sc + rs;
                    u64 sc2 = DUP2(sc);
#pragma unroll
                    for (int m = 0; m < 4; ++m) acc2[i][m] = MUL2(acc2[i][m], sc2);
#pragma unroll
                    for (int j = 0; j < 4; ++j) Pb[r * PSTR + gg + 16 * j] = s[j];
                }
                pf_sts(pf, Bbuf, tid);   // B = V_kt (fp32)
                __syncthreads();         // exp-Pb + B published

                // prefetch next K (tf32) or cmp K (fp32) while PV runs from B
                if (kt < t_hi) pf_ldg_kv(pf, k, b, h, wbase + (kt + 1) * 64, tid, true);
                else           pf_ldg_cmp(pf, g_cmpK, bh, tid);

                gemm_pv(Pb, Bbuf, acc2, rho, gg, 0);
                if (kt < t_hi) pf_sts_tf32(pf, Abuf, tid);  // A = next K (tf32)
                else           pf_sts(pf, Abuf, tid);       // A = cmpK (fp32)
                __syncthreads();
            }
            // finalize window: acc *= gate2 / rowsum
#pragma unroll
            for (int i = 0; i < 4; ++i) {
                int r = rho + 16 * i;
                u64 f2 = DUP2(gts[r * 3 + 2] / l_[i]);
#pragma unroll
                for (int m = 0; m < 4; ++m) acc2[i][m] = MUL2(acc2[i][m], f2);
            }
        }

        // ================= CMP branch (A = cmpK, fp32 scalar QK) =================
        gemm_qk_cmp(Qs, Abuf, Pb, rho, gg);
        pf_ldg_cmp(pf, g_cmpV, bh, tid);    // hide cmpV load behind softmax/reductions
        __syncthreads();
        softmax_rows(Pb, rmax, rinv, red, 64, tid);

        // column sums of normalized P_cmp (256 threads: 64 cols x 4 row-parts)
        {
            int col = tid & 63, part = tid >> 6;
            float s = 0.f;
            int r0 = part * 16;
#pragma unroll 4
            for (int r = r0; r < r0 + 16; ++r) s += Pb[r * PSTR + col] * rinv[r];
            red[part * 64 + col] = s;
        }
        __syncthreads();
        if (tid < 64)
            Cs[tid] = red[tid] + red[64 + tid] + red[128 + tid] + red[192 + tid];
        __syncthreads();
        // slc-map convolution: weights 1,2,2,2,1 at i = 4j, 4j-1, 4j-2, 4j-3, 4j-4
        if (tid < NSLC) {
            int j4 = 4 * tid;
            float g = 0.f;
            if (j4 < NCMP)                       g += Cs[j4];
            if (j4 - 1 >= 0 && j4 - 1 < NCMP)    g += 2.f * Cs[j4 - 1];
            if (j4 - 2 >= 0 && j4 - 2 < NCMP)    g += 2.f * Cs[j4 - 2];
            if (j4 - 3 >= 0 && j4 - 3 < NCMP)    g += 2.f * Cs[j4 - 3];
            if (j4 - 4 >= 0 && j4 - 4 < NCMP)    g += Cs[j4 - 4];
            Gb[tid] = g;
        }
        __syncthreads();
        // deterministic top-2 (jax tie rule: lower index first) — warp 0 reduction
        if (tid < 32) {
            float a  = (tid < NSLC)      ? Gb[tid]      : NEG_INF;
            float bb = (tid + 32 < NSLC) ? Gb[tid + 32] : NEG_INF;
            float m1 = a; int i1 = tid;
            if (bb > m1) { m1 = bb; i1 = tid + 32; }
#pragma unroll
            for (int off = 16; off > 0; off >>= 1) {
                float om = __shfl_down_sync(0xffffffffu, m1, off);
                int   oi = __shfl_down_sync(0xffffffffu, i1, off);
                if (om > m1 || (om == m1 && oi < i1)) { m1 = om; i1 = oi; }
            }
            int i0 = __shfl_sync(0xffffffffu, i1, 0);
            float a2  = (tid == i0)      ? NEG_INF : a;
            float b2  = (tid + 32 == i0) ? NEG_INF : bb;
            float m2 = a2; int i2 = tid;
            if (b2 > m2) { m2 = b2; i2 = tid + 32; }
#pragma unroll
            for (int off = 16; off > 0; off >>= 1) {
                float om = __shfl_down_sync(0xffffffffu, m2, off);
                int   oi = __shfl_down_sync(0xffffffffu, i2, off);
                if (om > m2 || (om == m2 && oi < i2)) { m2 = om; i2 = oi; }
            }
            if (tid == 0) { topi[0] = i0; topi[1] = i2; }
        }
        pf_sts(pf, Bbuf, tid);                   // B = cmpV (published by scale_rows' sync)
        scale_rows(Pb, rinv, gts, 0, 64, tid);   // gate0 fold; end sync -> topi + B visible

        int j0 = topi[0], j1 = topi[1];
        pf_ldg_kv(pf, k, b, h, j0 * 16, tid, false);  // K_j0 hides behind cmp PV
        gemm_pv(Pb, Bbuf, acc2, rho, gg, 0);
        __syncthreads();                  // Pb free for slc QK
        pf_sts_tf32(pf, Abuf, tid);       // A = K_j0 (tf32)
        __syncthreads();

        // ================= SLC branch (mma QK) =================
        {
            pf_ldg_kv(pf, k, b, h, j1 * 16, tid, false);
            mma_qk_sts(QsT, Abuf, Pb, wid, lane, SCALE_MUL);       // cols 0..63
            pf_sts_tf32(pf, Bbuf, tid);   // B = K_j1 (tf32)
            __syncthreads();

            pf_ldg_kv(pf, v, b, h, j0 * 16, tid, false);
            mma_qk_sts(QsT, Bbuf, Pb + 64, wid, lane, SCALE_MUL);  // cols 64..127
            pf_sts(pf, Abuf, tid);        // A = V_j0 (fp32)
            __syncthreads();              // Pb complete

            pf_ldg_kv(pf, v, b, h, j1 * 16, tid, false);
            softmax_rows(Pb, rmax, rinv, red, 128, tid);
            pf_sts(pf, Bbuf, tid);        // B = V_j1 (published by scale_rows' sync)
            scale_rows(Pb, rinv, gts, 1, 128, tid);

            gemm_pv(Pb, Abuf, acc2, rho, gg, 0);
            gemm_pv(Pb, Bbuf, acc2, rho, gg, 64);
        }

        // ---- write output (column pairs 2gg+32m) ----
#pragma unroll
        for (int i = 0; i < 4; ++i) {
            int r = rho + 16 * i;
            float* op = out + ((size_t)(b * Sn + q0 + r) * Hn + h) * DIMn + 2 * gg;
#pragma unroll
            for (int m = 0; m < 4; ++m) {
                float x, y; UNPK(acc2[i][m], x, y);
                *(float2*)(op + 32 * m) = make_float2(x, y);
            }
        }
    }
}

// ---------------- launch ----------------
extern "C" void kernel_launch(void* const* d_in, const int* in_sizes, int n_in,
                              void* d_out, int out_size)
{
    (void)in_sizes; (void)n_in; (void)out_size;
    const float* q   = (const float*)d_in[0];
    const float* k   = (const float*)d_in[1];
    const float* v   = (const float*)d_in[2];
    const float* wck = (const float*)d_in[3];
    const float* bck = (const float*)d_in[4];
    const float* wcv = (const float*)d_in[5];
    const float* bcv = (const float*)d_in[6];
    const float* wg  = (const float*)d_in[7];
    const float* bg  = (const float*)d_in[8];
    float* out = (float*)d_out;

    // kernel A: compressed K/V (also resets the work-stealing ticket)
    int totalA = Bn * Hn * NCMP * DIMn;
    cmp_kv_kernel<<<(totalA + 255) / 256, 256>>>(k, v, wck, bck, wcv, bcv);

    // fused NSA kernel: persistent, 1 CTA/SM (GB300: 152 SMs), tf32 mma QK
    size_t smem_floats = (size_t)4 * 64 * QSTR + (size_t)64 * PSTR
                       + 64 + 64 + 256 + 192 + 64 + 64 + 384 + 8;
    size_t smem_bytes = smem_floats * sizeof(float);
    cudaFuncSetAttribute(nsa_main, cudaFuncAttributeMaxDynamicSharedMemorySize,
                         (int)smem_bytes);
    nsa_main<<<152, 256, smem_bytes>>>(q, k, v, wg, bg, out);
}

// round 15
// speedup vs baseline: 2.3453x; 1.5042x over previous
#include <cuda_runtime.h>

// ---------------- problem constants ----------------
#define Bn    2
#define Sn    1024
#define Hn    8
#define DIMn  128
#define LCMP  32
#define NCMP  63          // (1024-32)/16+1
#define NSLC  61          // (1024-64)/16+1
#define BQ    64
#define NQB   (Sn / BQ)   // 16
#define NITEMS (Bn * Hn * NQB)  // 256
#define WINR  128
#define QSTR  132         // 4 mod 32: conflict-free QK mma fragments
#define VSTR  136         // 8 mod 32: conflict-free PV B fragments
#define PSTR  132         // 4 mod 32: conflict-free PV A fragments
#define NEG_INF (-1e30f)

#define SCALE_MUL 0.08838834764831845f   // 1/sqrt(128): slc & window
#define SQRT_D    11.313708498984761f    // sqrt(128): cmp branch (reference divides by scale)

typedef unsigned long long u64;

// ---------------- packed / tf32 helpers ----------------
__device__ __forceinline__ u64 FMA2(u64 a, u64 b, u64 c) {
    u64 d;
    asm("fma.rn.f32x2 %0, %1, %2, %3;" : "=l"(d) : "l"(a), "l"(b), "l"(c));
    return d;
}
__device__ __forceinline__ void UNPK(u64 a, float& x, float& y) {
    asm("mov.b64 {%0, %1}, %2;" : "=f"(x), "=f"(y) : "l"(a));
}
__device__ __forceinline__ float toTf32(float x) {
    unsigned u;
    asm("cvt.rna.tf32.f32 %0, %1;" : "=r"(u) : "f"(x));
    return __uint_as_float(u);
}

// scratch for compressed K/V: [b][h][n][d]
__device__ float g_cmpK[Bn * Hn * NCMP * DIMn];
__device__ float g_cmpV[Bn * Hn * NCMP * DIMn];
__device__ unsigned int g_ticket;

// ---------------- kernel A: compressed K/V (+ ticket reset) ----------------
__global__ void __launch_bounds__(256) cmp_kv_kernel(
    const float* __restrict__ k, const float* __restrict__ v,
    const float* __restrict__ wck, const float* __restrict__ bck,
    const float* __restrict__ wcv, const float* __restrict__ bcv)
{
    __shared__ float swk[LCMP], swv[LCMP], sb[2];
    int tid = threadIdx.x;
    if (blockIdx.x == 0 && tid == 0) g_ticket = 0u;
    if (tid < LCMP) { swk[tid] = wck[tid]; swv[tid] = wcv[tid]; }
    if (tid == 0)   { sb[0] = bck[0]; sb[1] = bcv[0]; }
    __syncthreads();

    int idx = blockIdx.x * 256 + tid;
    if (idx >= Bn * Hn * NCMP * DIMn) return;
    int d  = idx & (DIMn - 1);
    int n  = (idx >> 7) % NCMP;
    int bh = idx / (NCMP * DIMn);
    int h  = bh & (Hn - 1);
    int b  = bh >> 3;

    const float* kb = k + ((size_t)(b * Sn + n * 16) * Hn + h) * DIMn + d;
    const float* vb = v + ((size_t)(b * Sn + n * 16) * Hn + h) * DIMn + d;
    float ak = 0.f, av = 0.f;
#pragma unroll
    for (int l = 0; l < LCMP; ++l) {
        ak += kb[(size_t)l * Hn * DIMn] * swk[l];
        av += vb[(size_t)l * Hn * DIMn] * swv[l];
    }
    g_cmpK[idx] = ak + sb[0];
    g_cmpV[idx] = av + sb[1];
}

// ---------------- prefetch helpers (global -> regs -> smem) ----------------
__device__ __forceinline__ void pf_ldg_kv(float4 r[8], const float* __restrict__ src,
                                          int b, int h, int s_base, int tid, bool check)
{
    int t0 = tid >> 5, d4 = tid & 31;
#pragma unroll
    for (int i = 0; i < 8; ++i) {
        int srow = s_base + t0 + 8 * i;
        float4 val = make_float4(0.f, 0.f, 0.f, 0.f);
        if (!check || ((unsigned)srow < (unsigned)Sn))
            val = ((const float4*)(src + ((size_t)(b * Sn + srow) * Hn + h) * DIMn))[d4];
        r[i] = val;
    }
}
__device__ __forceinline__ void pf_ldg_cmp(float4 r[8], const float* __restrict__ src,
                                           int bh, int tid)
{
    int t0 = tid >> 5, d4 = tid & 31;
#pragma unroll
    for (int i = 0; i < 8; ++i) {
        int t = t0 + 8 * i;
        float4 val = make_float4(0.f, 0.f, 0.f, 0.f);
        if (t < NCMP)
            val = ((const float4*)(src + ((size_t)bh * NCMP + t) * DIMn))[d4];
        r[i] = val;
    }
}
template <int STRIDE, bool TF32>
__device__ __forceinline__ void pf_sts(const float4 r[8], float* __restrict__ dst, int tid)
{
    int t0 = tid >> 5, d4 = tid & 31;
#pragma unroll
    for (int i = 0; i < 8; ++i) {
        float* ds = &dst[(t0 + 8 * i) * STRIDE + (d4 << 2)];
        if (TF32) {
            *(float2*)(ds)     = make_float2(toTf32(r[i].x), toTf32(r[i].y));
            *(float2*)(ds + 2) = make_float2(toTf32(r[i].z), toTf32(r[i].w));
        } else {
            *(float2*)(ds)     = make_float2(r[i].x, r[i].y);
            *(float2*)(ds + 2) = make_float2(r[i].z, r[i].w);
        }
    }
}

// ---------------- tf32 mma QK: 64x64 tile, 8 warps (4M x 2N), epilogue STS ----------------
__device__ __forceinline__ void mma_qk_sts(const float* __restrict__ QsT,
                                           const float* __restrict__ Ks,
                                           float* __restrict__ Pbase,
                                           int wid, int lane, float scl)
{
    const int g = lane >> 2, t = lane & 3;
    const int mr = 16 * (wid & 3);
    const int nc = 32 * (wid >> 2);

    float c[4][4];
#pragma unroll
    for (int nt = 0; nt < 4; ++nt)
#pragma unroll
        for (int r = 0; r < 4; ++r) c[nt][r] = 0.f;

    const float* a0p = QsT + (mr + g) * QSTR + t;
    const float* a1p = a0p + 8 * QSTR;
    const float* bbp = Ks + (nc + g) * QSTR + t;

#pragma unroll
    for (int ks = 0; ks < 16; ++ks) {
        int kb = 8 * ks;
        unsigned ua0 = __float_as_uint(a0p[kb]);
        unsigned ua1 = __float_as_uint(a1p[kb]);
        unsigned ua2 = __float_as_uint(a0p[kb + 4]);
        unsigned ua3 = __float_as_uint(a1p[kb + 4]);
#pragma unroll
        for (int nt = 0; nt < 4; ++nt) {
            const float* bp = bbp + nt * 8 * QSTR + kb;
            unsigned ub0 = __float_as_uint(bp[0]);
            unsigned ub1 = __float_as_uint(bp[4]);
            asm volatile(
                "mma.sync.aligned.m16n8k8.row.col.f32.tf32.tf32.f32 "
                "{%0,%1,%2,%3}, {%4,%5,%6,%7}, {%8,%9}, {%0,%1,%2,%3};"
                : "+f"(c[nt][0]), "+f"(c[nt][1]), "+f"(c[nt][2]), "+f"(c[nt][3])
                : "r"(ua0), "r"(ua1), "r"(ua2), "r"(ua3), "r"(ub0), "r"(ub1));
        }
    }
    float* p0 = Pbase + (mr + g) * PSTR + nc + 2 * t;
    float* p1 = p0 + 8 * PSTR;
#pragma unroll
    for (int nt = 0; nt < 4; ++nt) {
        *(float2*)(p0 + 8 * nt) = make_float2(c[nt][0] * scl, c[nt][1] * scl);
        *(float2*)(p1 + 8 * nt) = make_float2(c[nt][2] * scl, c[nt][3] * scl);
    }
}

// ---------------- tf32 mma PV: acc[8][4] += P(64x64 @cb) * V(64x128) ----------------
// warp tile: 4M x 2N (m16 x n64); A = P (tf32 in Pb), B = V [key][dim] (tf32, stride VSTR)
__device__ __forceinline__ void mma_pv(const float* __restrict__ Pb,
                                       const float* __restrict__ Vs,
                                       float c[8][4], int wid, int lane, int cb)
{
    const int g = lane >> 2, t = lane & 3;
    const int mr = 16 * (wid & 3);
    const int nc = 64 * (wid >> 2);
    const float* ap = Pb + (mr + g) * PSTR + cb + t;
    const float* bp = Vs + t * VSTR + nc + g;
#pragma unroll
    for (int ks = 0; ks < 8; ++ks) {
        int kb = 8 * ks;
        unsigned ua0 = __float_as_uint(ap[kb]);
        unsigned ua1 = __float_as_uint(ap[8 * PSTR + kb]);
        unsigned ua2 = __float_as_uint(ap[kb + 4]);
        unsigned ua3 = __float_as_uint(ap[8 * PSTR + kb + 4]);
        const float* bk = bp + kb * VSTR;
#pragma unroll
        for (int nt = 0; nt < 8; ++nt) {
            unsigned ub0 = __float_as_uint(bk[8 * nt]);
            unsigned ub1 = __float_as_uint(bk[4 * VSTR + 8 * nt]);
            asm volatile(
                "mma.sync.aligned.m16n8k8.row.col.f32.tf32.tf32.f32 "
                "{%0,%1,%2,%3}, {%4,%5,%6,%7}, {%8,%9}, {%0,%1,%2,%3};"
                : "+f"(c[nt][0]), "+f"(c[nt][1]), "+f"(c[nt][2]), "+f"(c[nt][3])
                : "r"(ua0), "r"(ua1), "r"(ua2), "r"(ua3), "r"(ub0), "r"(ub1));
        }
    }
}

// ---------------- scalar QK (cmp branch only, fp32) ----------------
__device__ __forceinline__ void gemm_qk_cmp(const float* __restrict__ Qs,
                                            const float* __restrict__ Ks,
                                            float* __restrict__ Pb,
                                            int rho, int gg)
{
    u64 s2[4][4];
#pragma unroll
    for (int i = 0; i < 4; ++i)
#pragma unroll
        for (int j = 0; j < 4; ++j) s2[i][j] = 0ULL;

    const u64* qp = (const u64*)(Qs + rho * QSTR);
    const u64* kp = (const u64*)(Ks + gg  * QSTR);
    const int RS = 8 * QSTR;
#pragma unroll 4
    for (int kd = 0; kd < DIMn / 2; ++kd) {
        u64 a0 = qp[kd];
        u64 a1 = qp[RS + kd];
        u64 a2 = qp[2 * RS + kd];
        u64 a3 = qp[3 * RS + kd];
        u64 b0 = kp[kd];
        u64 b1 = kp[RS + kd];
        u64 b2 = kp[2 * RS + kd];
        u64 b3 = kp[3 * RS + kd];
        s2[0][0] = FMA2(a0, b0, s2[0][0]); s2[0][1] = FMA2(a0, b1, s2[0][1]);
        s2[0][2] = FMA2(a0, b2, s2[0][2]); s2[0][3] = FMA2(a0, b3, s2[0][3]);
        s2[1][0] = FMA2(a1, b0, s2[1][0]); s2[1][1] = FMA2(a1, b1, s2[1][1]);
        s2[1][2] = FMA2(a1, b2, s2[1][2]); s2[1][3] = FMA2(a1, b3, s2[1][3]);
        s2[2][0] = FMA2(a2, b0, s2[2][0]); s2[2][1] = FMA2(a2, b1, s2[2][1]);
        s2[2][2] = FMA2(a2, b2, s2[2][2]); s2[2][3] = FMA2(a2, b3, s2[2][3]);
        s2[3][0] = FMA2(a3, b0, s2[3][0]); s2[3][1] = FMA2(a3, b1, s2[3][1]);
        s2[3][2] = FMA2(a3, b2, s2[3][2]); s2[3][3] = FMA2(a3, b3, s2[3][3]);
    }
#pragma unroll
    for (int i = 0; i < 4; ++i) {
        int r = rho + 16 * i;
#pragma unroll
        for (int j = 0; j < 4; ++j) {
            int cc = gg + 16 * j;
            float x, y; UNPK(s2[i][j], x, y);
            float val = (x + y) * SQRT_D;
            if (cc >= NCMP) val = NEG_INF;
            Pb[r * PSTR + cc] = val;
        }
    }
}

// two-pass row softmax over Pb[:, 0:NK]; leaves exp() (fp32) in Pb, 1/rowsum in rinv
// mapping: r = tid>>2, part = tid&3  (conflict-free at PSTR%32==4)
__device__ __forceinline__ void softmax_rows(float* __restrict__ Pb,
                                             float* __restrict__ rmax,
                                             float* __restrict__ rinv,
                                             float* __restrict__ red,
                                             int NK, int tid)
{
    int r = tid >> 2, part = tid & 3;
    float m = NEG_INF;
    for (int c = part; c < NK; c += 4) m = fmaxf(m, Pb[r * PSTR + c]);
    red[part * 64 + r] = m;
    __syncthreads();
    if (tid < 64)
        rmax[tid] = fmaxf(fmaxf(red[tid], red[64 + tid]),
                          fmaxf(red[128 + tid], red[192 + tid]));
    __syncthreads();
    float mr = rmax[r];
    float sum = 0.f;
    for (int c = part; c < NK; c += 4) {
        float e = __expf(Pb[r * PSTR + c] - mr);
        Pb[r * PSTR + c] = e;
        sum += e;
    }
    red[part * 64 + r] = sum;
    __syncthreads();
    if (tid < 64)
        rinv[tid] = 1.0f / (red[tid] + red[64 + tid] + red[128 + tid] + red[192 + tid]);
    __syncthreads();
}

// P[r][c] = tf32(P[r][c] * gate[r][gi] / rowsum[r])  (ends with __syncthreads)
__device__ __forceinline__ void scale_rows(float* __restrict__ Pb,
                                           const float* __restrict__ rinv,
                                           const float* __restrict__ gts,
                                           int gi, int NK, int tid)
{
    int r = tid >> 2, part = tid & 3;
    float f = gts[r * 3 + gi] * rinv[r];
    for (int c = part; c < NK; c += 4) Pb[r * PSTR + c] = toTf32(Pb[r * PSTR + c] * f);
    __syncthreads();
}

// ---------------- fused main kernel (persistent, full tf32 mma) ----------------
__global__ void __launch_bounds__(256, 1) nsa_main(
    const float* __restrict__ q, const float* __restrict__ k, const float* __restrict__ v,
    const float* __restrict__ wgate, const float* __restrict__ bgate,
    float* __restrict__ out)
{
    extern __shared__ float sm[];
    float* Qs   = sm;                    // 64*132 fp32 Q (cmp QK + gates)
    float* QsT  = Qs   + 64 * QSTR;      // 64*132 tf32 Q (mma)
    float* KA   = QsT  + 64 * QSTR;      // 64*132 K tile (tf32) / cmpK (fp32)
    float* VA   = KA   + 64 * QSTR;      // 64*136 V tile (tf32)
    float* Pb   = VA   + 64 * VSTR;      // 64*132
    float* rinv = Pb  + 64 * PSTR;       // 64
    float* rmax = rinv + 64;             // 64
    float* red  = rmax + 64;             // 256
    float* gts  = red  + 256;            // 192
    float* Cs   = gts  + 192;            // 64
    float* Gb   = Cs   + 64;             // 64
    float* wgs  = Gb   + 64;             // 384
    float* scs  = wgs  + 384;            // 64  per-row rescale (window)
    float* fw   = scs  + 64;             // 64  per-row final window factor
    int*   topi = (int*)(fw + 64);       // 2
    unsigned int* s_item = (unsigned int*)(topi + 2);

    const int tid  = threadIdx.x;
    const int wid  = tid >> 5;
    const int lane = tid & 31;
    const int rho  = tid >> 4;   // 0..15 row group (softmax/online pass)
    const int gg   = tid & 15;   // 0..15 col group
    const int fg   = lane >> 2;  // fragment row
    const int ft   = lane & 3;   // fragment col
    const int mr   = 16 * (wid & 3);
    const int nc64 = 64 * (wid >> 2);

    for (int i = tid; i < 3 * DIMn; i += 256) wgs[i] = wgate[i];

    float4 pf[8];

    for (;;) {
        __syncthreads();
        if (tid == 0) *s_item = atomicAdd(&g_ticket, 1u);
        __syncthreads();
        unsigned int bhq = *s_item;
        if (bhq >= NITEMS) break;

        const int qb  = bhq & (NQB - 1);
        const int bh  = bhq >> 4;
        const int h   = bh & (Hn - 1);
        const int b   = bh >> 3;
        const int q0  = qb * BQ;
        const int wbase = q0 - WINR;

        const int clo_min = (128 - q0 > 0) ? (128 - q0) : 0;
        const int chi_max = (1151 - q0 < 319) ? (1151 - q0) : 319;
        const int t_lo = clo_min >> 6;
        const int t_hi = chi_max >> 6;

        // ---- load Q tile (fp32 + tf32 copies) ----
        {
            const float4* q4 = (const float4*)(q + ((size_t)(b * Sn + q0) * Hn + h) * DIMn);
            for (int idx = tid; idx < 64 * 32; idx += 256) {
                int t = idx >> 5, d4 = idx & 31;
                float4 val = q4[(size_t)t * (Hn * DIMn / 4) + d4];
                float* ds = &Qs[t * QSTR + (d4 << 2)];
                ds[0] = val.x; ds[1] = val.y; ds[2] = val.z; ds[3] = val.w;
                float* dt = &QsT[t * QSTR + (d4 << 2)];
                dt[0] = toTf32(val.x); dt[1] = toTf32(val.y);
                dt[2] = toTf32(val.z); dt[3] = toTf32(val.w);
            }
        }
        __syncthreads();

        pf_ldg_kv(pf, k, b, h, wbase + t_lo * 64, tid, true);

        // ---- gates ----
        if (tid < 192) {
            int r = tid / 3, c = tid - 3 * r;
            float a = bgate[c];
            const float* qr = &Qs[r * QSTR];
            const float* wr = &wgs[c * DIMn];
#pragma unroll 8
            for (int d = 0; d < DIMn; ++d) a += qr[d] * wr[d];
            gts[r * 3 + c] = 1.0f / (1.0f + __expf(-a));
        }
        pf_sts<QSTR, true>(pf, KA, tid);
        __syncthreads();   // KA = K_{t_lo} (tf32), gates ready

        float acc[8][4];
#pragma unroll
        for (int nt = 0; nt < 8; ++nt)
#pragma unroll
            for (int r = 0; r < 4; ++r) acc[nt][r] = 0.f;

        // ================= WINDOW branch (flash-style, full mma) =================
        {
            int clo[4], chi[4];
#pragma unroll
            for (int i = 0; i < 4; ++i) {
                int r = rho + 16 * i;
                int lo = 128 - q0;  if (lo < r) lo = r;
                int hi = 1151 - q0; if (hi > r + 256) hi = r + 256;
                clo[i] = lo; chi[i] = hi;
            }

            float m_[4], l_[4];
#pragma unroll
            for (int i = 0; i < 4; ++i) { m_[i] = NEG_INF; l_[i] = 0.f; }

#pragma unroll 1
            for (int kt = t_lo; kt <= t_hi; ++kt) {
                pf_ldg_kv(pf, v, b, h, wbase + kt * 64, tid, true);

                mma_qk_sts(QsT, KA, Pb, wid, lane, 1.0f);
                __syncthreads();   // Pb scores visible; KA free

                // online softmax (rho/gg layout); writes tf32 exp + scs
#pragma unroll
                for (int i = 0; i < 4; ++i) {
                    int r = rho + 16 * i;
                    float s[4];
#pragma unroll
                    for (int j = 0; j < 4; ++j) {
                        int cgl = kt * 64 + gg + 16 * j;
                        bool ok = (cgl >= clo[i]) && (cgl <= chi[i]);
                        s[j] = ok ? Pb[r * PSTR + gg + 16 * j] * SCALE_MUL : NEG_INF;
                    }
                    float tm = fmaxf(fmaxf(s[0], s[1]), fmaxf(s[2], s[3]));
                    tm = fmaxf(tm, __shfl_xor_sync(0xffffffffu, tm, 1));
                    tm = fmaxf(tm, __shfl_xor_sync(0xffffffffu, tm, 2));
                    tm = fmaxf(tm, __shfl_xor_sync(0xffffffffu, tm, 4));
                    tm = fmaxf(tm, __shfl_xor_sync(0xffffffffu, tm, 8));
                    float nm = fmaxf(m_[i], tm);
                    float sc = __expf(m_[i] - nm);   // ==1 when both sentinel
                    m_[i] = nm;
                    float rs = 0.f;
#pragma unroll
                    for (int j = 0; j < 4; ++j) {
                        float e = (s[j] > -1e29f) ? __expf(s[j] - nm) : 0.f;
                        s[j] = e;
                        rs += e;
                    }
                    rs += __shfl_xor_sync(0xffffffffu, rs, 1);
                    rs += __shfl_xor_sync(0xffffffffu, rs, 2);
                    rs += __shfl_xor_sync(0xffffffffu, rs, 4);
                    rs += __shfl_xor_sync(0xffffffffu, rs, 8);
                    l_[i] = l_[i] * sc + rs;
                    if (gg == 0) scs[r] = sc;
#pragma unroll
                    for (int j = 0; j < 4; ++j) Pb[r * PSTR + gg + 16 * j] = toTf32(s[j]);
                }
                pf_sts<VSTR, true>(pf, VA, tid);   // VA = V_kt (tf32)
                __syncthreads();                   // exp-Pb + scs + VA published

                if (kt < t_hi) pf_ldg_kv(pf, k, b, h, wbase + (kt + 1) * 64, tid, true);
                else           pf_ldg_cmp(pf, g_cmpK, bh, tid);

                // rescale fragments, then accumulate this tile
                {
                    float s0 = scs[mr + fg], s1 = scs[mr + fg + 8];
#pragma unroll
                    for (int nt = 0; nt < 8; ++nt) {
                        acc[nt][0] *= s0; acc[nt][1] *= s0;
                        acc[nt][2] *= s1; acc[nt][3] *= s1;
                    }
                }
                mma_pv(Pb, VA, acc, wid, lane, 0);

                if (kt < t_hi) pf_sts<QSTR, true>(pf, KA, tid);   // KA = next K (tf32)
                else           pf_sts<QSTR, false>(pf, KA, tid);  // KA = cmpK (fp32)
                __syncthreads();
            }
            // final window factor per row
            if (gg == 0) {
#pragma unroll
                for (int i = 0; i < 4; ++i) fw[rho + 16 * i] = gts[(rho + 16 * i) * 3 + 2] / l_[i];
            }
            __syncthreads();
            {
                float s0 = fw[mr + fg], s1 = fw[mr + fg + 8];
#pragma unroll
                for (int nt = 0; nt < 8; ++nt) {
                    acc[nt][0] *= s0; acc[nt][1] *= s0;
                    acc[nt][2] *= s1; acc[nt][3] *= s1;
                }
            }
        }

        // ================= CMP branch (KA = cmpK, fp32 scalar QK) =================
        gemm_qk_cmp(Qs, KA, Pb, rho, gg);
        pf_ldg_cmp(pf, g_cmpV, bh, tid);
        __syncthreads();
        softmax_rows(Pb, rmax, rinv, red, 64, tid);

        // column sums of normalized P_cmp
        {
            int col = tid & 63, part = tid >> 6;
            float s = 0.f;
            int r0 = part * 16;
#pragma unroll 4
            for (int r = r0; r < r0 + 16; ++r) s += Pb[r * PSTR + col] * rinv[r];
            red[part * 64 + col] = s;
        }
        __syncthreads();
        if (tid < 64)
            Cs[tid] = red[tid] + red[64 + tid] + red[128 + tid] + red[192 + tid];
        __syncthreads();
        if (tid < NSLC) {
            int j4 = 4 * tid;
            float g = 0.f;
            if (j4 < NCMP)                       g += Cs[j4];
            if (j4 - 1 >= 0 && j4 - 1 < NCMP)    g += 2.f * Cs[j4 - 1];
            if (j4 - 2 >= 0 && j4 - 2 < NCMP)    g += 2.f * Cs[j4 - 2];
            if (j4 - 3 >= 0 && j4 - 3 < NCMP)    g += 2.f * Cs[j4 - 3];
            if (j4 - 4 >= 0 && j4 - 4 < NCMP)    g += Cs[j4 - 4];
            Gb[tid] = g;
        }
        __syncthreads();
        if (tid < 32) {
            float a  = (tid < NSLC)      ? Gb[tid]      : NEG_INF;
            float bb = (tid + 32 < NSLC) ? Gb[tid + 32] : NEG_INF;
            float m1 = a; int i1 = tid;
            if (bb > m1) { m1 = bb; i1 = tid + 32; }
#pragma unroll
            for (int off = 16; off > 0; off >>= 1) {
                float om = __shfl_down_sync(0xffffffffu, m1, off);
                int   oi = __shfl_down_sync(0xffffffffu, i1, off);
                if (om > m1 || (om == m1 && oi < i1)) { m1 = om; i1 = oi; }
            }
            int i0 = __shfl_sync(0xffffffffu, i1, 0);
            float a2  = (tid == i0)      ? NEG_INF : a;
            float b2  = (tid + 32 == i0) ? NEG_INF : bb;
            float m2 = a2; int i2 = tid;
            if (b2 > m2) { m2 = b2; i2 = tid + 32; }
#pragma unroll
            for (int off = 16; off > 0; off >>= 1) {
                float om = __shfl_down_sync(0xffffffffu, m2, off);
                int   oi = __shfl_down_sync(0xffffffffu, i2, off);
                if (om > m2 || (om == m2 && oi < i2)) { m2 = om; i2 = oi; }
            }
            if (tid == 0) { topi[0] = i0; topi[1] = i2; }
        }
        pf_sts<VSTR, true>(pf, VA, tid);         // VA = cmpV (tf32); published by scale_rows sync
        scale_rows(Pb, rinv, gts, 0, 64, tid);   // Pb = tf32 gate0-folded P; topi visible

        int j0 = topi[0], j1 = topi[1];
        pf_ldg_kv(pf, k, b, h, j0 * 16, tid, false);
        mma_pv(Pb, VA, acc, wid, lane, 0);       // cmp PV
        __syncthreads();                         // Pb + KA free
        pf_sts<QSTR, true>(pf, KA, tid);         // KA = K_j0 (tf32)
        __syncthreads();

        // ================= SLC branch (full mma, single K/V buffer) =================
        {
            pf_ldg_kv(pf, k, b, h, j1 * 16, tid, false);
            mma_qk_sts(QsT, KA, Pb, wid, lane, SCALE_MUL);        // cols 0..63
            __syncthreads();                     // KA free
            pf_sts<QSTR, true>(pf, KA, tid);     // KA = K_j1 (tf32)
            __syncthreads();

            pf_ldg_kv(pf, v, b, h, j0 * 16, tid, false);
            mma_qk_sts(QsT, KA, Pb + 64, wid, lane, SCALE_MUL);   // cols 64..127
            pf_sts<VSTR, true>(pf, VA, tid);     // VA = V_j0 (tf32)
            __syncthreads();                     // Pb complete + VA ready

            pf_ldg_kv(pf, v, b, h, j1 * 16, tid, false);
            softmax_rows(Pb, rmax, rinv, red, 128, tid);
            scale_rows(Pb, rinv, gts, 1, 128, tid);

            mma_pv(Pb, VA, acc, wid, lane, 0);
            __syncthreads();                     // VA free
            pf_sts<VSTR, true>(pf, VA, tid);     // VA = V_j1 (tf32)
            __syncthreads();
            mma_pv(Pb, VA, acc, wid, lane, 64);
        }

        // ---- write output (fragment layout) ----
        {
            int r0 = mr + fg, r1 = mr + fg + 8;
            float* op0 = out + ((size_t)(b * Sn + q0 + r0) * Hn + h) * DIMn + nc64 + 2 * ft;
            float* op1 = out + ((size_t)(b * Sn + q0 + r1) * Hn + h) * DIMn + nc64 + 2 * ft;
#pragma unroll
            for (int nt = 0; nt < 8; ++nt) {
                *(float2*)(op0 + 8 * nt) = make_float2(acc[nt][0], acc[nt][1]);
                *(float2*)(op1 + 8 * nt) = make_float2(acc[nt][2], acc[nt][3]);
            }
        }
    }
}

// ---------------- launch ----------------
extern "C" void kernel_launch(void* const* d_in, const int* in_sizes, int n_in,
                              void* d_out, int out_size)
{
    (void)in_sizes; (void)n_in; (void)out_size;
    const float* q   = (const float*)d_in[0];
    const float* k   = (const float*)d_in[1];
    const float* v   = (const float*)d_in[2];
    const float* wck = (const float*)d_in[3];
    const float* bck = (const float*)d_in[4];
    const float* wcv = (const float*)d_in[5];
    const float* bcv = (const float*)d_in[6];
    const float* wg  = (const float*)d_in[7];
    const float* bg  = (const float*)d_in[8];
    float* out = (float*)d_out;

    int totalA = Bn * Hn * NCMP * DIMn;
    cmp_kv_kernel<<<(totalA + 255) / 256, 256>>>(k, v, wck, bck, wcv, bcv);

    size_t smem_floats = (size_t)4 * 64 * QSTR + (size_t)64 * VSTR
                       + 64 + 64 + 256 + 192 + 64 + 64 + 384 + 64 + 64 + 8;
    size_t smem_bytes = smem_floats * sizeof(float);
    cudaFuncSetAttribute(nsa_main, cudaFuncAttributeMaxDynamicSharedMemorySize,
                         (int)smem_bytes);
    nsa_main<<<152, 256, smem_bytes>>>(q, k, v, wg, bg, out);
}

// round 16
// speedup vs baseline: 2.4713x; 1.0537x over previous
#include <cuda_runtime.h>

// ---------------- problem constants ----------------
#define Bn    2
#define Sn    1024
#define Hn    8
#define DIMn  128
#define LCMP  32
#define NCMP  63          // (1024-32)/16+1
#define NSLC  61          // (1024-64)/16+1
#define BQ    64
#define NQB   (Sn / BQ)   // 16
#define NITEMS (Bn * Hn * NQB)  // 256
#define WINR  128
#define QSTR  132         // 4 mod 32: conflict-free QK mma fragments
#define VSTR  136         // 8 mod 32: conflict-free PV B fragments
#define PSTR  132
#define NEG_INF (-1e30f)
#define NTHR  384         // 8 compute warps + 4 producer warps

#define SCALE_MUL 0.08838834764831845f   // 1/sqrt(128): slc & window
#define SQRT_D    11.313708498984761f    // sqrt(128): cmp branch

typedef unsigned long long u64;

// ---------------- packed / tf32 helpers ----------------
__device__ __forceinline__ u64 FMA2(u64 a, u64 b, u64 c) {
    u64 d;
    asm("fma.rn.f32x2 %0, %1, %2, %3;" : "=l"(d) : "l"(a), "l"(b), "l"(c));
    return d;
}
__device__ __forceinline__ void UNPK(u64 a, float& x, float& y) {
    asm("mov.b64 {%0, %1}, %2;" : "=f"(x), "=f"(y) : "l"(a));
}
__device__ __forceinline__ float toTf32(float x) {
    unsigned u;
    asm("cvt.rna.tf32.f32 %0, %1;" : "=r"(u) : "f"(x));
    return __uint_as_float(u);
}

// scratch for compressed K/V: [b][h][n][d]
__device__ float g_cmpK[Bn * Hn * NCMP * DIMn];
__device__ float g_cmpV[Bn * Hn * NCMP * DIMn];
__device__ unsigned int g_ticket;

// ---------------- kernel A: compressed K/V (+ ticket reset) ----------------
__global__ void __launch_bounds__(256) cmp_kv_kernel(
    const float* __restrict__ k, const float* __restrict__ v,
    const float* __restrict__ wck, const float* __restrict__ bck,
    const float* __restrict__ wcv, const float* __restrict__ bcv)
{
    __shared__ float swk[LCMP], swv[LCMP], sb[2];
    int tid = threadIdx.x;
    if (blockIdx.x == 0 && tid == 0) g_ticket = 0u;
    if (tid < LCMP) { swk[tid] = wck[tid]; swv[tid] = wcv[tid]; }
    if (tid == 0)   { sb[0] = bck[0]; sb[1] = bcv[0]; }
    __syncthreads();

    int idx = blockIdx.x * 256 + tid;
    if (idx >= Bn * Hn * NCMP * DIMn) return;
    int d  = idx & (DIMn - 1);
    int n  = (idx >> 7) % NCMP;
    int bh = idx / (NCMP * DIMn);
    int h  = bh & (Hn - 1);
    int b  = bh >> 3;

    const float* kb = k + ((size_t)(b * Sn + n * 16) * Hn + h) * DIMn + d;
    const float* vb = v + ((size_t)(b * Sn + n * 16) * Hn + h) * DIMn + d;
    float ak = 0.f, av = 0.f;
#pragma unroll
    for (int l = 0; l < LCMP; ++l) {
        ak += kb[(size_t)l * Hn * DIMn] * swk[l];
        av += vb[(size_t)l * Hn * DIMn] * swv[l];
    }
    g_cmpK[idx] = ak + sb[0];
    g_cmpV[idx] = av + sb[1];
}

// ---------------- producer copies (128 producer threads, fused LDG->STS) ----------------
template <int STRIDE, bool TF32>
__device__ __forceinline__ void prod_copy_kv(float* __restrict__ dst,
                                             const float* __restrict__ src,
                                             int b, int h, int s_base, int ptid, bool check)
{
    int t0 = ptid >> 5, d4 = ptid & 31;
#pragma unroll 1
    for (int half = 0; half < 2; ++half) {
        float4 r[8];
#pragma unroll
        for (int i = 0; i < 8; ++i) {
            int row = t0 + 4 * (i + 8 * half);
            int srow = s_base + row;
            float4 val = make_float4(0.f, 0.f, 0.f, 0.f);
            if (!check || ((unsigned)srow < (unsigned)Sn))
                val = ((const float4*)(src + ((size_t)(b * Sn + srow) * Hn + h) * DIMn))[d4];
            r[i] = val;
        }
#pragma unroll
        for (int i = 0; i < 8; ++i) {
            int row = t0 + 4 * (i + 8 * half);
            float* ds = &dst[row * STRIDE + (d4 << 2)];
            if (TF32) {
                *(float2*)(ds)     = make_float2(toTf32(r[i].x), toTf32(r[i].y));
                *(float2*)(ds + 2) = make_float2(toTf32(r[i].z), toTf32(r[i].w));
            } else {
                *(float2*)(ds)     = make_float2(r[i].x, r[i].y);
                *(float2*)(ds + 2) = make_float2(r[i].z, r[i].w);
            }
        }
    }
}
template <int STRIDE, bool TF32>
__device__ __forceinline__ void prod_copy_cmp(float* __restrict__ dst,
                                              const float* __restrict__ src,
                                              int bh, int ptid)
{
    int t0 = ptid >> 5, d4 = ptid & 31;
#pragma unroll 1
    for (int half = 0; half < 2; ++half) {
        float4 r[8];
#pragma unroll
        for (int i = 0; i < 8; ++i) {
            int t = t0 + 4 * (i + 8 * half);
            float4 val = make_float4(0.f, 0.f, 0.f, 0.f);
            if (t < NCMP)
                val = ((const float4*)(src + ((size_t)bh * NCMP + t) * DIMn))[d4];
            r[i] = val;
        }
#pragma unroll
        for (int i = 0; i < 8; ++i) {
            int t = t0 + 4 * (i + 8 * half);
            float* ds = &dst[t * STRIDE + (d4 << 2)];
            if (TF32) {
                *(float2*)(ds)     = make_float2(toTf32(r[i].x), toTf32(r[i].y));
                *(float2*)(ds + 2) = make_float2(toTf32(r[i].z), toTf32(r[i].w));
            } else {
                *(float2*)(ds)     = make_float2(r[i].x, r[i].y);
                *(float2*)(ds + 2) = make_float2(r[i].z, r[i].w);
            }
        }
    }
}

// ---------------- tf32 mma QK: 64x64 tile, 8 compute warps (4M x 2N) ----------------
__device__ __forceinline__ void mma_qk_sts(const float* __restrict__ QsT,
                                           const float* __restrict__ Ks,
                                           float* __restrict__ Pbase,
                                           int wid, int lane, float scl)
{
    const int g = lane >> 2, t = lane & 3;
    const int mr = 16 * (wid & 3);
    const int nc = 32 * (wid >> 2);

    float c[4][4];
#pragma unroll
    for (int nt = 0; nt < 4; ++nt)
#pragma unroll
        for (int r = 0; r < 4; ++r) c[nt][r] = 0.f;

    const float* a0p = QsT + (mr + g) * QSTR + t;
    const float* a1p = a0p + 8 * QSTR;
    const float* bbp = Ks + (nc + g) * QSTR + t;

#pragma unroll
    for (int ks = 0; ks < 16; ++ks) {
        int kb = 8 * ks;
        unsigned ua0 = __float_as_uint(a0p[kb]);
        unsigned ua1 = __float_as_uint(a1p[kb]);
        unsigned ua2 = __float_as_uint(a0p[kb + 4]);
        unsigned ua3 = __float_as_uint(a1p[kb + 4]);
#pragma unroll
        for (int nt = 0; nt < 4; ++nt) {
            const float* bp = bbp + nt * 8 * QSTR + kb;
            unsigned ub0 = __float_as_uint(bp[0]);
            unsigned ub1 = __float_as_uint(bp[4]);
            asm volatile(
                "mma.sync.aligned.m16n8k8.row.col.f32.tf32.tf32.f32 "
                "{%0,%1,%2,%3}, {%4,%5,%6,%7}, {%8,%9}, {%0,%1,%2,%3};"
                : "+f"(c[nt][0]), "+f"(c[nt][1]), "+f"(c[nt][2]), "+f"(c[nt][3])
                : "r"(ua0), "r"(ua1), "r"(ua2), "r"(ua3), "r"(ub0), "r"(ub1));
        }
    }
    float* p0 = Pbase + (mr + g) * PSTR + nc + 2 * t;
    float* p1 = p0 + 8 * PSTR;
#pragma unroll
    for (int nt = 0; nt < 4; ++nt) {
        *(float2*)(p0 + 8 * nt) = make_float2(c[nt][0] * scl, c[nt][1] * scl);
        *(float2*)(p1 + 8 * nt) = make_float2(c[nt][2] * scl, c[nt][3] * scl);
    }
}

// ---------------- tf32 mma PV: acc[8][4] += P(64x64 @cb) * V(64x128) ----------------
__device__ __forceinline__ void mma_pv(const float* __restrict__ Pb,
                                       const float* __restrict__ Vs,
                                       float c[8][4], int wid, int lane, int cb)
{
    const int g = lane >> 2, t = lane & 3;
    const int mr = 16 * (wid & 3);
    const int nc = 64 * (wid >> 2);
    const float* ap = Pb + (mr + g) * PSTR + cb + t;
    const float* bp = Vs + t * VSTR + nc + g;
#pragma unroll
    for (int ks = 0; ks < 8; ++ks) {
        int kb = 8 * ks;
        unsigned ua0 = __float_as_uint(ap[kb]);
        unsigned ua1 = __float_as_uint(ap[8 * PSTR + kb]);
        unsigned ua2 = __float_as_uint(ap[kb + 4]);
        unsigned ua3 = __float_as_uint(ap[8 * PSTR + kb + 4]);
        const float* bk = bp + kb * VSTR;
#pragma unroll
        for (int nt = 0; nt < 8; ++nt) {
            unsigned ub0 = __float_as_uint(bk[8 * nt]);
            unsigned ub1 = __float_as_uint(bk[4 * VSTR + 8 * nt]);
            asm volatile(
                "mma.sync.aligned.m16n8k8.row.col.f32.tf32.tf32.f32 "
                "{%0,%1,%2,%3}, {%4,%5,%6,%7}, {%8,%9}, {%0,%1,%2,%3};"
                : "+f"(c[nt][0]), "+f"(c[nt][1]), "+f"(c[nt][2]), "+f"(c[nt][3])
                : "r"(ua0), "r"(ua1), "r"(ua2), "r"(ua3), "r"(ub0), "r"(ub1));
        }
    }
}

// ---------------- scalar QK (cmp branch only, fp32) ----------------
__device__ __forceinline__ void gemm_qk_cmp(const float* __restrict__ Qs,
                                            const float* __restrict__ Ks,
                                            float* __restrict__ Pb,
                                            int rho, int gg)
{
    u64 s2[4][4];
#pragma unroll
    for (int i = 0; i < 4; ++i)
#pragma unroll
        for (int j = 0; j < 4; ++j) s2[i][j] = 0ULL;

    const u64* qp = (const u64*)(Qs + rho * QSTR);
    const u64* kp = (const u64*)(Ks + gg  * QSTR);
    const int RS = 8 * QSTR;
#pragma unroll 4
    for (int kd = 0; kd < DIMn / 2; ++kd) {
        u64 a0 = qp[kd];
        u64 a1 = qp[RS + kd];
        u64 a2 = qp[2 * RS + kd];
        u64 a3 = qp[3 * RS + kd];
        u64 b0 = kp[kd];
        u64 b1 = kp[RS + kd];
        u64 b2 = kp[2 * RS + kd];
        u64 b3 = kp[3 * RS + kd];
        s2[0][0] = FMA2(a0, b0, s2[0][0]); s2[0][1] = FMA2(a0, b1, s2[0][1]);
        s2[0][2] = FMA2(a0, b2, s2[0][2]); s2[0][3] = FMA2(a0, b3, s2[0][3]);
        s2[1][0] = FMA2(a1, b0, s2[1][0]); s2[1][1] = FMA2(a1, b1, s2[1][1]);
        s2[1][2] = FMA2(a1, b2, s2[1][2]); s2[1][3] = FMA2(a1, b3, s2[1][3]);
        s2[2][0] = FMA2(a2, b0, s2[2][0]); s2[2][1] = FMA2(a2, b1, s2[2][1]);
        s2[2][2] = FMA2(a2, b2, s2[2][2]); s2[2][3] = FMA2(a2, b3, s2[2][3]);
        s2[3][0] = FMA2(a3, b0, s2[3][0]); s2[3][1] = FMA2(a3, b1, s2[3][1]);
        s2[3][2] = FMA2(a3, b2, s2[3][2]); s2[3][3] = FMA2(a3, b3, s2[3][3]);
    }
#pragma unroll
    for (int i = 0; i < 4; ++i) {
        int r = rho + 16 * i;
#pragma unroll
        for (int j = 0; j < 4; ++j) {
            int cc = gg + 16 * j;
            float x, y; UNPK(s2[i][j], x, y);
            float val = (x + y) * SQRT_D;
            if (cc >= NCMP) val = NEG_INF;
            Pb[r * PSTR + cc] = val;
        }
    }
}

// two-pass row softmax over Pb[:, 0:NK]; fp32 exp in Pb, 1/rowsum in rinv.
// ALL NTHR threads must call (uniform barriers); work guarded to tid<256.
__device__ __forceinline__ void softmax_rows(float* __restrict__ Pb,
                                             float* __restrict__ rmax,
                                             float* __restrict__ rinv,
                                             float* __restrict__ red,
                                             int NK, int tid)
{
    int r = tid >> 2, part = tid & 3;
    bool act = tid < 256;
    if (act) {
        float m = NEG_INF;
        for (int c = part; c < NK; c += 4) m = fmaxf(m, Pb[r * PSTR + c]);
        red[part * 64 + r] = m;
    }
    __syncthreads();
    if (tid < 64)
        rmax[tid] = fmaxf(fmaxf(red[tid], red[64 + tid]),
                          fmaxf(red[128 + tid], red[192 + tid]));
    __syncthreads();
    if (act) {
        float mr = rmax[r];
        float sum = 0.f;
        for (int c = part; c < NK; c += 4) {
            float e = __expf(Pb[r * PSTR + c] - mr);
            Pb[r * PSTR + c] = e;
            sum += e;
        }
        red[part * 64 + r] = sum;
    }
    __syncthreads();
    if (tid < 64)
        rinv[tid] = 1.0f / (red[tid] + red[64 + tid] + red[128 + tid] + red[192 + tid]);
    __syncthreads();
}

// P[r][c] = tf32(P[r][c] * gate[r][gi] / rowsum[r])  (uniform; trailing sync)
__device__ __forceinline__ void scale_rows(float* __restrict__ Pb,
                                           const float* __restrict__ rinv,
                                           const float* __restrict__ gts,
                                           int gi, int NK, int tid)
{
    if (tid < 256) {
        int r = tid >> 2, part = tid & 3;
        float f = gts[r * 3 + gi] * rinv[r];
        for (int c = part; c < NK; c += 4) Pb[r * PSTR + c] = toTf32(Pb[r * PSTR + c] * f);
    }
    __syncthreads();
}

// ---------------- fused main kernel (persistent, warp-specialized) ----------------
__global__ void __launch_bounds__(NTHR, 1) nsa_main(
    const float* __restrict__ q, const float* __restrict__ k, const float* __restrict__ v,
    const float* __restrict__ wgate, const float* __restrict__ bgate,
    float* __restrict__ out)
{
    extern __shared__ float sm[];
    float* Qs   = sm;                    // 64*132 fp32 Q (cmp QK + gates)
    float* QsT  = Qs   + 64 * QSTR;      // 64*132 tf32 Q (mma)
    float* KA   = QsT  + 64 * QSTR;      // 64*136 buffer A (K@132 / V@136)
    float* VA   = KA   + 64 * VSTR;      // 64*136 buffer B
    float* Pb   = VA   + 64 * VSTR;      // 64*132
    float* rinv = Pb  + 64 * PSTR;       // 64
    float* rmax = rinv + 64;             // 64
    float* red  = rmax + 64;             // 256
    float* gts  = red  + 256;            // 192
    float* Cs   = gts  + 192;            // 64
    float* Gb   = Cs   + 64;             // 64
    float* wgs  = Gb   + 64;             // 384
    float* scs  = wgs  + 384;            // 64
    float* fw   = scs  + 64;             // 64
    int*   topi = (int*)(fw + 64);       // 2
    unsigned int* s_item = (unsigned int*)(topi + 2);

    const int tid  = threadIdx.x;
    const int wid  = tid >> 5;
    const int lane = tid & 31;
    const bool comp = (wid < 8);
    const int ptid = tid - 256;          // producer thread id (valid when !comp)
    const int rho  = tid >> 4;           // softmax row group (compute only)
    const int gg   = tid & 15;
    const int fg   = lane >> 2;
    const int ft   = lane & 3;
    const int mr   = 16 * (wid & 3);
    const int nc64 = 64 * (wid >> 2);

    for (int i = tid; i < 3 * DIMn; i += NTHR) wgs[i] = wgate[i];

    for (;;) {
        __syncthreads();
        if (tid == 0) *s_item = atomicAdd(&g_ticket, 1u);
        __syncthreads();
        unsigned int bhq = *s_item;
        if (bhq >= NITEMS) break;

        const int qb  = bhq & (NQB - 1);
        const int bh  = bhq >> 4;
        const int h   = bh & (Hn - 1);
        const int b   = bh >> 3;
        const int q0  = qb * BQ;
        const int wbase = q0 - WINR;

        const int clo_min = (128 - q0 > 0) ? (128 - q0) : 0;
        const int chi_max = (1151 - q0 < 319) ? (1151 - q0) : 319;
        const int t_lo = clo_min >> 6;
        const int t_hi = chi_max >> 6;

        // ---- phase 0: Q load (all threads) ----
        {
            const float4* q4 = (const float4*)(q + ((size_t)(b * Sn + q0) * Hn + h) * DIMn);
            for (int idx = tid; idx < 64 * 32; idx += NTHR) {
                int t = idx >> 5, d4 = idx & 31;
                float4 val = q4[(size_t)t * (Hn * DIMn / 4) + d4];
                float* ds = &Qs[t * QSTR + (d4 << 2)];
                ds[0] = val.x; ds[1] = val.y; ds[2] = val.z; ds[3] = val.w;
                float* dt = &QsT[t * QSTR + (d4 << 2)];
                dt[0] = toTf32(val.x); dt[1] = toTf32(val.y);
                dt[2] = toTf32(val.z); dt[3] = toTf32(val.w);
            }
        }
        __syncthreads();

        // ---- phase 1: gates (compute) || copy K_tlo -> KA (producers) ----
        if (comp) {
            if (tid < 192) {
                int r = tid / 3, c = tid - 3 * r;
                float a = bgate[c];
                const float* qr = &Qs[r * QSTR];
                const float* wr = &wgs[c * DIMn];
#pragma unroll 8
                for (int d = 0; d < DIMn; ++d) a += qr[d] * wr[d];
                gts[r * 3 + c] = 1.0f / (1.0f + __expf(-a));
            }
        } else {
            prod_copy_kv<QSTR, true>(KA, k, b, h, wbase + t_lo * 64, ptid, true);
        }
        __syncthreads();

        float acc[8][4];
#pragma unroll
        for (int nt = 0; nt < 8; ++nt)
#pragma unroll
            for (int r = 0; r < 4; ++r) acc[nt][r] = 0.f;

        // ================= WINDOW branch =================
        int clo[4], chi[4];
#pragma unroll
        for (int i = 0; i < 4; ++i) {
            int r = rho + 16 * i;
            int lo = 128 - q0;  if (lo < r) lo = r;
            int hi = 1151 - q0; if (hi > r + 256) hi = r + 256;
            clo[i] = lo; chi[i] = hi;
        }
        float m_[4], l_[4];
#pragma unroll
        for (int i = 0; i < 4; ++i) { m_[i] = NEG_INF; l_[i] = 0.f; }

#pragma unroll 1
        for (int kt = t_lo; kt <= t_hi; ++kt) {
            // QK (compute) || copy V_kt -> VA (producers)
            if (comp) mma_qk_sts(QsT, KA, Pb, wid, lane, 1.0f);
            else      prod_copy_kv<VSTR, true>(VA, v, b, h, wbase + kt * 64, ptid, true);
            __syncthreads();

            // online softmax (compute) || copy next K / cmpK -> KA (producers)
            if (comp) {
#pragma unroll
                for (int i = 0; i < 4; ++i) {
                    int r = rho + 16 * i;
                    float s[4];
#pragma unroll
                    for (int j = 0; j < 4; ++j) {
                        int cgl = kt * 64 + gg + 16 * j;
                        bool ok = (cgl >= clo[i]) && (cgl <= chi[i]);
                        s[j] = ok ? Pb[r * PSTR + gg + 16 * j] * SCALE_MUL : NEG_INF;
                    }
                    float tm = fmaxf(fmaxf(s[0], s[1]), fmaxf(s[2], s[3]));
                    tm = fmaxf(tm, __shfl_xor_sync(0xffffffffu, tm, 1));
                    tm = fmaxf(tm, __shfl_xor_sync(0xffffffffu, tm, 2));
                    tm = fmaxf(tm, __shfl_xor_sync(0xffffffffu, tm, 4));
                    tm = fmaxf(tm, __shfl_xor_sync(0xffffffffu, tm, 8));
                    float nm = fmaxf(m_[i], tm);
                    float sc = __expf(m_[i] - nm);
                    m_[i] = nm;
                    float rs = 0.f;
#pragma unroll
                    for (int j = 0; j < 4; ++j) {
                        float e = (s[j] > -1e29f) ? __expf(s[j] - nm) : 0.f;
                        s[j] = e;
                        rs += e;
                    }
                    rs += __shfl_xor_sync(0xffffffffu, rs, 1);
                    rs += __shfl_xor_sync(0xffffffffu, rs, 2);
                    rs += __shfl_xor_sync(0xffffffffu, rs, 4);
                    rs += __shfl_xor_sync(0xffffffffu, rs, 8);
                    l_[i] = l_[i] * sc + rs;
                    if (gg == 0) scs[r] = sc;
#pragma unroll
                    for (int j = 0; j < 4; ++j) Pb[r * PSTR + gg + 16 * j] = toTf32(s[j]);
                }
            } else {
                if (kt < t_hi) prod_copy_kv<QSTR, true>(KA, k, b, h, wbase + (kt + 1) * 64, ptid, true);
                else           prod_copy_cmp<QSTR, false>(KA, g_cmpK, bh, ptid);
            }
            __syncthreads();

            // PV (compute) || producers idle
            if (comp) {
                float s0 = scs[mr + fg], s1 = scs[mr + fg + 8];
#pragma unroll
                for (int nt = 0; nt < 8; ++nt) {
                    acc[nt][0] *= s0; acc[nt][1] *= s0;
                    acc[nt][2] *= s1; acc[nt][3] *= s1;
                }
                mma_pv(Pb, VA, acc, wid, lane, 0);
            }
            __syncthreads();
        }
        // finalize window factor
        if (comp && gg == 0) {
#pragma unroll
            for (int i = 0; i < 4; ++i) fw[rho + 16 * i] = gts[(rho + 16 * i) * 3 + 2] / l_[i];
        }
        __syncthreads();

        // ================= CMP branch =================
        // cmp QK (compute, fp32 scalar; also applies window finalize to acc) || copy cmpV -> VA
        if (comp) {
            float s0 = fw[mr + fg], s1 = fw[mr + fg + 8];
#pragma unroll
            for (int nt = 0; nt < 8; ++nt) {
                acc[nt][0] *= s0; acc[nt][1] *= s0;
                acc[nt][2] *= s1; acc[nt][3] *= s1;
            }
            gemm_qk_cmp(Qs, KA, Pb, rho, gg);
        } else {
            prod_copy_cmp<VSTR, true>(VA, g_cmpV, bh, ptid);
        }
        __syncthreads();

        softmax_rows(Pb, rmax, rinv, red, 64, tid);

        // column sums of normalized P_cmp
        if (tid < 256) {
            int col = tid & 63, part = tid >> 6;
            float s = 0.f;
            int r0 = part * 16;
#pragma unroll 4
            for (int r = r0; r < r0 + 16; ++r) s += Pb[r * PSTR + col] * rinv[r];
            red[part * 64 + col] = s;
        }
        __syncthreads();
        if (tid < 64)
            Cs[tid] = red[tid] + red[64 + tid] + red[128 + tid] + red[192 + tid];
        __syncthreads();
        if (tid < NSLC) {
            int j4 = 4 * tid;
            float g = 0.f;
            if (j4 < NCMP)                       g += Cs[j4];
            if (j4 - 1 >= 0 && j4 - 1 < NCMP)    g += 2.f * Cs[j4 - 1];
            if (j4 - 2 >= 0 && j4 - 2 < NCMP)    g += 2.f * Cs[j4 - 2];
            if (j4 - 3 >= 0 && j4 - 3 < NCMP)    g += 2.f * Cs[j4 - 3];
            if (j4 - 4 >= 0 && j4 - 4 < NCMP)    g += Cs[j4 - 4];
            Gb[tid] = g;
        }
        __syncthreads();
        if (tid < 32) {
            float a  = (tid < NSLC)      ? Gb[tid]      : NEG_INF;
            float bb = (tid + 32 < NSLC) ? Gb[tid + 32] : NEG_INF;
            float m1 = a; int i1 = tid;
            if (bb > m1) { m1 = bb; i1 = tid + 32; }
#pragma unroll
            for (int off = 16; off > 0; off >>= 1) {
                float om = __shfl_down_sync(0xffffffffu, m1, off);
                int   oi = __shfl_down_sync(0xffffffffu, i1, off);
                if (om > m1 || (om == m1 && oi < i1)) { m1 = om; i1 = oi; }
            }
            int i0 = __shfl_sync(0xffffffffu, i1, 0);
            float a2  = (tid == i0)      ? NEG_INF : a;
            float b2  = (tid + 32 == i0) ? NEG_INF : bb;
            float m2 = a2; int i2 = tid;
            if (b2 > m2) { m2 = b2; i2 = tid + 32; }
#pragma unroll
            for (int off = 16; off > 0; off >>= 1) {
                float om = __shfl_down_sync(0xffffffffu, m2, off);
                int   oi = __shfl_down_sync(0xffffffffu, i2, off);
                if (om > m2 || (om == m2 && oi < i2)) { m2 = om; i2 = oi; }
            }
            if (tid == 0) { topi[0] = i0; topi[1] = i2; }
        }
        scale_rows(Pb, rinv, gts, 0, 64, tid);   // trailing sync -> topi visible

        // cmp PV (compute) || copy K_j0 -> KA (producers)
        if (comp) mma_pv(Pb, VA, acc, wid, lane, 0);
        else      prod_copy_kv<QSTR, true>(KA, k, b, h, topi[0] * 16, ptid, false);
        __syncthreads();

        // ================= SLC branch =================
        // slc A: QK j0 -> Pb[0:64] || copy K_j1 -> VA (as K layout)
        if (comp) mma_qk_sts(QsT, KA, Pb, wid, lane, SCALE_MUL);
        else      prod_copy_kv<QSTR, true>(VA, k, b, h, topi[1] * 16, ptid, false);
        __syncthreads();

        // slc B: QK j1 (from VA) -> Pb[64:128] || copy V_j0 -> KA (as V layout)
        if (comp) mma_qk_sts(QsT, VA, Pb + 64, wid, lane, SCALE_MUL);
        else      prod_copy_kv<VSTR, true>(KA, v, b, h, topi[0] * 16, ptid, false);
        __syncthreads();

        // slc C: softmax + gate1 scale (compute) || copy V_j1 -> VA
        if (!comp) prod_copy_kv<VSTR, true>(VA, v, b, h, topi[1] * 16, ptid, false);
        softmax_rows(Pb, rmax, rinv, red, 128, tid);
        scale_rows(Pb, rinv, gts, 1, 128, tid);   // trailing sync -> VA published

        // slc D: both PVs + output (compute)
        if (comp) {
            mma_pv(Pb, KA, acc, wid, lane, 0);    // V_j0 (VSTR layout in KA buffer)
            mma_pv(Pb, VA, acc, wid, lane, 64);   // V_j1

            int r0 = mr + fg, r1 = mr + fg + 8;
            float* op0 = out + ((size_t)(b * Sn + q0 + r0) * Hn + h) * DIMn + nc64 + 2 * ft;
            float* op1 = out + ((size_t)(b * Sn + q0 + r1) * Hn + h) * DIMn + nc64 + 2 * ft;
#pragma unroll
            for (int nt = 0; nt < 8; ++nt) {
                *(float2*)(op0 + 8 * nt) = make_float2(acc[nt][0], acc[nt][1]);
                *(float2*)(op1 + 8 * nt) = make_float2(acc[nt][2], acc[nt][3]);
            }
        }
    }
}

// ---------------- launch ----------------
extern "C" void kernel_launch(void* const* d_in, const int* in_sizes, int n_in,
                              void* d_out, int out_size)
{
    (void)in_sizes; (void)n_in; (void)out_size;
    const float* q   = (const float*)d_in[0];
    const float* k   = (const float*)d_in[1];
    const float* v   = (const float*)d_in[2];
    const float* wck = (const float*)d_in[3];
    const float* bck = (const float*)d_in[4];
    const float* wcv = (const float*)d_in[5];
    const float* bcv = (const float*)d_in[6];
    const float* wg  = (const float*)d_in[7];
    const float* bg  = (const float*)d_in[8];
    float* out = (float*)d_out;

    int totalA = Bn * Hn * NCMP * DIMn;
    cmp_kv_kernel<<<(totalA + 255) / 256, 256>>>(k, v, wck, bck, wcv, bcv);

    size_t smem_floats = (size_t)2 * 64 * QSTR + (size_t)2 * 64 * VSTR + (size_t)64 * PSTR
                       + 64 + 64 + 256 + 192 + 64 + 64 + 384 + 64 + 64 + 8;
    size_t smem_bytes = smem_floats * sizeof(float);
    cudaFuncSetAttribute(nsa_main, cudaFuncAttributeMaxDynamicSharedMemorySize,
                         (int)smem_bytes);
    nsa_main<<<152, NTHR, smem_bytes>>>(q, k, v, wg, bg, out);
}

// round 17
// speedup vs baseline: 2.5966x; 1.0507x over previous
#include <cuda_runtime.h>

// ---------------- problem constants ----------------
#define Bn    2
#define Sn    1024
#define Hn    8
#define DIMn  128
#define LCMP  32
#define NCMP  63          // (1024-32)/16+1
#define NSLC  61          // (1024-64)/16+1
#define BQ    64
#define NQB   (Sn / BQ)   // 16
#define NITEMS (Bn * Hn * NQB)  // 256
#define WINR  128
#define QSTR  132         // 4 mod 32: conflict-free QK mma fragments
#define VSTR  136         // 8 mod 32: conflict-free PV B fragments
#define PSTR  132
#define NEG_INF (-1e30f)
#define NTHR  384         // 8 compute warps + 4 producer warps

#define SCALE_MUL 0.08838834764831845f   // 1/sqrt(128): slc & window
#define SQRT_D    11.313708498984761f    // sqrt(128): cmp branch

typedef unsigned long long u64;

// ---------------- packed / tf32 helpers ----------------
__device__ __forceinline__ u64 FMA2(u64 a, u64 b, u64 c) {
    u64 d;
    asm("fma.rn.f32x2 %0, %1, %2, %3;" : "=l"(d) : "l"(a), "l"(b), "l"(c));
    return d;
}
__device__ __forceinline__ void UNPK(u64 a, float& x, float& y) {
    asm("mov.b64 {%0, %1}, %2;" : "=f"(x), "=f"(y) : "l"(a));
}
__device__ __forceinline__ float toTf32(float x) {
    unsigned u;
    asm("cvt.rna.tf32.f32 %0, %1;" : "=r"(u) : "f"(x));
    return __uint_as_float(u);
}

// scratch for compressed K/V: [b][h][n][d]
__device__ float g_cmpK[Bn * Hn * NCMP * DIMn];
__device__ float g_cmpV[Bn * Hn * NCMP * DIMn];
__device__ unsigned int g_ticket;

// ---------------- kernel A: compressed K/V (+ ticket reset) ----------------
__global__ void __launch_bounds__(256) cmp_kv_kernel(
    const float* __restrict__ k, const float* __restrict__ v,
    const float* __restrict__ wck, const float* __restrict__ bck,
    const float* __restrict__ wcv, const float* __restrict__ bcv)
{
    __shared__ float swk[LCMP], swv[LCMP], sb[2];
    int tid = threadIdx.x;
    if (blockIdx.x == 0 && tid == 0) g_ticket = 0u;
    if (tid < LCMP) { swk[tid] = wck[tid]; swv[tid] = wcv[tid]; }
    if (tid == 0)   { sb[0] = bck[0]; sb[1] = bcv[0]; }
    __syncthreads();

    int idx = blockIdx.x * 256 + tid;
    if (idx >= Bn * Hn * NCMP * DIMn) return;
    int d  = idx & (DIMn - 1);
    int n  = (idx >> 7) % NCMP;
    int bh = idx / (NCMP * DIMn);
    int h  = bh & (Hn - 1);
    int b  = bh >> 3;

    const float* kb = k + ((size_t)(b * Sn + n * 16) * Hn + h) * DIMn + d;
    const float* vb = v + ((size_t)(b * Sn + n * 16) * Hn + h) * DIMn + d;
    float ak = 0.f, av = 0.f;
#pragma unroll
    for (int l = 0; l < LCMP; ++l) {
        ak += kb[(size_t)l * Hn * DIMn] * swk[l];
        av += vb[(size_t)l * Hn * DIMn] * swv[l];
    }
    g_cmpK[idx] = ak + sb[0];
    g_cmpV[idx] = av + sb[1];
}

// ---------------- tile copies (NT threads, fused LDG->STS, batched by 8) ----------------
template <int STRIDE, bool TF32, int NT>
__device__ __forceinline__ void copy_kv_n(float* __restrict__ dst,
                                          const float* __restrict__ src,
                                          int b, int h, int s_base, int id, bool check)
{
    const int RG = NT / 32;     // row groups per pass
    const int R  = 64 / RG;     // float4 rows per thread
    int t0 = id >> 5, d4 = id & 31;
#pragma unroll 1
    for (int base = 0; base < R; base += 8) {
        float4 r[8];
#pragma unroll
        for (int i = 0; i < 8; ++i) {
            int row = t0 + RG * (base + i);
            int srow = s_base + row;
            float4 val = make_float4(0.f, 0.f, 0.f, 0.f);
            if (!check || ((unsigned)srow < (unsigned)Sn))
                val = ((const float4*)(src + ((size_t)(b * Sn + srow) * Hn + h) * DIMn))[d4];
            r[i] = val;
        }
#pragma unroll
        for (int i = 0; i < 8; ++i) {
            int row = t0 + RG * (base + i);
            float* ds = &dst[row * STRIDE + (d4 << 2)];
            if (TF32) {
                *(float2*)(ds)     = make_float2(toTf32(r[i].x), toTf32(r[i].y));
                *(float2*)(ds + 2) = make_float2(toTf32(r[i].z), toTf32(r[i].w));
            } else {
                *(float2*)(ds)     = make_float2(r[i].x, r[i].y);
                *(float2*)(ds + 2) = make_float2(r[i].z, r[i].w);
            }
        }
    }
}
template <int STRIDE, bool TF32, int NT>
__device__ __forceinline__ void copy_cmp_n(float* __restrict__ dst,
                                           const float* __restrict__ src,
                                           int bh, int id)
{
    const int RG = NT / 32;
    const int R  = 64 / RG;
    int t0 = id >> 5, d4 = id & 31;
#pragma unroll 1
    for (int base = 0; base < R; base += 8) {
        float4 r[8];
#pragma unroll
        for (int i = 0; i < 8; ++i) {
            int t = t0 + RG * (base + i);
            float4 val = make_float4(0.f, 0.f, 0.f, 0.f);
            if (t < NCMP)
                val = ((const float4*)(src + ((size_t)bh * NCMP + t) * DIMn))[d4];
            r[i] = val;
        }
#pragma unroll
        for (int i = 0; i < 8; ++i) {
            int t = t0 + RG * (base + i);
            float* ds = &dst[t * STRIDE + (d4 << 2)];
            if (TF32) {
                *(float2*)(ds)     = make_float2(toTf32(r[i].x), toTf32(r[i].y));
                *(float2*)(ds + 2) = make_float2(toTf32(r[i].z), toTf32(r[i].w));
            } else {
                *(float2*)(ds)     = make_float2(r[i].x, r[i].y);
                *(float2*)(ds + 2) = make_float2(r[i].z, r[i].w);
            }
        }
    }
}

// ---------------- tf32 mma QK: 64x64 tile, 4 warps with 32x32 warp tiles ----------------
// wid 0..3: quadrant rows 32*(wid&1), cols 32*(wid>>1)
__device__ __forceinline__ void mma_qk_sts32(const float* __restrict__ QsT,
                                             const float* __restrict__ Ks,
                                             float* __restrict__ Pbase,
                                             int wid, int lane, float scl)
{
    const int g = lane >> 2, t = lane & 3;
    const int qr = 32 * (wid & 1);
    const int qc = 32 * (wid >> 1);

    float c[2][4][4];
#pragma unroll
    for (int i = 0; i < 2; ++i)
#pragma unroll
        for (int nt = 0; nt < 4; ++nt)
#pragma unroll
            for (int r = 0; r < 4; ++r) c[i][nt][r] = 0.f;

    const float* a0p = QsT + (qr + g) * QSTR + t;
    const float* bbp = Ks + (qc + g) * QSTR + t;

#pragma unroll
    for (int ks = 0; ks < 16; ++ks) {
        int kb = 8 * ks;
        unsigned ua[2][4];
#pragma unroll
        for (int i = 0; i < 2; ++i) {
            const float* ap = a0p + 16 * i * QSTR;
            ua[i][0] = __float_as_uint(ap[kb]);
            ua[i][1] = __float_as_uint(ap[8 * QSTR + kb]);
            ua[i][2] = __float_as_uint(ap[kb + 4]);
            ua[i][3] = __float_as_uint(ap[8 * QSTR + kb + 4]);
        }
#pragma unroll
        for (int nt = 0; nt < 4; ++nt) {
            const float* bp = bbp + nt * 8 * QSTR + kb;
            unsigned ub0 = __float_as_uint(bp[0]);
            unsigned ub1 = __float_as_uint(bp[4]);
#pragma unroll
            for (int i = 0; i < 2; ++i) {
                asm volatile(
                    "mma.sync.aligned.m16n8k8.row.col.f32.tf32.tf32.f32 "
                    "{%0,%1,%2,%3}, {%4,%5,%6,%7}, {%8,%9}, {%0,%1,%2,%3};"
                    : "+f"(c[i][nt][0]), "+f"(c[i][nt][1]), "+f"(c[i][nt][2]), "+f"(c[i][nt][3])
                    : "r"(ua[i][0]), "r"(ua[i][1]), "r"(ua[i][2]), "r"(ua[i][3]),
                      "r"(ub0), "r"(ub1));
            }
        }
    }
#pragma unroll
    for (int i = 0; i < 2; ++i) {
        float* p0 = Pbase + (qr + 16 * i + g) * PSTR + qc + 2 * t;
        float* p1 = p0 + 8 * PSTR;
#pragma unroll
        for (int nt = 0; nt < 4; ++nt) {
            *(float2*)(p0 + 8 * nt) = make_float2(c[i][nt][0] * scl, c[i][nt][1] * scl);
            *(float2*)(p1 + 8 * nt) = make_float2(c[i][nt][2] * scl, c[i][nt][3] * scl);
        }
    }
}

// ---------------- tf32 mma PV: 8 warps, 32x32 warp tiles over 64x128 ----------------
// wid 0..7: rows 32*(wid&1), cols 32*(wid>>1)
__device__ __forceinline__ void mma_pv32(const float* __restrict__ Pb,
                                         const float* __restrict__ Vs,
                                         float c[2][4][4], int wid, int lane, int cb)
{
    const int g = lane >> 2, t = lane & 3;
    const int pr = 32 * (wid & 1);
    const int pc = 32 * (wid >> 1);
    const float* ap0 = Pb + (pr + g) * PSTR + cb + t;
    const float* bp = Vs + t * VSTR + pc + g;
#pragma unroll
    for (int ks = 0; ks < 8; ++ks) {
        int kb = 8 * ks;
        unsigned ua[2][4];
#pragma unroll
        for (int i = 0; i < 2; ++i) {
            const float* ap = ap0 + 16 * i * PSTR;
            ua[i][0] = __float_as_uint(ap[kb]);
            ua[i][1] = __float_as_uint(ap[8 * PSTR + kb]);
            ua[i][2] = __float_as_uint(ap[kb + 4]);
            ua[i][3] = __float_as_uint(ap[8 * PSTR + kb + 4]);
        }
        const float* bk = bp + kb * VSTR;
#pragma unroll
        for (int nt = 0; nt < 4; ++nt) {
            unsigned ub0 = __float_as_uint(bk[8 * nt]);
            unsigned ub1 = __float_as_uint(bk[4 * VSTR + 8 * nt]);
#pragma unroll
            for (int i = 0; i < 2; ++i) {
                asm volatile(
                    "mma.sync.aligned.m16n8k8.row.col.f32.tf32.tf32.f32 "
                    "{%0,%1,%2,%3}, {%4,%5,%6,%7}, {%8,%9}, {%0,%1,%2,%3};"
                    : "+f"(c[i][nt][0]), "+f"(c[i][nt][1]), "+f"(c[i][nt][2]), "+f"(c[i][nt][3])
                    : "r"(ua[i][0]), "r"(ua[i][1]), "r"(ua[i][2]), "r"(ua[i][3]),
                      "r"(ub0), "r"(ub1));
            }
        }
    }
}

// ---------------- scalar QK (cmp branch only, fp32) ----------------
__device__ __forceinline__ void gemm_qk_cmp(const float* __restrict__ Qs,
                                            const float* __restrict__ Ks,
                                            float* __restrict__ Pb,
                                            int rho, int gg)
{
    u64 s2[4][4];
#pragma unroll
    for (int i = 0; i < 4; ++i)
#pragma unroll
        for (int j = 0; j < 4; ++j) s2[i][j] = 0ULL;

    const u64* qp = (const u64*)(Qs + rho * QSTR);
    const u64* kp = (const u64*)(Ks + gg  * QSTR);
    const int RS = 8 * QSTR;
#pragma unroll 4
    for (int kd = 0; kd < DIMn / 2; ++kd) {
        u64 a0 = qp[kd];
        u64 a1 = qp[RS + kd];
        u64 a2 = qp[2 * RS + kd];
        u64 a3 = qp[3 * RS + kd];
        u64 b0 = kp[kd];
        u64 b1 = kp[RS + kd];
        u64 b2 = kp[2 * RS + kd];
        u64 b3 = kp[3 * RS + kd];
        s2[0][0] = FMA2(a0, b0, s2[0][0]); s2[0][1] = FMA2(a0, b1, s2[0][1]);
        s2[0][2] = FMA2(a0, b2, s2[0][2]); s2[0][3] = FMA2(a0, b3, s2[0][3]);
        s2[1][0] = FMA2(a1, b0, s2[1][0]); s2[1][1] = FMA2(a1, b1, s2[1][1]);
        s2[1][2] = FMA2(a1, b2, s2[1][2]); s2[1][3] = FMA2(a1, b3, s2[1][3]);
        s2[2][0] = FMA2(a2, b0, s2[2][0]); s2[2][1] = FMA2(a2, b1, s2[2][1]);
        s2[2][2] = FMA2(a2, b2, s2[2][2]); s2[2][3] = FMA2(a2, b3, s2[2][3]);
        s2[3][0] = FMA2(a3, b0, s2[3][0]); s2[3][1] = FMA2(a3, b1, s2[3][1]);
        s2[3][2] = FMA2(a3, b2, s2[3][2]); s2[3][3] = FMA2(a3, b3, s2[3][3]);
    }
#pragma unroll
    for (int i = 0; i < 4; ++i) {
        int r = rho + 16 * i;
#pragma unroll
        for (int j = 0; j < 4; ++j) {
            int cc = gg + 16 * j;
            float x, y; UNPK(s2[i][j], x, y);
            float val = (x + y) * SQRT_D;
            if (cc >= NCMP) val = NEG_INF;
            Pb[r * PSTR + cc] = val;
        }
    }
}

// two-pass row softmax over Pb[:, 0:NK]; fp32 exp in Pb, 1/rowsum in rinv.
// ALL NTHR threads must call (uniform barriers); work guarded to tid<256.
__device__ __forceinline__ void softmax_rows(float* __restrict__ Pb,
                                             float* __restrict__ rmax,
                                             float* __restrict__ rinv,
                                             float* __restrict__ red,
                                             int NK, int tid)
{
    int r = tid >> 2, part = tid & 3;
    bool act = tid < 256;
    if (act) {
        float m = NEG_INF;
        for (int c = part; c < NK; c += 4) m = fmaxf(m, Pb[r * PSTR + c]);
        red[part * 64 + r] = m;
    }
    __syncthreads();
    if (tid < 64)
        rmax[tid] = fmaxf(fmaxf(red[tid], red[64 + tid]),
                          fmaxf(red[128 + tid], red[192 + tid]));
    __syncthreads();
    if (act) {
        float mr = rmax[r];
        float sum = 0.f;
        for (int c = part; c < NK; c += 4) {
            float e = __expf(Pb[r * PSTR + c] - mr);
            Pb[r * PSTR + c] = e;
            sum += e;
        }
        red[part * 64 + r] = sum;
    }
    __syncthreads();
    if (tid < 64)
        rinv[tid] = 1.0f / (red[tid] + red[64 + tid] + red[128 + tid] + red[192 + tid]);
    __syncthreads();
}

// P[r][c] = tf32(P[r][c] * gate[r][gi] / rowsum[r])  (uniform; trailing sync)
__device__ __forceinline__ void scale_rows(float* __restrict__ Pb,
                                           const float* __restrict__ rinv,
                                           const float* __restrict__ gts,
                                           int gi, int NK, int tid)
{
    if (tid < 256) {
        int r = tid >> 2, part = tid & 3;
        float f = gts[r * 3 + gi] * rinv[r];
        for (int c = part; c < NK; c += 4) Pb[r * PSTR + c] = toTf32(Pb[r * PSTR + c] * f);
    }
    __syncthreads();
}

// ---------------- fused main kernel (persistent, warp-specialized, 32x32 tiles) --------
__global__ void __launch_bounds__(NTHR, 1) nsa_main(
    const float* __restrict__ q, const float* __restrict__ k, const float* __restrict__ v,
    const float* __restrict__ wgate, const float* __restrict__ bgate,
    float* __restrict__ out)
{
    extern __shared__ float sm[];
    float* Qs   = sm;                    // 64*132 fp32 Q (cmp QK + gates)
    float* QsT  = Qs   + 64 * QSTR;      // 64*132 tf32 Q (mma)
    float* KA   = QsT  + 64 * QSTR;      // 64*136 buffer A (K@132 / V@136)
    float* VA   = KA   + 64 * VSTR;      // 64*136 buffer B
    float* Pb   = VA   + 64 * VSTR;      // 64*132
    float* rinv = Pb  + 64 * PSTR;       // 64
    float* rmax = rinv + 64;             // 64
    float* red  = rmax + 64;             // 256
    float* gts  = red  + 256;            // 192
    float* Cs   = gts  + 192;            // 64
    float* Gb   = Cs   + 64;             // 64
    float* wgs  = Gb   + 64;             // 384
    float* scs  = wgs  + 384;            // 64
    float* fw   = scs  + 64;             // 64
    int*   topi = (int*)(fw + 64);       // 2
    unsigned int* s_item = (unsigned int*)(topi + 2);

    const int tid  = threadIdx.x;
    const int wid  = tid >> 5;
    const int lane = tid & 31;
    const bool comp = (wid < 8);
    const int ptid = tid - 256;          // producer id (128-wide copies)
    const int xtid = tid - 128;          // extended copier id (256-wide copies)
    const int rho  = tid >> 4;
    const int gg   = tid & 15;
    const int fg   = lane >> 2;          // fragment g
    const int ft   = lane & 3;           // fragment t
    const int pr   = 32 * (wid & 1);     // PV row block
    const int pc   = 32 * (wid >> 1);    // PV col block (compute warps)

    for (int i = tid; i < 3 * DIMn; i += NTHR) wgs[i] = wgate[i];

    for (;;) {
        __syncthreads();
        if (tid == 0) *s_item = atomicAdd(&g_ticket, 1u);
        __syncthreads();
        unsigned int bhq = *s_item;
        if (bhq >= NITEMS) break;

        const int qb  = bhq & (NQB - 1);
        const int bh  = bhq >> 4;
        const int h   = bh & (Hn - 1);
        const int b   = bh >> 3;
        const int q0  = qb * BQ;
        const int wbase = q0 - WINR;

        const int clo_min = (128 - q0 > 0) ? (128 - q0) : 0;
        const int chi_max = (1151 - q0 < 319) ? (1151 - q0) : 319;
        const int t_lo = clo_min >> 6;
        const int t_hi = chi_max >> 6;

        // ---- phase 0: Q load (all threads) ----
        {
            const float4* q4 = (const float4*)(q + ((size_t)(b * Sn + q0) * Hn + h) * DIMn);
            for (int idx = tid; idx < 64 * 32; idx += NTHR) {
                int t = idx >> 5, d4 = idx & 31;
                float4 val = q4[(size_t)t * (Hn * DIMn / 4) + d4];
                float* ds = &Qs[t * QSTR + (d4 << 2)];
                ds[0] = val.x; ds[1] = val.y; ds[2] = val.z; ds[3] = val.w;
                float* dt = &QsT[t * QSTR + (d4 << 2)];
                dt[0] = toTf32(val.x); dt[1] = toTf32(val.y);
                dt[2] = toTf32(val.z); dt[3] = toTf32(val.w);
            }
        }
        __syncthreads();

        // ---- phase 1: gates (compute) || copy K_tlo -> KA (producers) ----
        if (comp) {
            if (tid < 192) {
                int r = tid / 3, c = tid - 3 * r;
                float a = bgate[c];
                const float* qr_ = &Qs[r * QSTR];
                const float* wr = &wgs[c * DIMn];
#pragma unroll 8
                for (int d = 0; d < DIMn; ++d) a += qr_[d] * wr[d];
                gts[r * 3 + c] = 1.0f / (1.0f + __expf(-a));
            }
        } else {
            copy_kv_n<QSTR, true, 128>(KA, k, b, h, wbase + t_lo * 64, ptid, true);
        }
        __syncthreads();

        float acc[2][4][4];
#pragma unroll
        for (int i = 0; i < 2; ++i)
#pragma unroll
            for (int nt = 0; nt < 4; ++nt)
#pragma unroll
                for (int r = 0; r < 4; ++r) acc[i][nt][r] = 0.f;

        // ================= WINDOW branch =================
        int clo[4], chi[4];
#pragma unroll
        for (int i = 0; i < 4; ++i) {
            int r = rho + 16 * i;
            int lo = 128 - q0;  if (lo < r) lo = r;
            int hi = 1151 - q0; if (hi > r + 256) hi = r + 256;
            clo[i] = lo; chi[i] = hi;
        }
        float m_[4], l_[4];
#pragma unroll
        for (int i = 0; i < 4; ++i) { m_[i] = NEG_INF; l_[i] = 0.f; }

#pragma unroll 1
        for (int kt = t_lo; kt <= t_hi; ++kt) {
            // QK (warps 0-3) || copy V_kt -> VA (warps 4-11, 256-wide)
            if (wid < 4) mma_qk_sts32(QsT, KA, Pb, wid, lane, 1.0f);
            else         copy_kv_n<VSTR, true, 256>(VA, v, b, h, wbase + kt * 64, xtid, true);
            __syncthreads();

            // online softmax (compute) || copy next K / cmpK -> KA (producers)
            if (comp) {
#pragma unroll
                for (int i = 0; i < 4; ++i) {
                    int r = rho + 16 * i;
                    float s[4];
#pragma unroll
                    for (int j = 0; j < 4; ++j) {
                        int cgl = kt * 64 + gg + 16 * j;
                        bool ok = (cgl >= clo[i]) && (cgl <= chi[i]);
                        s[j] = ok ? Pb[r * PSTR + gg + 16 * j] * SCALE_MUL : NEG_INF;
                    }
                    float tm = fmaxf(fmaxf(s[0], s[1]), fmaxf(s[2], s[3]));
                    tm = fmaxf(tm, __shfl_xor_sync(0xffffffffu, tm, 1));
                    tm = fmaxf(tm, __shfl_xor_sync(0xffffffffu, tm, 2));
                    tm = fmaxf(tm, __shfl_xor_sync(0xffffffffu, tm, 4));
                    tm = fmaxf(tm, __shfl_xor_sync(0xffffffffu, tm, 8));
                    float nm = fmaxf(m_[i], tm);
                    float sc = __expf(m_[i] - nm);
                    m_[i] = nm;
                    float rs = 0.f;
#pragma unroll
                    for (int j = 0; j < 4; ++j) {
                        float e = (s[j] > -1e29f) ? __expf(s[j] - nm) : 0.f;
                        s[j] = e;
                        rs += e;
                    }
                    rs += __shfl_xor_sync(0xffffffffu, rs, 1);
                    rs += __shfl_xor_sync(0xffffffffu, rs, 2);
                    rs += __shfl_xor_sync(0xffffffffu, rs, 4);
                    rs += __shfl_xor_sync(0xffffffffu, rs, 8);
                    l_[i] = l_[i] * sc + rs;
                    if (gg == 0) scs[r] = sc;
#pragma unroll
                    for (int j = 0; j < 4; ++j) Pb[r * PSTR + gg + 16 * j] = toTf32(s[j]);
                }
            } else {
                if (kt < t_hi) copy_kv_n<QSTR, true, 128>(KA, k, b, h, wbase + (kt + 1) * 64, ptid, true);
                else           copy_cmp_n<QSTR, false, 128>(KA, g_cmpK, bh, ptid);
            }
            __syncthreads();

            // PV (8 compute warps) || producers idle
            if (comp) {
                float sa0 = scs[pr + fg],      sb0 = scs[pr + fg + 8];
                float sa1 = scs[pr + 16 + fg], sb1 = scs[pr + 24 + fg];
#pragma unroll
                for (int nt = 0; nt < 4; ++nt) {
                    acc[0][nt][0] *= sa0; acc[0][nt][1] *= sa0;
                    acc[0][nt][2] *= sb0; acc[0][nt][3] *= sb0;
                    acc[1][nt][0] *= sa1; acc[1][nt][1] *= sa1;
                    acc[1][nt][2] *= sb1; acc[1][nt][3] *= sb1;
                }
                mma_pv32(Pb, VA, acc, wid, lane, 0);
            }
            __syncthreads();
        }
        // finalize window factor
        if (comp && gg == 0) {
#pragma unroll
            for (int i = 0; i < 4; ++i) fw[rho + 16 * i] = gts[(rho + 16 * i) * 3 + 2] / l_[i];
        }
        __syncthreads();

        // ================= CMP branch =================
        if (comp) {
            float fa0 = fw[pr + fg],      fb0 = fw[pr + fg + 8];
            float fa1 = fw[pr + 16 + fg], fb1 = fw[pr + 24 + fg];
#pragma unroll
            for (int nt = 0; nt < 4; ++nt) {
                acc[0][nt][0] *= fa0; acc[0][nt][1] *= fa0;
                acc[0][nt][2] *= fb0; acc[0][nt][3] *= fb0;
                acc[1][nt][0] *= fa1; acc[1][nt][1] *= fa1;
                acc[1][nt][2] *= fb1; acc[1][nt][3] *= fb1;
            }
            gemm_qk_cmp(Qs, KA, Pb, rho, gg);
        } else {
            copy_cmp_n<VSTR, true, 128>(VA, g_cmpV, bh, ptid);
        }
        __syncthreads();

        softmax_rows(Pb, rmax, rinv, red, 64, tid);

        // column sums of normalized P_cmp
        if (tid < 256) {
            int col = tid & 63, part = tid >> 6;
            float s = 0.f;
            int r0 = part * 16;
#pragma unroll 4
            for (int r = r0; r < r0 + 16; ++r) s += Pb[r * PSTR + col] * rinv[r];
            red[part * 64 + col] = s;
        }
        __syncthreads();
        if (tid < 64)
            Cs[tid] = red[tid] + red[64 + tid] + red[128 + tid] + red[192 + tid];
        __syncthreads();
        if (tid < NSLC) {
            int j4 = 4 * tid;
            float g = 0.f;
            if (j4 < NCMP)                       g += Cs[j4];
            if (j4 - 1 >= 0 && j4 - 1 < NCMP)    g += 2.f * Cs[j4 - 1];
            if (j4 - 2 >= 0 && j4 - 2 < NCMP)    g += 2.f * Cs[j4 - 2];
            if (j4 - 3 >= 0 && j4 - 3 < NCMP)    g += 2.f * Cs[j4 - 3];
            if (j4 - 4 >= 0 && j4 - 4 < NCMP)    g += Cs[j4 - 4];
            Gb[tid] = g;
        }
        __syncthreads();
        if (tid < 32) {
            float a  = (tid < NSLC)      ? Gb[tid]      : NEG_INF;
            float bb = (tid + 32 < NSLC) ? Gb[tid + 32] : NEG_INF;
            float m1 = a; int i1 = tid;
            if (bb > m1) { m1 = bb; i1 = tid + 32; }
#pragma unroll
            for (int off = 16; off > 0; off >>= 1) {
                float om = __shfl_down_sync(0xffffffffu, m1, off);
                int   oi = __shfl_down_sync(0xffffffffu, i1, off);
                if (om > m1 || (om == m1 && oi < i1)) { m1 = om; i1 = oi; }
            }
            int i0 = __shfl_sync(0xffffffffu, i1, 0);
            float a2  = (tid == i0)      ? NEG_INF : a;
            float b2  = (tid + 32 == i0) ? NEG_INF : bb;
            float m2 = a2; int i2 = tid;
            if (b2 > m2) { m2 = b2; i2 = tid + 32; }
#pragma unroll
            for (int off = 16; off > 0; off >>= 1) {
                float om = __shfl_down_sync(0xffffffffu, m2, off);
                int   oi = __shfl_down_sync(0xffffffffu, i2, off);
                if (om > m2 || (om == m2 && oi < i2)) { m2 = om; i2 = oi; }
            }
            if (tid == 0) { topi[0] = i0; topi[1] = i2; }
        }
        scale_rows(Pb, rinv, gts, 0, 64, tid);   // trailing sync -> topi visible

        // cmp PV (compute) || copy K_j0 -> KA (producers)
        if (comp) mma_pv32(Pb, VA, acc, wid, lane, 0);
        else      copy_kv_n<QSTR, true, 128>(KA, k, b, h, topi[0] * 16, ptid, false);
        __syncthreads();

        // ================= SLC branch =================
        // slc A: QK j0 -> Pb[0:64] (warps 0-3) || copy K_j1 -> VA (warps 4-11)
        if (wid < 4) mma_qk_sts32(QsT, KA, Pb, wid, lane, SCALE_MUL);
        else         copy_kv_n<QSTR, true, 256>(VA, k, b, h, topi[1] * 16, xtid, false);
        __syncthreads();

        // slc B: QK j1 (from VA) -> Pb[64:128] (warps 0-3) || copy V_j0 -> KA (warps 4-11)
        if (wid < 4) mma_qk_sts32(QsT, VA, Pb + 64, wid, lane, SCALE_MUL);
        else         copy_kv_n<VSTR, true, 256>(KA, v, b, h, topi[0] * 16, xtid, false);
        __syncthreads();

        // slc C: softmax + gate1 scale (compute) || copy V_j1 -> VA (producers)
        if (!comp) copy_kv_n<VSTR, true, 128>(VA, v, b, h, topi[1] * 16, ptid, false);
        softmax_rows(Pb, rmax, rinv, red, 128, tid);
        scale_rows(Pb, rinv, gts, 1, 128, tid);   // trailing sync -> VA published

        // slc D: both PVs + output (compute)
        if (comp) {
            mma_pv32(Pb, KA, acc, wid, lane, 0);    // V_j0 (VSTR layout in KA buffer)
            mma_pv32(Pb, VA, acc, wid, lane, 64);   // V_j1

#pragma unroll
            for (int i = 0; i < 2; ++i) {
                int r0 = pr + 16 * i + fg, r1 = r0 + 8;
                float* op0 = out + ((size_t)(b * Sn + q0 + r0) * Hn + h) * DIMn + pc + 2 * ft;
                float* op1 = out + ((size_t)(b * Sn + q0 + r1) * Hn + h) * DIMn + pc + 2 * ft;
#pragma unroll
                for (int nt = 0; nt < 4; ++nt) {
                    *(float2*)(op0 + 8 * nt) = make_float2(acc[i][nt][0], acc[i][nt][1]);
                    *(float2*)(op1 + 8 * nt) = make_float2(acc[i][nt][2], acc[i][nt][3]);
                }
            }
        }
    }
}

// ---------------- launch ----------------
extern "C" void kernel_launch(void* const* d_in, const int* in_sizes, int n_in,
                              void* d_out, int out_size)
{
    (void)in_sizes; (void)n_in; (void)out_size;
    const float* q   = (const float*)d_in[0];
    const float* k   = (const float*)d_in[1];
    const float* v   = (const float*)d_in[2];
    const float* wck = (const float*)d_in[3];
    const float* bck = (const float*)d_in[4];
    const float* wcv = (const float*)d_in[5];
    const float* bcv = (const float*)d_in[6];
    const float* wg  = (const float*)d_in[7];
    const float* bg  = (const float*)d_in[8];
    float* out = (float*)d_out;

    int totalA = Bn * Hn * NCMP * DIMn;
    cmp_kv_kernel<<<(totalA + 255) / 256, 256>>>(k, v, wck, bck, wcv, bcv);

    size_t smem_floats = (size_t)2 * 64 * QSTR + (size_t)2 * 64 * VSTR + (size_t)64 * PSTR
                       + 64 + 64 + 256 + 192 + 64 + 64 + 384 + 64 + 64 + 8;
    size_t smem_bytes = smem_floats * sizeof(float);
    cudaFuncSetAttribute(nsa_main, cudaFuncAttributeMaxDynamicSharedMemorySize,
                         (int)smem_bytes);
    nsa_main<<<152, NTHR, smem_bytes>>>(q, k, v, wg, bg, out);
}